// round 4
// baseline (speedup 1.0000x reference)
#include <cuda_runtime.h>
#include <cstdint>

#define Lr 3
#define Hd 128
#define NHd 8
#define HDd 16
#define FFd 512
#define Bd 32
#define Nd 512
#define NUM_BINS 50
#define Md (Bd*Nd)          // 16384 rows

// ---------------- scratch (device globals; no allocation allowed) ----------
__device__ float g_hn[(size_t)Md*Hd];
__device__ float g_q [(size_t)Md*Hd];
__device__ float g_k [(size_t)Md*Hd];
__device__ float g_v [(size_t)Md*Hd];
__device__ float g_ao[(size_t)Md*Hd];
__device__ float g_u [(size_t)Md*2*FFd];
__device__ float g_gl[(size_t)Md*FFd];
__device__ unsigned char g_mask[Md];   // canonical expanded mask (B*N == Md)

// ---------------- mask dtype detection + expansion --------------------------
// bool input may arrive as int32 (0/1), float32 (0.0/1.0), or uint8.
// Inspect the first 4096 words (16384 bytes -- safe under all hypotheses),
// then expand into g_mask as uchar. Deterministic, graph-capturable.
__global__ void mask_expand_kernel(const void* __restrict__ mraw) {
    __shared__ int s_notint, s_notfloat;
    if (threadIdx.x == 0) { s_notint = 0; s_notfloat = 0; }
    __syncthreads();
    const int* mi = (const int*)mraw;
    int notint = 0, notfloat = 0;
    for (int i = threadIdx.x; i < 4096; i += 256) {
        int v = mi[i];
        if (v != 0 && v != 1) notint = 1;
        if (v != 0 && v != 0x3F800000) notfloat = 1;
    }
    if (notint)   atomicOr(&s_notint, 1);
    if (notfloat) atomicOr(&s_notfloat, 1);
    __syncthreads();
    int isInt   = !s_notint;                 // all-zero also lands here (harmless)
    int isFloat = (!s_notfloat) && s_notint;
    for (int i = threadIdx.x; i < Md; i += 256) {
        unsigned char m;
        if (isInt)        m = (unsigned char)(mi[i] != 0);
        else if (isFloat) m = (unsigned char)(((const float*)mraw)[i] != 0.0f);
        else              m = (unsigned char)(((const unsigned char*)mraw)[i] != 0);
        g_mask[i] = m;
    }
}

// ---------------- LayerNorm: one block per row, 128 threads ----------------
__global__ void ln_kernel(const float* __restrict__ h,
                          const float* __restrict__ gamma,
                          const float* __restrict__ beta,
                          float* __restrict__ out) {
    int row = blockIdx.x;
    int t = threadIdx.x;           // 0..127 == H
    float v = h[(size_t)row*Hd + t];
    __shared__ float s1[128], s2[128];
    s1[t] = v; s2[t] = v*v;
    __syncthreads();
    for (int s = 64; s > 0; s >>= 1) {
        if (t < s) { s1[t] += s1[t+s]; s2[t] += s2[t+s]; }
        __syncthreads();
    }
    float mean = s1[0] * (1.0f/Hd);
    float var  = s2[0] * (1.0f/Hd) - mean*mean;
    float inv  = rsqrtf(var + 1e-5f);
    out[(size_t)row*Hd + t] = (v - mean) * inv * gamma[t] + beta[t];
}

// ---------------- tiled GEMM: C = A[M,K] @ W[K,Nc] + bias (+resid) ----------
__global__ void gemm_kernel(const float* __restrict__ A,
                            const float* __restrict__ W,
                            const float* __restrict__ bias,
                            const float* __restrict__ resid,   // may be null
                            float* __restrict__ C,
                            int M, int Nc, int K) {
    __shared__ float As[16][16];
    __shared__ float Ws[16][17];
    int tx = threadIdx.x, ty = threadIdx.y;
    int row = blockIdx.y*16 + ty;
    int col = blockIdx.x*16 + tx;
    float acc = 0.0f;
    for (int k0 = 0; k0 < K; k0 += 16) {
        As[ty][tx] = A[(size_t)row*K + k0 + tx];
        Ws[ty][tx] = W[(size_t)(k0+ty)*Nc + col];
        __syncthreads();
        #pragma unroll
        for (int kk = 0; kk < 16; kk++)
            acc += As[ty][kk] * Ws[kk][tx];
        __syncthreads();
    }
    float v = acc + bias[col];
    if (resid) v += resid[(size_t)row*Nc + col];
    C[(size_t)row*Nc + col] = v;
}

// ---------------- fused attention per (q, head, batch) ---------------------
__global__ void attn_kernel(const float* __restrict__ Q,
                            const float* __restrict__ K,
                            const float* __restrict__ V,
                            const float* __restrict__ dm,
                            const unsigned char* __restrict__ mask,
                            const float* __restrict__ dist_emb_l,  // [50,8]
                            const float* __restrict__ attn_bias_l, // [8]
                            float* __restrict__ out) {
    int qi = blockIdx.x, nh = blockIdx.y, b = blockIdx.z;
    int t = threadIdx.x;                       // 0..127
    __shared__ float qv[HDd];
    __shared__ float sc[Nd];
    __shared__ float red[128];
    __shared__ float part[8][HDd];

    const float* qrow = Q + ((size_t)(b*Nd + qi)*Hd + nh*HDd);
    if (t < HDd) qv[t] = qrow[t];
    __syncthreads();

    float ab = attn_bias_l[nh];
    const float* dmr = dm + ((size_t)b*Nd + qi)*Nd;
    const unsigned char* mr = mask + (size_t)b*Nd;

    float lmax = -1e30f;
    for (int k = t; k < Nd; k += 128) {
        const float* krow = K + ((size_t)(b*Nd + k)*Hd + nh*HDd);
        float s = 0.0f;
        #pragma unroll
        for (int d = 0; d < HDd; d++) s += qv[d]*krow[d];
        s *= 0.25f;                    // 1/sqrt(16)
        int bin = (int)(dmr[k]*10.0f);
        bin = min(max(bin,0), NUM_BINS-1);
        s += dist_emb_l[bin*NHd + nh] + ab;
        if (mr[k]) s = -1e9f;
        sc[k] = s;
        lmax = fmaxf(lmax, s);
    }
    red[t] = lmax; __syncthreads();
    for (int s = 64; s > 0; s >>= 1) {
        if (t < s) red[t] = fmaxf(red[t], red[t+s]);
        __syncthreads();
    }
    float m = red[0];
    __syncthreads();

    float lsum = 0.0f;
    for (int k = t; k < Nd; k += 128) {
        float e = __expf(sc[k] - m);
        sc[k] = e;
        lsum += e;
    }
    red[t] = lsum; __syncthreads();
    for (int s = 64; s > 0; s >>= 1) {
        if (t < s) red[t] += red[t+s];
        __syncthreads();
    }
    float inv = 1.0f / red[0];
    __syncthreads();

    // AV: 8 groups of 16 threads; group g does k in [g*64, g*64+64)
    int d = t & 15, g = t >> 4;
    float acc = 0.0f;
    const float* vbase = V + ((size_t)b*Nd)*Hd + nh*HDd + d;
    for (int k = g*64; k < g*64 + 64; k++)
        acc += sc[k] * vbase[(size_t)k*Hd];
    part[g][d] = acc;
    __syncthreads();
    if (g == 0) {
        float o = 0.0f;
        #pragma unroll
        for (int gg = 0; gg < 8; gg++) o += part[gg][d];
        out[((size_t)(b*Nd + qi)*Hd + nh*HDd) + d] = o * inv;
    }
}

// ---------------- GLU: glu[m,f] = ua * sigmoid(ub) --------------------------
__global__ void glu_kernel(const float* __restrict__ u, float* __restrict__ g) {
    int idx = blockIdx.x*blockDim.x + threadIdx.x;
    if (idx >= Md*FFd) return;
    int m = idx / FFd, f = idx % FFd;
    float a = u[(size_t)m*2*FFd + f];
    float b = u[(size_t)m*2*FFd + FFd + f];
    g[idx] = a * (1.0f/(1.0f + __expf(-b)));
}

extern "C" void kernel_launch(void* const* d_in, const int* in_sizes, int n_in,
                              void* d_out, int out_size) {
    const float* x    = (const float*)d_in[0];
    const float* dm   = (const float*)d_in[1];
    const void*  mraw = (const void*)d_in[2];
    const float* Wq = (const float*)d_in[3];
    const float* bq = (const float*)d_in[4];
    const float* Wk = (const float*)d_in[5];
    const float* bk = (const float*)d_in[6];
    const float* Wv = (const float*)d_in[7];
    const float* bv = (const float*)d_in[8];
    const float* Wo = (const float*)d_in[9];
    const float* bo = (const float*)d_in[10];
    const float* dist_emb  = (const float*)d_in[11];
    const float* attn_bias = (const float*)d_in[12];
    const float* g1 = (const float*)d_in[13];
    const float* b1 = (const float*)d_in[14];
    const float* g2 = (const float*)d_in[15];
    const float* b2 = (const float*)d_in[16];
    const float* Wf1 = (const float*)d_in[17];
    const float* bf1 = (const float*)d_in[18];
    const float* Wf2 = (const float*)d_in[19];
    const float* bf2 = (const float*)d_in[20];

    float *hn, *Qb, *Kb, *Vb, *AO, *U, *G;
    unsigned char* msk;
    cudaGetSymbolAddress((void**)&hn, g_hn);
    cudaGetSymbolAddress((void**)&Qb, g_q);
    cudaGetSymbolAddress((void**)&Kb, g_k);
    cudaGetSymbolAddress((void**)&Vb, g_v);
    cudaGetSymbolAddress((void**)&AO, g_ao);
    cudaGetSymbolAddress((void**)&U,  g_u);
    cudaGetSymbolAddress((void**)&G,  g_gl);
    cudaGetSymbolAddress((void**)&msk, g_mask);

    float* h = (float*)d_out;
    cudaMemcpyAsync(h, x, (size_t)Md*Hd*sizeof(float), cudaMemcpyDeviceToDevice);
    mask_expand_kernel<<<1,256>>>(mraw);

    dim3 tb(16,16);
    for (int l = 0; l < Lr; l++) {
        // pre-LN attention block
        ln_kernel<<<Md,128>>>(h, g1 + l*Hd, b1 + l*Hd, hn);
        gemm_kernel<<<dim3(Hd/16,  Md/16), tb>>>(hn, Wq + (size_t)l*Hd*Hd, bq + l*Hd, nullptr, Qb, Md, Hd, Hd);
        gemm_kernel<<<dim3(Hd/16,  Md/16), tb>>>(hn, Wk + (size_t)l*Hd*Hd, bk + l*Hd, nullptr, Kb, Md, Hd, Hd);
        gemm_kernel<<<dim3(Hd/16,  Md/16), tb>>>(hn, Wv + (size_t)l*Hd*Hd, bv + l*Hd, nullptr, Vb, Md, Hd, Hd);
        attn_kernel<<<dim3(Nd, NHd, Bd), 128>>>(Qb, Kb, Vb, dm, msk,
                                                dist_emb + (size_t)l*NUM_BINS*NHd,
                                                attn_bias + (size_t)l*NHd, AO);
        gemm_kernel<<<dim3(Hd/16,  Md/16), tb>>>(AO, Wo + (size_t)l*Hd*Hd, bo + l*Hd, h, h, Md, Hd, Hd);

        // pre-LN GLU FFN
        ln_kernel<<<Md,128>>>(h, g2 + l*Hd, b2 + l*Hd, hn);
        gemm_kernel<<<dim3(2*FFd/16, Md/16), tb>>>(hn, Wf1 + (size_t)l*Hd*2*FFd, bf1 + l*2*FFd, nullptr, U, Md, 2*FFd, Hd);
        glu_kernel<<<(Md*FFd + 255)/256, 256>>>(U, G);
        gemm_kernel<<<dim3(Hd/16,  Md/16), tb>>>(G, Wf2 + (size_t)l*FFd*Hd, bf2 + l*Hd, h, h, Md, Hd, FFd);
    }
}

// round 8
// speedup vs baseline: 5.9621x; 5.9621x over previous
#include <cuda_runtime.h>
#include <cstdint>

#define Lr 3
#define Hd 128
#define NHd 8
#define HDd 16
#define FFd 512
#define Bd 32
#define Nd 512
#define NUM_BINS 50
#define Md (Bd*Nd)          // 16384 rows
#define QKVLD 384           // interleaved QKV row stride

// ---------------- scratch (device globals; no allocation allowed) ----------
__device__ float g_hn [(size_t)Md*Hd];
__device__ float g_qkv[(size_t)Md*QKVLD];
__device__ float g_ao [(size_t)Md*Hd];
__device__ float g_gl [(size_t)Md*FFd];
__device__ unsigned char g_mask[Md];
__device__ unsigned char g_bins[(size_t)Bd*Nd*Nd];   // 8.4 MB

// ---------------- mask dtype detection + expansion --------------------------
__global__ void mask_expand_kernel(const void* __restrict__ mraw) {
    __shared__ int s_notint, s_notfloat;
    if (threadIdx.x == 0) { s_notint = 0; s_notfloat = 0; }
    __syncthreads();
    const int* mi = (const int*)mraw;
    int notint = 0, notfloat = 0;
    for (int i = threadIdx.x; i < 4096; i += 256) {
        int v = mi[i];
        if (v != 0 && v != 1) notint = 1;
        if (v != 0 && v != 0x3F800000) notfloat = 1;
    }
    if (notint)   atomicOr(&s_notint, 1);
    if (notfloat) atomicOr(&s_notfloat, 1);
    __syncthreads();
    int isInt   = !s_notint;
    int isFloat = (!s_notfloat) && s_notint;
    for (int i = threadIdx.x; i < Md; i += 256) {
        unsigned char m;
        if (isInt)        m = (unsigned char)(mi[i] != 0);
        else if (isFloat) m = (unsigned char)(((const float*)mraw)[i] != 0.0f);
        else              m = (unsigned char)(((const unsigned char*)mraw)[i] != 0);
        g_mask[i] = m;
    }
}

// ---------------- bins: once per call (layer-independent) -------------------
__global__ void bins_kernel(const float* __restrict__ dm,
                            unsigned char* __restrict__ bins, int n) {
    int i = blockIdx.x*blockDim.x + threadIdx.x;
    if (i >= n) return;
    int b = (int)(dm[i]*10.0f);
    bins[i] = (unsigned char)min(max(b,0), NUM_BINS-1);
}

// ---------------- LayerNorm: one block per row, 128 threads ----------------
__global__ void ln_kernel(const float* __restrict__ h,
                          const float* __restrict__ gamma,
                          const float* __restrict__ beta,
                          float* __restrict__ out) {
    int row = blockIdx.x;
    int t = threadIdx.x;
    float v = h[(size_t)row*Hd + t];
    __shared__ float s1[128], s2[128];
    s1[t] = v; s2[t] = v*v;
    __syncthreads();
    for (int s = 64; s > 0; s >>= 1) {
        if (t < s) { s1[t] += s1[t+s]; s2[t] += s2[t+s]; }
        __syncthreads();
    }
    float mean = s1[0] * (1.0f/Hd);
    float var  = s2[0] * (1.0f/Hd) - mean*mean;
    float inv  = rsqrtf(var + 1e-5f);
    out[(size_t)row*Hd + t] = (v - mean) * inv * gamma[t] + beta[t];
}

// ------------- register-tiled GEMM: 64x64 tile, 4x4/thread, BK=16 ----------
__global__ __launch_bounds__(256)
void gemm64_kernel(const float* __restrict__ A,
                   const float* __restrict__ W,
                   const float* __restrict__ bias,
                   const float* __restrict__ resid,
                   float* __restrict__ C,
                   int M, int N, int K, int ldc, int coff) {
    __shared__ float As[16][64];
    __shared__ float Ws[16][64];
    int tx = threadIdx.x, ty = threadIdx.y;
    int tid = ty*16 + tx;
    int bm = blockIdx.y*64, bn = blockIdx.x*64;

    int aRow = bm + (tid >> 2);
    int aCol = (tid & 3) * 4;
    int wK   = tid >> 4;
    int wN   = (tid & 15) * 4;

    float acc[4][4] = {};
    for (int k0 = 0; k0 < K; k0 += 16) {
        float4 av = *(const float4*)&A[(size_t)aRow*K + k0 + aCol];
        As[aCol+0][tid>>2] = av.x;
        As[aCol+1][tid>>2] = av.y;
        As[aCol+2][tid>>2] = av.z;
        As[aCol+3][tid>>2] = av.w;
        *(float4*)&Ws[wK][wN] = *(const float4*)&W[(size_t)(k0+wK)*N + bn + wN];
        __syncthreads();
        #pragma unroll
        for (int kk = 0; kk < 16; kk++) {
            float4 a = *(const float4*)&As[kk][ty*4];
            float4 b = *(const float4*)&Ws[kk][tx*4];
            float ar[4] = {a.x,a.y,a.z,a.w};
            float br[4] = {b.x,b.y,b.z,b.w};
            #pragma unroll
            for (int i = 0; i < 4; i++)
                #pragma unroll
                for (int j = 0; j < 4; j++)
                    acc[i][j] += ar[i]*br[j];
        }
        __syncthreads();
    }
    #pragma unroll
    for (int i = 0; i < 4; i++) {
        int row = bm + ty*4 + i;
        #pragma unroll
        for (int j = 0; j < 4; j++) {
            int col = bn + tx*4 + j;
            float v = acc[i][j] + bias[col];
            if (resid) v += resid[(size_t)row*ldc + coff + col];
            C[(size_t)row*ldc + coff + col] = v;
        }
    }
}

// ---------- GEMM + GLU fused: G[M,FF] = (A@Wf1a + ba) * sigmoid(A@Wf1b + bb)
__global__ __launch_bounds__(256)
void gemm_glu_kernel(const float* __restrict__ A,
                     const float* __restrict__ Wf1,
                     const float* __restrict__ bf1,
                     float* __restrict__ G,
                     int M, int K) {
    __shared__ float As [16][64];
    __shared__ float Wsa[16][64];
    __shared__ float Wsb[16][64];
    int tx = threadIdx.x, ty = threadIdx.y;
    int tid = ty*16 + tx;
    int bm = blockIdx.y*64, bn = blockIdx.x*64;

    int aRow = bm + (tid >> 2);
    int aCol = (tid & 3) * 4;
    int wK   = tid >> 4;
    int wN   = (tid & 15) * 4;

    float acca[4][4] = {};
    float accb[4][4] = {};
    for (int k0 = 0; k0 < K; k0 += 16) {
        float4 av = *(const float4*)&A[(size_t)aRow*K + k0 + aCol];
        As[aCol+0][tid>>2] = av.x;
        As[aCol+1][tid>>2] = av.y;
        As[aCol+2][tid>>2] = av.z;
        As[aCol+3][tid>>2] = av.w;
        *(float4*)&Wsa[wK][wN] = *(const float4*)&Wf1[(size_t)(k0+wK)*(2*FFd) + bn + wN];
        *(float4*)&Wsb[wK][wN] = *(const float4*)&Wf1[(size_t)(k0+wK)*(2*FFd) + FFd + bn + wN];
        __syncthreads();
        #pragma unroll
        for (int kk = 0; kk < 16; kk++) {
            float4 a  = *(const float4*)&As [kk][ty*4];
            float4 ba = *(const float4*)&Wsa[kk][tx*4];
            float4 bb = *(const float4*)&Wsb[kk][tx*4];
            float ar[4]  = {a.x,a.y,a.z,a.w};
            float bra[4] = {ba.x,ba.y,ba.z,ba.w};
            float brb[4] = {bb.x,bb.y,bb.z,bb.w};
            #pragma unroll
            for (int i = 0; i < 4; i++)
                #pragma unroll
                for (int j = 0; j < 4; j++) {
                    acca[i][j] += ar[i]*bra[j];
                    accb[i][j] += ar[i]*brb[j];
                }
        }
        __syncthreads();
    }
    #pragma unroll
    for (int i = 0; i < 4; i++) {
        int row = bm + ty*4 + i;
        #pragma unroll
        for (int j = 0; j < 4; j++) {
            int col = bn + tx*4 + j;
            float ua = acca[i][j] + bf1[col];
            float ub = accb[i][j] + bf1[FFd + col];
            G[(size_t)row*FFd + col] = ua * (1.0f/(1.0f + __expf(-ub)));
        }
    }
}

// ---------------- attention: one block per (h, b); K/V in smem -------------
#define KVPITCH 17
#define ATTN_SMEM ((2*512*KVPITCH + 16*512 + 52)*4 + 512)

__global__ __launch_bounds__(512, 2)
void attn2_kernel(const float* __restrict__ QKV,
                  const unsigned char* __restrict__ bins,
                  const unsigned char* __restrict__ mask,
                  const float* __restrict__ dist_emb_l,   // [50,8]
                  const float* __restrict__ attn_bias_l,  // [8]
                  float* __restrict__ out) {
    int h = blockIdx.x, b = blockIdx.y;
    extern __shared__ float sm[];
    float* Ks  = sm;
    float* Vs  = Ks + 512*KVPITCH;
    float* sc  = Vs + 512*KVPITCH;
    float* emb = sc + 16*512;
    unsigned char* msk = (unsigned char*)(emb + 52);

    int tid = threadIdx.x;
    int w = tid >> 5, l = tid & 31;

    {   // K/V tile load: one row per thread
        int k = tid;
        const float* kr = QKV + ((size_t)(b*Nd + k)*QKVLD + Hd + h*HDd);
        #pragma unroll
        for (int d = 0; d < 16; d += 4) {
            float4 kv = *(const float4*)&kr[d];
            float4 vv = *(const float4*)&kr[128 + d];
            Ks[k*KVPITCH + d+0] = kv.x; Ks[k*KVPITCH + d+1] = kv.y;
            Ks[k*KVPITCH + d+2] = kv.z; Ks[k*KVPITCH + d+3] = kv.w;
            Vs[k*KVPITCH + d+0] = vv.x; Vs[k*KVPITCH + d+1] = vv.y;
            Vs[k*KVPITCH + d+2] = vv.z; Vs[k*KVPITCH + d+3] = vv.w;
        }
    }
    if (tid < NUM_BINS) emb[tid] = dist_emb_l[tid*NHd + h];
    if (tid < 128) ((uint32_t*)msk)[tid] = ((const uint32_t*)(mask + (size_t)b*Nd))[tid];
    float ab = attn_bias_l[h];
    __syncthreads();

    float* scw = sc + w*512;
    const unsigned char* binb = bins + ((size_t)b*Nd)*Nd;

    for (int q = w*32; q < w*32 + 32; q++) {
        const float* qr = QKV + ((size_t)(b*Nd + q)*QKVLD + h*HDd);
        float qv[16];
        #pragma unroll
        for (int d = 0; d < 16; d += 4) {
            float4 t = *(const float4*)&qr[d];
            qv[d] = t.x; qv[d+1] = t.y; qv[d+2] = t.z; qv[d+3] = t.w;
        }
        const unsigned char* binrow = binb + (size_t)q*Nd;

        float lmax = -1e30f;
        #pragma unroll
        for (int i = 0; i < 16; i++) {
            int k = l + 32*i;
            const float* kp = &Ks[k*KVPITCH];
            float s0=0, s1=0, s2=0, s3=0;
            #pragma unroll
            for (int d = 0; d < 16; d += 4) {
                s0 += qv[d+0]*kp[d+0];
                s1 += qv[d+1]*kp[d+1];
                s2 += qv[d+2]*kp[d+2];
                s3 += qv[d+3]*kp[d+3];
            }
            float s = (s0+s1)+(s2+s3);
            s = s*0.25f + emb[binrow[k]] + ab;
            if (msk[k]) s = -1e9f;
            scw[k] = s;
            lmax = fmaxf(lmax, s);
        }
        #pragma unroll
        for (int o = 16; o; o >>= 1)
            lmax = fmaxf(lmax, __shfl_xor_sync(0xffffffffu, lmax, o));
        __syncwarp();

        float lsum = 0.0f;
        #pragma unroll
        for (int i = 0; i < 16; i++) {
            int k = l + 32*i;
            float e = __expf(scw[k] - lmax);
            scw[k] = e;
            lsum += e;
        }
        #pragma unroll
        for (int o = 16; o; o >>= 1)
            lsum += __shfl_xor_sync(0xffffffffu, lsum, o);
        float inv = 1.0f/lsum;
        __syncwarp();

        // AV: lanes 0-15 sum k in [0,256), lanes 16-31 sum k in [256,512)
        int d = l & 15;
        int kbase = (l < 16) ? 0 : 256;
        float a0=0, a1=0, a2=0, a3=0;
        #pragma unroll 4
        for (int kk = 0; kk < 256; kk += 4) {
            int k = kbase + kk;
            a0 += scw[k+0]*Vs[(k+0)*KVPITCH + d];
            a1 += scw[k+1]*Vs[(k+1)*KVPITCH + d];
            a2 += scw[k+2]*Vs[(k+2)*KVPITCH + d];
            a3 += scw[k+3]*Vs[(k+3)*KVPITCH + d];
        }
        float acc = (a0+a1)+(a2+a3);
        acc += __shfl_down_sync(0xffffffffu, acc, 16);
        if (l < 16)
            out[((size_t)(b*Nd + q)*Hd) + h*HDd + d] = acc*inv;
        __syncwarp();
    }
}

extern "C" void kernel_launch(void* const* d_in, const int* in_sizes, int n_in,
                              void* d_out, int out_size) {
    const float* x    = (const float*)d_in[0];
    const float* dm   = (const float*)d_in[1];
    const void*  mraw = (const void*)d_in[2];
    const float* Wq = (const float*)d_in[3];
    const float* bq = (const float*)d_in[4];
    const float* Wk = (const float*)d_in[5];
    const float* bk = (const float*)d_in[6];
    const float* Wv = (const float*)d_in[7];
    const float* bv = (const float*)d_in[8];
    const float* Wo = (const float*)d_in[9];
    const float* bo = (const float*)d_in[10];
    const float* dist_emb  = (const float*)d_in[11];
    const float* attn_bias = (const float*)d_in[12];
    const float* g1 = (const float*)d_in[13];
    const float* b1 = (const float*)d_in[14];
    const float* g2 = (const float*)d_in[15];
    const float* b2 = (const float*)d_in[16];
    const float* Wf1 = (const float*)d_in[17];
    const float* bf1 = (const float*)d_in[18];
    const float* Wf2 = (const float*)d_in[19];
    const float* bf2 = (const float*)d_in[20];

    float *hn, *QKV, *AO, *G;
    unsigned char *msk, *bins;
    cudaGetSymbolAddress((void**)&hn,  g_hn);
    cudaGetSymbolAddress((void**)&QKV, g_qkv);
    cudaGetSymbolAddress((void**)&AO,  g_ao);
    cudaGetSymbolAddress((void**)&G,   g_gl);
    cudaGetSymbolAddress((void**)&msk, g_mask);
    cudaGetSymbolAddress((void**)&bins,g_bins);

    cudaFuncSetAttribute(attn2_kernel,
                         cudaFuncAttributeMaxDynamicSharedMemorySize, ATTN_SMEM);

    float* h = (float*)d_out;
    cudaMemcpyAsync(h, x, (size_t)Md*Hd*sizeof(float), cudaMemcpyDeviceToDevice);
    mask_expand_kernel<<<1,256>>>(mraw);
    bins_kernel<<<(Bd*Nd*Nd + 255)/256, 256>>>(dm, bins, Bd*Nd*Nd);

    dim3 tb(16,16);
    for (int l = 0; l < Lr; l++) {
        // pre-LN attention block
        ln_kernel<<<Md,128>>>(h, g1 + l*Hd, b1 + l*Hd, hn);
        gemm64_kernel<<<dim3(Hd/64, Md/64), tb>>>(hn, Wq + (size_t)l*Hd*Hd, bq + l*Hd, nullptr, QKV, Md, Hd, Hd, QKVLD, 0);
        gemm64_kernel<<<dim3(Hd/64, Md/64), tb>>>(hn, Wk + (size_t)l*Hd*Hd, bk + l*Hd, nullptr, QKV, Md, Hd, Hd, QKVLD, Hd);
        gemm64_kernel<<<dim3(Hd/64, Md/64), tb>>>(hn, Wv + (size_t)l*Hd*Hd, bv + l*Hd, nullptr, QKV, Md, Hd, Hd, QKVLD, 2*Hd);
        attn2_kernel<<<dim3(NHd, Bd), 512, ATTN_SMEM>>>(QKV, bins, msk,
                                                        dist_emb + (size_t)l*NUM_BINS*NHd,
                                                        attn_bias + (size_t)l*NHd, AO);
        gemm64_kernel<<<dim3(Hd/64, Md/64), tb>>>(AO, Wo + (size_t)l*Hd*Hd, bo + l*Hd, h, h, Md, Hd, Hd, Hd, 0);

        // pre-LN GLU FFN (fused GEMM+GLU)
        ln_kernel<<<Md,128>>>(h, g2 + l*Hd, b2 + l*Hd, hn);
        gemm_glu_kernel<<<dim3(FFd/64, Md/64), tb>>>(hn, Wf1 + (size_t)l*Hd*2*FFd, bf1 + (size_t)l*2*FFd, G, Md, Hd);
        gemm64_kernel<<<dim3(Hd/64, Md/64), tb>>>(G, Wf2 + (size_t)l*FFd*Hd, bf2 + l*Hd, h, h, Md, Hd, FFd, Hd, 0);
    }
}

// round 9
// speedup vs baseline: 6.2297x; 1.0449x over previous
#include <cuda_runtime.h>
#include <cstdint>

#define Lr 3
#define Hd 128
#define NHd 8
#define HDd 16
#define FFd 512
#define Bd 32
#define Nd 512
#define NUM_BINS 50
#define Md (Bd*Nd)          // 16384 rows
#define QKVLD 384           // interleaved QKV row stride

// ---------------- scratch (device globals; no allocation allowed) ----------
__device__ float g_hn [(size_t)Md*Hd];
__device__ float g_qkv[(size_t)Md*QKVLD];
__device__ float g_ao [(size_t)Md*Hd];
__device__ float g_gl [(size_t)Md*FFd];
__device__ unsigned char g_mask[Md];
__device__ unsigned char g_bins[(size_t)Bd*Nd*Nd];   // 8.4 MB

// ---------------- mask dtype detection + expansion --------------------------
__global__ void mask_expand_kernel(const void* __restrict__ mraw) {
    __shared__ int s_notint, s_notfloat;
    if (threadIdx.x == 0) { s_notint = 0; s_notfloat = 0; }
    __syncthreads();
    const int* mi = (const int*)mraw;
    int notint = 0, notfloat = 0;
    for (int i = threadIdx.x; i < 4096; i += 256) {
        int v = mi[i];
        if (v != 0 && v != 1) notint = 1;
        if (v != 0 && v != 0x3F800000) notfloat = 1;
    }
    if (notint)   atomicOr(&s_notint, 1);
    if (notfloat) atomicOr(&s_notfloat, 1);
    __syncthreads();
    int isInt   = !s_notint;
    int isFloat = (!s_notfloat) && s_notint;
    for (int i = threadIdx.x; i < Md; i += 256) {
        unsigned char m;
        if (isInt)        m = (unsigned char)(mi[i] != 0);
        else if (isFloat) m = (unsigned char)(((const float*)mraw)[i] != 0.0f);
        else              m = (unsigned char)(((const unsigned char*)mraw)[i] != 0);
        g_mask[i] = m;
    }
}

// ---------------- bins: vectorized, once per call ---------------------------
__global__ void bins_kernel(const float4* __restrict__ dm,
                            uchar4* __restrict__ bins, int n4) {
    int i = blockIdx.x*blockDim.x + threadIdx.x;
    if (i >= n4) return;
    float4 v = dm[i];
    uchar4 o;
    int bx = (int)(v.x*10.0f); o.x = (unsigned char)min(max(bx,0), NUM_BINS-1);
    int by = (int)(v.y*10.0f); o.y = (unsigned char)min(max(by,0), NUM_BINS-1);
    int bz = (int)(v.z*10.0f); o.z = (unsigned char)min(max(bz,0), NUM_BINS-1);
    int bw = (int)(v.w*10.0f); o.w = (unsigned char)min(max(bw,0), NUM_BINS-1);
    bins[i] = o;
}

// ---------------- LayerNorm: warp per row, 8 rows/block ---------------------
__global__ __launch_bounds__(256)
void ln_kernel(const float* __restrict__ h,
               const float* __restrict__ gamma,
               const float* __restrict__ beta,
               float* __restrict__ out) {
    int row = blockIdx.x*8 + (threadIdx.x >> 5);
    int l = threadIdx.x & 31;
    float4 v = ((const float4*)(h + (size_t)row*Hd))[l];
    float s  = (v.x + v.y) + (v.z + v.w);
    float s2 = (v.x*v.x + v.y*v.y) + (v.z*v.z + v.w*v.w);
    #pragma unroll
    for (int o = 16; o; o >>= 1) {
        s  += __shfl_xor_sync(0xffffffffu, s,  o);
        s2 += __shfl_xor_sync(0xffffffffu, s2, o);
    }
    float mean = s * (1.0f/Hd);
    float var  = s2 * (1.0f/Hd) - mean*mean;
    float inv  = rsqrtf(var + 1e-5f);
    float4 g = ((const float4*)gamma)[l];
    float4 bb = ((const float4*)beta)[l];
    float4 o4;
    o4.x = (v.x - mean)*inv*g.x + bb.x;
    o4.y = (v.y - mean)*inv*g.y + bb.y;
    o4.z = (v.z - mean)*inv*g.z + bb.z;
    o4.w = (v.w - mean)*inv*g.w + bb.w;
    ((float4*)(out + (size_t)row*Hd))[l] = o4;
}

// ------------- double-buffered 64x64 GEMM body, 4x4/thread, BK=16 ----------
__device__ __forceinline__
void gemm_body(const float* __restrict__ A, const float* __restrict__ W,
               const float* __restrict__ bias, const float* __restrict__ resid,
               float* __restrict__ C, int N, int K, int ldc, int coff,
               int bm, int bn) {
    __shared__ float As[2][16][64];
    __shared__ float Ws[2][16][64];
    int tx = threadIdx.x, ty = threadIdx.y;
    int tid = ty*16 + tx;

    int aRow = bm + (tid >> 2);
    int aCol = (tid & 3) * 4;
    int wK   = tid >> 4;
    int wN   = (tid & 15) * 4;

    const float* Aptr = &A[(size_t)aRow*K + aCol];
    const float* Wptr = &W[(size_t)wK*N + bn + wN];

    float4 av = *(const float4*)Aptr;
    float4 wv = *(const float4*)Wptr;
    As[0][aCol+0][tid>>2] = av.x;
    As[0][aCol+1][tid>>2] = av.y;
    As[0][aCol+2][tid>>2] = av.z;
    As[0][aCol+3][tid>>2] = av.w;
    *(float4*)&Ws[0][wK][wN] = wv;
    __syncthreads();

    float acc[4][4] = {};
    int buf = 0;
    for (int k0 = 16; k0 <= K; k0 += 16) {
        float4 av2, wv2;
        if (k0 < K) {
            av2 = *(const float4*)(Aptr + k0);
            wv2 = *(const float4*)(Wptr + (size_t)k0*N);
        }
        #pragma unroll
        for (int kk = 0; kk < 16; kk++) {
            float4 a = *(const float4*)&As[buf][kk][ty*4];
            float4 b = *(const float4*)&Ws[buf][kk][tx*4];
            float ar[4] = {a.x,a.y,a.z,a.w};
            float br[4] = {b.x,b.y,b.z,b.w};
            #pragma unroll
            for (int i = 0; i < 4; i++)
                #pragma unroll
                for (int j = 0; j < 4; j++)
                    acc[i][j] += ar[i]*br[j];
        }
        if (k0 < K) {
            As[buf^1][aCol+0][tid>>2] = av2.x;
            As[buf^1][aCol+1][tid>>2] = av2.y;
            As[buf^1][aCol+2][tid>>2] = av2.z;
            As[buf^1][aCol+3][tid>>2] = av2.w;
            *(float4*)&Ws[buf^1][wK][wN] = wv2;
            __syncthreads();
            buf ^= 1;
        }
    }
    #pragma unroll
    for (int i = 0; i < 4; i++) {
        int row = bm + ty*4 + i;
        #pragma unroll
        for (int j = 0; j < 4; j++) {
            int col = bn + tx*4 + j;
            float v = acc[i][j] + bias[col];
            if (resid) v += resid[(size_t)row*ldc + coff + col];
            C[(size_t)row*ldc + coff + col] = v;
        }
    }
}

__global__ __launch_bounds__(256)
void gemm64_kernel(const float* __restrict__ A, const float* __restrict__ W,
                   const float* __restrict__ bias, const float* __restrict__ resid,
                   float* __restrict__ C, int N, int K, int ldc, int coff) {
    gemm_body(A, W, bias, resid, C, N, K, ldc, coff,
              blockIdx.y*64, blockIdx.x*64);
}

// fused QKV: blockIdx.z selects among Wq/Wk/Wv -> QKV interleaved [M,384]
__global__ __launch_bounds__(256)
void qkv_kernel(const float* __restrict__ A,
                const float* __restrict__ Wq, const float* __restrict__ Wk,
                const float* __restrict__ Wv,
                const float* __restrict__ bq, const float* __restrict__ bk,
                const float* __restrict__ bv,
                float* __restrict__ QKV) {
    int z = blockIdx.z;
    const float* W    = (z == 0) ? Wq : (z == 1 ? Wk : Wv);
    const float* bias = (z == 0) ? bq : (z == 1 ? bk : bv);
    gemm_body(A, W, bias, nullptr, QKV, Hd, Hd, QKVLD, z*Hd,
              blockIdx.y*64, blockIdx.x*64);
}

// ---------- GEMM + GLU fused, double-buffered: G = (A@W1a+ba)*sig(A@W1b+bb)
__global__ __launch_bounds__(256)
void gemm_glu_kernel(const float* __restrict__ A,
                     const float* __restrict__ Wf1,
                     const float* __restrict__ bf1,
                     float* __restrict__ G, int K) {
    __shared__ float As [2][16][64];
    __shared__ float Wsa[2][16][64];
    __shared__ float Wsb[2][16][64];
    int tx = threadIdx.x, ty = threadIdx.y;
    int tid = ty*16 + tx;
    int bm = blockIdx.y*64, bn = blockIdx.x*64;

    int aRow = bm + (tid >> 2);
    int aCol = (tid & 3) * 4;
    int wK   = tid >> 4;
    int wN   = (tid & 15) * 4;

    const float* Aptr  = &A[(size_t)aRow*K + aCol];
    const float* Waptr = &Wf1[(size_t)wK*(2*FFd) + bn + wN];
    const float* Wbptr = Waptr + FFd;

    {
        float4 av = *(const float4*)Aptr;
        float4 wa = *(const float4*)Waptr;
        float4 wb = *(const float4*)Wbptr;
        As[0][aCol+0][tid>>2] = av.x;
        As[0][aCol+1][tid>>2] = av.y;
        As[0][aCol+2][tid>>2] = av.z;
        As[0][aCol+3][tid>>2] = av.w;
        *(float4*)&Wsa[0][wK][wN] = wa;
        *(float4*)&Wsb[0][wK][wN] = wb;
    }
    __syncthreads();

    float acca[4][4] = {};
    float accb[4][4] = {};
    int buf = 0;
    for (int k0 = 16; k0 <= K; k0 += 16) {
        float4 av2, wa2, wb2;
        if (k0 < K) {
            av2 = *(const float4*)(Aptr + k0);
            wa2 = *(const float4*)(Waptr + (size_t)k0*(2*FFd));
            wb2 = *(const float4*)(Wbptr + (size_t)k0*(2*FFd));
        }
        #pragma unroll
        for (int kk = 0; kk < 16; kk++) {
            float4 a  = *(const float4*)&As [buf][kk][ty*4];
            float4 ba = *(const float4*)&Wsa[buf][kk][tx*4];
            float4 bb = *(const float4*)&Wsb[buf][kk][tx*4];
            float ar[4]  = {a.x,a.y,a.z,a.w};
            float bra[4] = {ba.x,ba.y,ba.z,ba.w};
            float brb[4] = {bb.x,bb.y,bb.z,bb.w};
            #pragma unroll
            for (int i = 0; i < 4; i++)
                #pragma unroll
                for (int j = 0; j < 4; j++) {
                    acca[i][j] += ar[i]*bra[j];
                    accb[i][j] += ar[i]*brb[j];
                }
        }
        if (k0 < K) {
            As[buf^1][aCol+0][tid>>2] = av2.x;
            As[buf^1][aCol+1][tid>>2] = av2.y;
            As[buf^1][aCol+2][tid>>2] = av2.z;
            As[buf^1][aCol+3][tid>>2] = av2.w;
            *(float4*)&Wsa[buf^1][wK][wN] = wa2;
            *(float4*)&Wsb[buf^1][wK][wN] = wb2;
            __syncthreads();
            buf ^= 1;
        }
    }
    #pragma unroll
    for (int i = 0; i < 4; i++) {
        int row = bm + ty*4 + i;
        #pragma unroll
        for (int j = 0; j < 4; j++) {
            int col = bn + tx*4 + j;
            float ua = acca[i][j] + bf1[col];
            float ub = accb[i][j] + bf1[FFd + col];
            G[(size_t)row*FFd + col] = ua * (1.0f/(1.0f + __expf(-ub)));
        }
    }
}

// ---------------- attention: block per (h, b, qhalf); K/V in smem ----------
#define KVPITCH 17
#define ATTN_SMEM ((2*512*KVPITCH + 16*512 + 52)*4 + 512)

__global__ __launch_bounds__(512, 2)
void attn2_kernel(const float* __restrict__ QKV,
                  const unsigned char* __restrict__ bins,
                  const unsigned char* __restrict__ mask,
                  const float* __restrict__ dist_emb_l,   // [50,8]
                  const float* __restrict__ attn_bias_l,  // [8]
                  float* __restrict__ out) {
    int h = blockIdx.x, b = blockIdx.y;
    int qbase = blockIdx.z * 256;
    extern __shared__ float sm[];
    float* Ks  = sm;
    float* Vs  = Ks + 512*KVPITCH;
    float* sc  = Vs + 512*KVPITCH;
    float* emb = sc + 16*512;
    unsigned char* msk = (unsigned char*)(emb + 52);

    int tid = threadIdx.x;
    int w = tid >> 5, l = tid & 31;

    {   // K/V tile load: one row per thread
        int k = tid;
        const float* kr = QKV + ((size_t)(b*Nd + k)*QKVLD + Hd + h*HDd);
        #pragma unroll
        for (int d = 0; d < 16; d += 4) {
            float4 kv = *(const float4*)&kr[d];
            float4 vv = *(const float4*)&kr[128 + d];
            Ks[k*KVPITCH + d+0] = kv.x; Ks[k*KVPITCH + d+1] = kv.y;
            Ks[k*KVPITCH + d+2] = kv.z; Ks[k*KVPITCH + d+3] = kv.w;
            Vs[k*KVPITCH + d+0] = vv.x; Vs[k*KVPITCH + d+1] = vv.y;
            Vs[k*KVPITCH + d+2] = vv.z; Vs[k*KVPITCH + d+3] = vv.w;
        }
    }
    if (tid < NUM_BINS) emb[tid] = dist_emb_l[tid*NHd + h];
    if (tid < 128) ((uint32_t*)msk)[tid] = ((const uint32_t*)(mask + (size_t)b*Nd))[tid];
    float ab = attn_bias_l[h];
    __syncthreads();

    float* scw = sc + w*512;
    const unsigned char* binb = bins + ((size_t)b*Nd)*Nd;

    int q0 = qbase + w*16;
    for (int q = q0; q < q0 + 16; q++) {
        const float* qr = QKV + ((size_t)(b*Nd + q)*QKVLD + h*HDd);
        float qv[16];
        #pragma unroll
        for (int d = 0; d < 16; d += 4) {
            float4 t = *(const float4*)&qr[d];
            qv[d] = t.x; qv[d+1] = t.y; qv[d+2] = t.z; qv[d+3] = t.w;
        }
        const unsigned char* binrow = binb + (size_t)q*Nd;

        float lmax = -1e30f;
        #pragma unroll
        for (int i = 0; i < 16; i++) {
            int k = l + 32*i;
            const float* kp = &Ks[k*KVPITCH];
            float s0=0, s1=0, s2=0, s3=0;
            #pragma unroll
            for (int d = 0; d < 16; d += 4) {
                s0 += qv[d+0]*kp[d+0];
                s1 += qv[d+1]*kp[d+1];
                s2 += qv[d+2]*kp[d+2];
                s3 += qv[d+3]*kp[d+3];
            }
            float s = (s0+s1)+(s2+s3);
            s = s*0.25f + emb[binrow[k]] + ab;
            if (msk[k]) s = -1e9f;
            scw[k] = s;
            lmax = fmaxf(lmax, s);
        }
        #pragma unroll
        for (int o = 16; o; o >>= 1)
            lmax = fmaxf(lmax, __shfl_xor_sync(0xffffffffu, lmax, o));
        __syncwarp();

        float lsum = 0.0f;
        #pragma unroll
        for (int i = 0; i < 16; i++) {
            int k = l + 32*i;
            float e = __expf(scw[k] - lmax);
            scw[k] = e;
            lsum += e;
        }
        #pragma unroll
        for (int o = 16; o; o >>= 1)
            lsum += __shfl_xor_sync(0xffffffffu, lsum, o);
        float inv = 1.0f/lsum;
        __syncwarp();

        // AV: lanes 0-15 sum k in [0,256), lanes 16-31 sum k in [256,512)
        int d = l & 15;
        int kbase = (l < 16) ? 0 : 256;
        float a0=0, a1=0, a2=0, a3=0;
        #pragma unroll 4
        for (int kk = 0; kk < 256; kk += 4) {
            int k = kbase + kk;
            a0 += scw[k+0]*Vs[(k+0)*KVPITCH + d];
            a1 += scw[k+1]*Vs[(k+1)*KVPITCH + d];
            a2 += scw[k+2]*Vs[(k+2)*KVPITCH + d];
            a3 += scw[k+3]*Vs[(k+3)*KVPITCH + d];
        }
        float acc = (a0+a1)+(a2+a3);
        acc += __shfl_down_sync(0xffffffffu, acc, 16);
        if (l < 16)
            out[((size_t)(b*Nd + q)*Hd) + h*HDd + d] = acc*inv;
        __syncwarp();
    }
}

extern "C" void kernel_launch(void* const* d_in, const int* in_sizes, int n_in,
                              void* d_out, int out_size) {
    const float* x    = (const float*)d_in[0];
    const float* dm   = (const float*)d_in[1];
    const void*  mraw = (const void*)d_in[2];
    const float* Wq = (const float*)d_in[3];
    const float* bq = (const float*)d_in[4];
    const float* Wk = (const float*)d_in[5];
    const float* bk = (const float*)d_in[6];
    const float* Wv = (const float*)d_in[7];
    const float* bv = (const float*)d_in[8];
    const float* Wo = (const float*)d_in[9];
    const float* bo = (const float*)d_in[10];
    const float* dist_emb  = (const float*)d_in[11];
    const float* attn_bias = (const float*)d_in[12];
    const float* g1 = (const float*)d_in[13];
    const float* b1 = (const float*)d_in[14];
    const float* g2 = (const float*)d_in[15];
    const float* b2 = (const float*)d_in[16];
    const float* Wf1 = (const float*)d_in[17];
    const float* bf1 = (const float*)d_in[18];
    const float* Wf2 = (const float*)d_in[19];
    const float* bf2 = (const float*)d_in[20];

    float *hn, *QKV, *AO, *G;
    unsigned char *msk, *bins;
    cudaGetSymbolAddress((void**)&hn,  g_hn);
    cudaGetSymbolAddress((void**)&QKV, g_qkv);
    cudaGetSymbolAddress((void**)&AO,  g_ao);
    cudaGetSymbolAddress((void**)&G,   g_gl);
    cudaGetSymbolAddress((void**)&msk, g_mask);
    cudaGetSymbolAddress((void**)&bins,g_bins);

    cudaFuncSetAttribute(attn2_kernel,
                         cudaFuncAttributeMaxDynamicSharedMemorySize, ATTN_SMEM);

    float* h = (float*)d_out;
    cudaMemcpyAsync(h, x, (size_t)Md*Hd*sizeof(float), cudaMemcpyDeviceToDevice);
    mask_expand_kernel<<<1,256>>>(mraw);
    bins_kernel<<<(Bd*Nd*Nd/4 + 255)/256, 256>>>((const float4*)dm,
                                                 (uchar4*)bins, Bd*Nd*Nd/4);

    dim3 tb(16,16);
    for (int l = 0; l < Lr; l++) {
        // pre-LN attention block
        ln_kernel<<<Md/8,256>>>(h, g1 + l*Hd, b1 + l*Hd, hn);
        qkv_kernel<<<dim3(Hd/64, Md/64, 3), tb>>>(hn,
                Wq + (size_t)l*Hd*Hd, Wk + (size_t)l*Hd*Hd, Wv + (size_t)l*Hd*Hd,
                bq + l*Hd, bk + l*Hd, bv + l*Hd, QKV);
        attn2_kernel<<<dim3(NHd, Bd, 2), 512, ATTN_SMEM>>>(QKV, bins, msk,
                                                dist_emb + (size_t)l*NUM_BINS*NHd,
                                                attn_bias + (size_t)l*NHd, AO);
        gemm64_kernel<<<dim3(Hd/64, Md/64), tb>>>(AO, Wo + (size_t)l*Hd*Hd,
                bo + l*Hd, h, h, Hd, Hd, Hd, 0);

        // pre-LN GLU FFN (fused GEMM+GLU)
        ln_kernel<<<Md/8,256>>>(h, g2 + l*Hd, b2 + l*Hd, hn);
        gemm_glu_kernel<<<dim3(FFd/64, Md/64), tb>>>(hn,
                Wf1 + (size_t)l*Hd*2*FFd, bf1 + (size_t)l*2*FFd, G, Hd);
        gemm64_kernel<<<dim3(Hd/64, Md/64), tb>>>(G, Wf2 + (size_t)l*FFd*Hd,
                bf2 + l*Hd, h, h, Hd, FFd, Hd, 0);
    }
}

// round 10
// speedup vs baseline: 11.9697x; 1.9214x over previous
#include <cuda_runtime.h>
#include <cstdint>

#define Lr 3
#define Hd 128
#define NHd 8
#define HDd 16
#define FFd 512
#define Bd 32
#define Nd 512
#define NUM_BINS 50
#define Md (Bd*Nd)          // 16384 rows
#define QKVLD 384           // interleaved QKV row stride

// ---------------- scratch (device globals; no allocation allowed) ----------
__device__ float g_hn [(size_t)Md*Hd];
__device__ float g_qkv[(size_t)Md*QKVLD];
__device__ float g_ao [(size_t)Md*Hd];
__device__ float g_gl [(size_t)Md*FFd];
__device__ unsigned char g_mask[Md];
__device__ unsigned char g_bins[(size_t)Bd*Nd*Nd];   // 8.4 MB

// ---------------- tf32 helpers ----------------------------------------------
__device__ __forceinline__ uint32_t f2tf32(float f) {
    uint32_t r; asm("cvt.rna.tf32.f32 %0, %1;" : "=r"(r) : "f"(f)); return r;
}
__device__ __forceinline__ void mma_tf32(float& d0, float& d1, float& d2, float& d3,
                                         uint32_t a0, uint32_t a1, uint32_t a2, uint32_t a3,
                                         uint32_t b0, uint32_t b1) {
    asm("mma.sync.aligned.m16n8k8.row.col.f32.tf32.tf32.f32 "
        "{%0,%1,%2,%3}, {%4,%5,%6,%7}, {%8,%9}, {%0,%1,%2,%3};"
        : "+f"(d0), "+f"(d1), "+f"(d2), "+f"(d3)
        : "r"(a0), "r"(a1), "r"(a2), "r"(a3), "r"(b0), "r"(b1));
}

// ---------------- mask dtype detection + expansion --------------------------
__global__ void mask_expand_kernel(const void* __restrict__ mraw) {
    __shared__ int s_notint, s_notfloat;
    if (threadIdx.x == 0) { s_notint = 0; s_notfloat = 0; }
    __syncthreads();
    const int* mi = (const int*)mraw;
    int notint = 0, notfloat = 0;
    for (int i = threadIdx.x; i < 4096; i += 256) {
        int v = mi[i];
        if (v != 0 && v != 1) notint = 1;
        if (v != 0 && v != 0x3F800000) notfloat = 1;
    }
    if (notint)   atomicOr(&s_notint, 1);
    if (notfloat) atomicOr(&s_notfloat, 1);
    __syncthreads();
    int isInt   = !s_notint;
    int isFloat = (!s_notfloat) && s_notint;
    for (int i = threadIdx.x; i < Md; i += 256) {
        unsigned char m;
        if (isInt)        m = (unsigned char)(mi[i] != 0);
        else if (isFloat) m = (unsigned char)(((const float*)mraw)[i] != 0.0f);
        else              m = (unsigned char)(((const unsigned char*)mraw)[i] != 0);
        g_mask[i] = m;
    }
}

// ---------------- bins: vectorized, once per call ---------------------------
__global__ void bins_kernel(const float4* __restrict__ dm,
                            uchar4* __restrict__ bins, int n4) {
    int i = blockIdx.x*blockDim.x + threadIdx.x;
    if (i >= n4) return;
    float4 v = dm[i];
    uchar4 o;
    int bx = (int)(v.x*10.0f); o.x = (unsigned char)min(max(bx,0), NUM_BINS-1);
    int by = (int)(v.y*10.0f); o.y = (unsigned char)min(max(by,0), NUM_BINS-1);
    int bz = (int)(v.z*10.0f); o.z = (unsigned char)min(max(bz,0), NUM_BINS-1);
    int bw = (int)(v.w*10.0f); o.w = (unsigned char)min(max(bw,0), NUM_BINS-1);
    bins[i] = o;
}

// ---------------- LayerNorm: warp per row, 8 rows/block ---------------------
__global__ __launch_bounds__(256)
void ln_kernel(const float* __restrict__ h,
               const float* __restrict__ gamma,
               const float* __restrict__ beta,
               float* __restrict__ out) {
    int row = blockIdx.x*8 + (threadIdx.x >> 5);
    int l = threadIdx.x & 31;
    float4 v = ((const float4*)(h + (size_t)row*Hd))[l];
    float s  = (v.x + v.y) + (v.z + v.w);
    float s2 = (v.x*v.x + v.y*v.y) + (v.z*v.z + v.w*v.w);
    #pragma unroll
    for (int o = 16; o; o >>= 1) {
        s  += __shfl_xor_sync(0xffffffffu, s,  o);
        s2 += __shfl_xor_sync(0xffffffffu, s2, o);
    }
    float mean = s * (1.0f/Hd);
    float var  = s2 * (1.0f/Hd) - mean*mean;
    float inv  = rsqrtf(var + 1e-5f);
    float4 g = ((const float4*)gamma)[l];
    float4 bb = ((const float4*)beta)[l];
    float4 o4;
    o4.x = (v.x - mean)*inv*g.x + bb.x;
    o4.y = (v.y - mean)*inv*g.y + bb.y;
    o4.z = (v.z - mean)*inv*g.z + bb.z;
    o4.w = (v.w - mean)*inv*g.w + bb.w;
    ((float4*)(out + (size_t)row*Hd))[l] = o4;
}

// ------------- double-buffered 64x64 GEMM body, 4x4/thread, BK=16 ----------
__device__ __forceinline__
void gemm_body(const float* __restrict__ A, const float* __restrict__ W,
               const float* __restrict__ bias, const float* __restrict__ resid,
               float* __restrict__ C, int N, int K, int ldc, int coff,
               int bm, int bn) {
    __shared__ float As[2][16][64];
    __shared__ float Ws[2][16][64];
    int tx = threadIdx.x, ty = threadIdx.y;
    int tid = ty*16 + tx;

    int aRow = bm + (tid >> 2);
    int aCol = (tid & 3) * 4;
    int wK   = tid >> 4;
    int wN   = (tid & 15) * 4;

    const float* Aptr = &A[(size_t)aRow*K + aCol];
    const float* Wptr = &W[(size_t)wK*N + bn + wN];

    float4 av = *(const float4*)Aptr;
    float4 wv = *(const float4*)Wptr;
    As[0][aCol+0][tid>>2] = av.x;
    As[0][aCol+1][tid>>2] = av.y;
    As[0][aCol+2][tid>>2] = av.z;
    As[0][aCol+3][tid>>2] = av.w;
    *(float4*)&Ws[0][wK][wN] = wv;
    __syncthreads();

    float acc[4][4] = {};
    int buf = 0;
    for (int k0 = 16; k0 <= K; k0 += 16) {
        float4 av2, wv2;
        if (k0 < K) {
            av2 = *(const float4*)(Aptr + k0);
            wv2 = *(const float4*)(Wptr + (size_t)k0*N);
        }
        #pragma unroll
        for (int kk = 0; kk < 16; kk++) {
            float4 a = *(const float4*)&As[buf][kk][ty*4];
            float4 b = *(const float4*)&Ws[buf][kk][tx*4];
            float ar[4] = {a.x,a.y,a.z,a.w};
            float br[4] = {b.x,b.y,b.z,b.w};
            #pragma unroll
            for (int i = 0; i < 4; i++)
                #pragma unroll
                for (int j = 0; j < 4; j++)
                    acc[i][j] += ar[i]*br[j];
        }
        if (k0 < K) {
            As[buf^1][aCol+0][tid>>2] = av2.x;
            As[buf^1][aCol+1][tid>>2] = av2.y;
            As[buf^1][aCol+2][tid>>2] = av2.z;
            As[buf^1][aCol+3][tid>>2] = av2.w;
            *(float4*)&Ws[buf^1][wK][wN] = wv2;
            __syncthreads();
            buf ^= 1;
        }
    }
    #pragma unroll
    for (int i = 0; i < 4; i++) {
        int row = bm + ty*4 + i;
        #pragma unroll
        for (int j = 0; j < 4; j++) {
            int col = bn + tx*4 + j;
            float v = acc[i][j] + bias[col];
            if (resid) v += resid[(size_t)row*ldc + coff + col];
            C[(size_t)row*ldc + coff + col] = v;
        }
    }
}

__global__ __launch_bounds__(256)
void gemm64_kernel(const float* __restrict__ A, const float* __restrict__ W,
                   const float* __restrict__ bias, const float* __restrict__ resid,
                   float* __restrict__ C, int N, int K, int ldc, int coff) {
    gemm_body(A, W, bias, resid, C, N, K, ldc, coff,
              blockIdx.y*64, blockIdx.x*64);
}

// fused QKV: blockIdx.z selects among Wq/Wk/Wv -> QKV interleaved [M,384]
__global__ __launch_bounds__(256)
void qkv_kernel(const float* __restrict__ A,
                const float* __restrict__ Wq, const float* __restrict__ Wk,
                const float* __restrict__ Wv,
                const float* __restrict__ bq, const float* __restrict__ bk,
                const float* __restrict__ bv,
                float* __restrict__ QKV) {
    int z = blockIdx.z;
    const float* W    = (z == 0) ? Wq : (z == 1 ? Wk : Wv);
    const float* bias = (z == 0) ? bq : (z == 1 ? bk : bv);
    gemm_body(A, W, bias, nullptr, QKV, Hd, Hd, QKVLD, z*Hd,
              blockIdx.y*64, blockIdx.x*64);
}

// ---------- GEMM + GLU fused, double-buffered: G = (A@W1a+ba)*sig(A@W1b+bb)
__global__ __launch_bounds__(256)
void gemm_glu_kernel(const float* __restrict__ A,
                     const float* __restrict__ Wf1,
                     const float* __restrict__ bf1,
                     float* __restrict__ G, int K) {
    __shared__ float As [2][16][64];
    __shared__ float Wsa[2][16][64];
    __shared__ float Wsb[2][16][64];
    int tx = threadIdx.x, ty = threadIdx.y;
    int tid = ty*16 + tx;
    int bm = blockIdx.y*64, bn = blockIdx.x*64;

    int aRow = bm + (tid >> 2);
    int aCol = (tid & 3) * 4;
    int wK   = tid >> 4;
    int wN   = (tid & 15) * 4;

    const float* Aptr  = &A[(size_t)aRow*K + aCol];
    const float* Waptr = &Wf1[(size_t)wK*(2*FFd) + bn + wN];
    const float* Wbptr = Waptr + FFd;

    {
        float4 av = *(const float4*)Aptr;
        float4 wa = *(const float4*)Waptr;
        float4 wb = *(const float4*)Wbptr;
        As[0][aCol+0][tid>>2] = av.x;
        As[0][aCol+1][tid>>2] = av.y;
        As[0][aCol+2][tid>>2] = av.z;
        As[0][aCol+3][tid>>2] = av.w;
        *(float4*)&Wsa[0][wK][wN] = wa;
        *(float4*)&Wsb[0][wK][wN] = wb;
    }
    __syncthreads();

    float acca[4][4] = {};
    float accb[4][4] = {};
    int buf = 0;
    for (int k0 = 16; k0 <= K; k0 += 16) {
        float4 av2, wa2, wb2;
        if (k0 < K) {
            av2 = *(const float4*)(Aptr + k0);
            wa2 = *(const float4*)(Waptr + (size_t)k0*(2*FFd));
            wb2 = *(const float4*)(Wbptr + (size_t)k0*(2*FFd));
        }
        #pragma unroll
        for (int kk = 0; kk < 16; kk++) {
            float4 a  = *(const float4*)&As [buf][kk][ty*4];
            float4 ba = *(const float4*)&Wsa[buf][kk][tx*4];
            float4 bb = *(const float4*)&Wsb[buf][kk][tx*4];
            float ar[4]  = {a.x,a.y,a.z,a.w};
            float bra[4] = {ba.x,ba.y,ba.z,ba.w};
            float brb[4] = {bb.x,bb.y,bb.z,bb.w};
            #pragma unroll
            for (int i = 0; i < 4; i++)
                #pragma unroll
                for (int j = 0; j < 4; j++) {
                    acca[i][j] += ar[i]*bra[j];
                    accb[i][j] += ar[i]*brb[j];
                }
        }
        if (k0 < K) {
            As[buf^1][aCol+0][tid>>2] = av2.x;
            As[buf^1][aCol+1][tid>>2] = av2.y;
            As[buf^1][aCol+2][tid>>2] = av2.z;
            As[buf^1][aCol+3][tid>>2] = av2.w;
            *(float4*)&Wsa[buf^1][wK][wN] = wa2;
            *(float4*)&Wsb[buf^1][wK][wN] = wb2;
            __syncthreads();
            buf ^= 1;
        }
    }
    #pragma unroll
    for (int i = 0; i < 4; i++) {
        int row = bm + ty*4 + i;
        #pragma unroll
        for (int j = 0; j < 4; j++) {
            int col = bn + tx*4 + j;
            float ua = acca[i][j] + bf1[col];
            float ub = accb[i][j] + bf1[FFd + col];
            G[(size_t)row*FFd + col] = ua * (1.0f/(1.0f + __expf(-ub)));
        }
    }
}

// ============ attention v3: tf32 mma flash-style, block per (h,b,half) ======
// 512 threads = 16 warps; each warp owns 16 queries for the whole 512-key pass.
// Kt[d][key] pitch 520 (conflict-free B-frag reads: banks 8*t4+g),
// Vs[key][d] pitch 24  (conflict-free B-frag reads: banks 24*t4+g).
#define KT_PITCH 520
#define V_PITCH  24
#define ATTN_SMEM ((16*KT_PITCH + 512*V_PITCH + 512 + 64)*4)

__global__ __launch_bounds__(512, 2)
void attn3_kernel(const float* __restrict__ QKV,
                  const unsigned char* __restrict__ bins,
                  const unsigned char* __restrict__ mask,
                  const float* __restrict__ dist_emb_l,   // [50,8]
                  const float* __restrict__ attn_bias_l,  // [8]
                  float* __restrict__ out) {
    int h = blockIdx.x, b = blockIdx.y;
    extern __shared__ uint32_t smu[];
    uint32_t* Kt = smu;                         // [16][KT_PITCH]
    uint32_t* Vs = Kt + 16*KT_PITCH;            // [512][V_PITCH]
    float* mb    = (float*)(Vs + 512*V_PITCH);  // [512] additive mask bias
    float* emb2  = mb + 512;                    // [50] emb + attn_bias

    int tid = threadIdx.x;
    {   // stage K (transposed) and V as tf32; one key row per thread
        int k = tid;
        const float* kr = QKV + ((size_t)(b*Nd + k)*QKVLD + Hd + h*HDd);
        #pragma unroll
        for (int d = 0; d < 16; d++) Kt[d*KT_PITCH + k] = f2tf32(kr[d]);
        #pragma unroll
        for (int d = 0; d < 16; d++) Vs[k*V_PITCH + d] = f2tf32(kr[128 + d]);
        mb[k] = mask[(size_t)b*Nd + k] ? -1e9f : 0.0f;
    }
    if (tid < NUM_BINS) emb2[tid] = dist_emb_l[tid*NHd + h] + attn_bias_l[h];
    __syncthreads();

    int lane = tid & 31, w = tid >> 5;
    int g = lane >> 2, t4 = lane & 3;
    int qbase = blockIdx.z*256 + w*16;

    // Q fragments for 16 queries x 16 dims (2 k8 steps), resident in regs
    const float* qp = QKV + ((size_t)(b*Nd + qbase)*QKVLD + h*HDd);
    uint32_t qa[8];
    #pragma unroll
    for (int s = 0; s < 2; s++) {
        qa[s*4+0] = f2tf32(qp[(size_t)g    *QKVLD + s*8 + t4]);
        qa[s*4+1] = f2tf32(qp[(size_t)(g+8)*QKVLD + s*8 + t4]);
        qa[s*4+2] = f2tf32(qp[(size_t)g    *QKVLD + s*8 + t4+4]);
        qa[s*4+3] = f2tf32(qp[(size_t)(g+8)*QKVLD + s*8 + t4+4]);
    }

    const uchar2* br0 = (const uchar2*)(bins + ((size_t)(b*Nd + qbase+g  ))*Nd);
    const uchar2* br1 = (const uchar2*)(bins + ((size_t)(b*Nd + qbase+g+8))*Nd);

    // O accumulators: ntile0 (d=2t4,2t4+1) o0..o3; ntile1 (+8) o4..o7
    float o0=0,o1=0,o2=0,o3=0,o4=0,o5=0,o6=0,o7=0;
    float m0=-1e30f, m1=-1e30f, l0=0.0f, l1=0.0f;

    uchar2 nb0 = br0[t4], nb1 = br1[t4];   // prefetch first chunk's bins

    for (int kc = 0; kc < Nd; kc += 8) {
        uchar2 bn0 = nb0, bn1 = nb1;
        if (kc + 8 < Nd) { nb0 = br0[(kc+8)/2 + t4]; nb1 = br1[(kc+8)/2 + t4]; }

        // K^T fragments (B): rows d = t4,t4+4 (step0) / +8 (step1); col = key kc+g
        uint32_t kb0 = Kt[ t4      *KT_PITCH + kc + g];
        uint32_t kb1 = Kt[(t4+4 )  *KT_PITCH + kc + g];
        uint32_t kb2 = Kt[(t4+8 )  *KT_PITCH + kc + g];
        uint32_t kb3 = Kt[(t4+12)  *KT_PITCH + kc + g];

        // S[16q x 8k] — lane owns (q=g, k=kc+2t4 / +1) and (q=g+8, same k)
        float s0=0,s1=0,s2=0,s3=0;
        mma_tf32(s0,s1,s2,s3, qa[0],qa[1],qa[2],qa[3], kb0,kb1);
        mma_tf32(s0,s1,s2,s3, qa[4],qa[5],qa[6],qa[7], kb2,kb3);

        float mbl0 = mb[kc + 2*t4], mbl1 = mb[kc + 2*t4 + 1];
        s0 = s0*0.25f + emb2[bn0.x] + mbl0;
        s1 = s1*0.25f + emb2[bn0.y] + mbl1;
        s2 = s2*0.25f + emb2[bn1.x] + mbl0;
        s3 = s3*0.25f + emb2[bn1.y] + mbl1;

        // online softmax over this 8-key chunk (row = q; quad t4 covers 8 keys)
        float cm0 = fmaxf(s0, s1), cm1 = fmaxf(s2, s3);
        cm0 = fmaxf(cm0, __shfl_xor_sync(0xffffffffu, cm0, 1));
        cm0 = fmaxf(cm0, __shfl_xor_sync(0xffffffffu, cm0, 2));
        cm1 = fmaxf(cm1, __shfl_xor_sync(0xffffffffu, cm1, 1));
        cm1 = fmaxf(cm1, __shfl_xor_sync(0xffffffffu, cm1, 2));
        float m0n = fmaxf(m0, cm0), m1n = fmaxf(m1, cm1);
        float sc0 = __expf(m0 - m0n), sc1 = __expf(m1 - m1n);
        float p0 = __expf(s0 - m0n), p1 = __expf(s1 - m0n);
        float p2 = __expf(s2 - m1n), p3 = __expf(s3 - m1n);
        float rs0 = p0 + p1, rs1 = p2 + p3;
        rs0 += __shfl_xor_sync(0xffffffffu, rs0, 1);
        rs0 += __shfl_xor_sync(0xffffffffu, rs0, 2);
        rs1 += __shfl_xor_sync(0xffffffffu, rs1, 1);
        rs1 += __shfl_xor_sync(0xffffffffu, rs1, 2);
        l0 = l0*sc0 + rs0;  l1 = l1*sc1 + rs1;
        m0 = m0n;  m1 = m1n;
        o0 *= sc0; o1 *= sc0; o4 *= sc0; o5 *= sc0;   // rows q=g
        o2 *= sc1; o3 *= sc1; o6 *= sc1; o7 *= sc1;   // rows q=g+8

        // permute P (C-layout) -> A-frag layout: a = P[row][kc + t4 (+4)]
        int qsl0 = (lane & ~3) | (t4 >> 1);
        int qsl1 = qsl0 + 2;
        bool odd = (t4 & 1);
        float x0a = __shfl_sync(0xffffffffu, p0, qsl0);
        float x0b = __shfl_sync(0xffffffffu, p1, qsl0);
        float x2a = __shfl_sync(0xffffffffu, p0, qsl1);
        float x2b = __shfl_sync(0xffffffffu, p1, qsl1);
        float x1a = __shfl_sync(0xffffffffu, p2, qsl0);
        float x1b = __shfl_sync(0xffffffffu, p3, qsl0);
        float x3a = __shfl_sync(0xffffffffu, p2, qsl1);
        float x3b = __shfl_sync(0xffffffffu, p3, qsl1);
        uint32_t pa0 = __float_as_uint(odd ? x0b : x0a);   // (g,    t4)
        uint32_t pa1 = __float_as_uint(odd ? x1b : x1a);   // (g+8,  t4)
        uint32_t pa2 = __float_as_uint(odd ? x2b : x2a);   // (g,    t4+4)
        uint32_t pa3 = __float_as_uint(odd ? x3b : x3a);   // (g+8,  t4+4)

        // V fragments (B): row k = kc+t4 (+4); col d = g (ntile0) / g+8 (ntile1)
        uint32_t vb0 = Vs[(kc + t4    )*V_PITCH + g];
        uint32_t vb1 = Vs[(kc + t4 + 4)*V_PITCH + g];
        uint32_t vb2 = Vs[(kc + t4    )*V_PITCH + g + 8];
        uint32_t vb3 = Vs[(kc + t4 + 4)*V_PITCH + g + 8];

        mma_tf32(o0,o1,o2,o3, pa0,pa1,pa2,pa3, vb0,vb1);
        mma_tf32(o4,o5,o6,o7, pa0,pa1,pa2,pa3, vb2,vb3);
    }

    // epilogue: divide by row sums and store (cols h*16 + 2t4 (+1), +8)
    float i0 = 1.0f/l0, i1 = 1.0f/l1;
    float* orow0 = out + ((size_t)(b*Nd + qbase + g    ))*Hd + h*HDd + 2*t4;
    float* orow1 = out + ((size_t)(b*Nd + qbase + g + 8))*Hd + h*HDd + 2*t4;
    *(float2*)(orow0    ) = make_float2(o0*i0, o1*i0);
    *(float2*)(orow0 + 8) = make_float2(o4*i0, o5*i0);
    *(float2*)(orow1    ) = make_float2(o2*i1, o3*i1);
    *(float2*)(orow1 + 8) = make_float2(o6*i1, o7*i1);
}

extern "C" void kernel_launch(void* const* d_in, const int* in_sizes, int n_in,
                              void* d_out, int out_size) {
    const float* x    = (const float*)d_in[0];
    const float* dm   = (const float*)d_in[1];
    const void*  mraw = (const void*)d_in[2];
    const float* Wq = (const float*)d_in[3];
    const float* bq = (const float*)d_in[4];
    const float* Wk = (const float*)d_in[5];
    const float* bk = (const float*)d_in[6];
    const float* Wv = (const float*)d_in[7];
    const float* bv = (const float*)d_in[8];
    const float* Wo = (const float*)d_in[9];
    const float* bo = (const float*)d_in[10];
    const float* dist_emb  = (const float*)d_in[11];
    const float* attn_bias = (const float*)d_in[12];
    const float* g1 = (const float*)d_in[13];
    const float* b1 = (const float*)d_in[14];
    const float* g2 = (const float*)d_in[15];
    const float* b2 = (const float*)d_in[16];
    const float* Wf1 = (const float*)d_in[17];
    const float* bf1 = (const float*)d_in[18];
    const float* Wf2 = (const float*)d_in[19];
    const float* bf2 = (const float*)d_in[20];

    float *hn, *QKV, *AO, *G;
    unsigned char *msk, *bins;
    cudaGetSymbolAddress((void**)&hn,  g_hn);
    cudaGetSymbolAddress((void**)&QKV, g_qkv);
    cudaGetSymbolAddress((void**)&AO,  g_ao);
    cudaGetSymbolAddress((void**)&G,   g_gl);
    cudaGetSymbolAddress((void**)&msk, g_mask);
    cudaGetSymbolAddress((void**)&bins,g_bins);

    cudaFuncSetAttribute(attn3_kernel,
                         cudaFuncAttributeMaxDynamicSharedMemorySize, ATTN_SMEM);

    float* h = (float*)d_out;
    cudaMemcpyAsync(h, x, (size_t)Md*Hd*sizeof(float), cudaMemcpyDeviceToDevice);
    mask_expand_kernel<<<1,256>>>(mraw);
    bins_kernel<<<(Bd*Nd*Nd/4 + 255)/256, 256>>>((const float4*)dm,
                                                 (uchar4*)bins, Bd*Nd*Nd/4);

    dim3 tb(16,16);
    for (int l = 0; l < Lr; l++) {
        // pre-LN attention block
        ln_kernel<<<Md/8,256>>>(h, g1 + l*Hd, b1 + l*Hd, hn);
        qkv_kernel<<<dim3(Hd/64, Md/64, 3), tb>>>(hn,
                Wq + (size_t)l*Hd*Hd, Wk + (size_t)l*Hd*Hd, Wv + (size_t)l*Hd*Hd,
                bq + l*Hd, bk + l*Hd, bv + l*Hd, QKV);
        attn3_kernel<<<dim3(NHd, Bd, 2), 512, ATTN_SMEM>>>(QKV, bins, msk,
                                                dist_emb + (size_t)l*NUM_BINS*NHd,
                                                attn_bias + (size_t)l*NHd, AO);
        gemm64_kernel<<<dim3(Hd/64, Md/64), tb>>>(AO, Wo + (size_t)l*Hd*Hd,
                bo + l*Hd, h, h, Hd, Hd, Hd, 0);

        // pre-LN GLU FFN (fused GEMM+GLU)
        ln_kernel<<<Md/8,256>>>(h, g2 + l*Hd, b2 + l*Hd, hn);
        gemm_glu_kernel<<<dim3(FFd/64, Md/64), tb>>>(hn,
                Wf1 + (size_t)l*Hd*2*FFd, bf1 + (size_t)l*2*FFd, G, Hd);
        gemm64_kernel<<<dim3(Hd/64, Md/64), tb>>>(G, Wf2 + (size_t)l*FFd*Hd,
                bf2 + l*Hd, h, h, Hd, FFd, Hd, 0);
    }
}

// round 11
// speedup vs baseline: 17.9585x; 1.5003x over previous
#include <cuda_runtime.h>
#include <cstdint>

#define Lr 3
#define Hd 128
#define NHd 8
#define HDd 16
#define FFd 512
#define Bd 32
#define Nd 512
#define NUM_BINS 50
#define Md (Bd*Nd)          // 16384 rows
#define QKVLD 384           // interleaved QKV row stride

// ---------------- scratch (device globals; no allocation allowed) ----------
__device__ float g_hn [(size_t)Md*Hd];
__device__ float g_qkv[(size_t)Md*QKVLD];
__device__ float g_ao [(size_t)Md*Hd];
__device__ float g_gl [(size_t)Md*FFd];
__device__ unsigned char g_mask[Md];
__device__ unsigned char g_bins[(size_t)Bd*Nd*Nd];   // 8.4 MB

// ---------------- tf32 helpers ----------------------------------------------
__device__ __forceinline__ uint32_t f2tf32(float f) {
    uint32_t r; asm("cvt.rna.tf32.f32 %0, %1;" : "=r"(r) : "f"(f)); return r;
}
__device__ __forceinline__ void mma_tf32(float& d0, float& d1, float& d2, float& d3,
                                         uint32_t a0, uint32_t a1, uint32_t a2, uint32_t a3,
                                         uint32_t b0, uint32_t b1) {
    asm("mma.sync.aligned.m16n8k8.row.col.f32.tf32.tf32.f32 "
        "{%0,%1,%2,%3}, {%4,%5,%6,%7}, {%8,%9}, {%0,%1,%2,%3};"
        : "+f"(d0), "+f"(d1), "+f"(d2), "+f"(d3)
        : "r"(a0), "r"(a1), "r"(a2), "r"(a3), "r"(b0), "r"(b1));
}

// ---------------- mask dtype detection + expansion --------------------------
__global__ void mask_expand_kernel(const void* __restrict__ mraw) {
    __shared__ int s_notint, s_notfloat;
    if (threadIdx.x == 0) { s_notint = 0; s_notfloat = 0; }
    __syncthreads();
    const int* mi = (const int*)mraw;
    int notint = 0, notfloat = 0;
    for (int i = threadIdx.x; i < 4096; i += 256) {
        int v = mi[i];
        if (v != 0 && v != 1) notint = 1;
        if (v != 0 && v != 0x3F800000) notfloat = 1;
    }
    if (notint)   atomicOr(&s_notint, 1);
    if (notfloat) atomicOr(&s_notfloat, 1);
    __syncthreads();
    int isInt   = !s_notint;
    int isFloat = (!s_notfloat) && s_notint;
    for (int i = threadIdx.x; i < Md; i += 256) {
        unsigned char m;
        if (isInt)        m = (unsigned char)(mi[i] != 0);
        else if (isFloat) m = (unsigned char)(((const float*)mraw)[i] != 0.0f);
        else              m = (unsigned char)(((const unsigned char*)mraw)[i] != 0);
        g_mask[i] = m;
    }
}

// ---------------- bins: vectorized, once per call ---------------------------
__global__ void bins_kernel(const float4* __restrict__ dm,
                            uchar4* __restrict__ bins, int n4) {
    int i = blockIdx.x*blockDim.x + threadIdx.x;
    if (i >= n4) return;
    float4 v = dm[i];
    uchar4 o;
    int bx = (int)(v.x*10.0f); o.x = (unsigned char)min(max(bx,0), NUM_BINS-1);
    int by = (int)(v.y*10.0f); o.y = (unsigned char)min(max(by,0), NUM_BINS-1);
    int bz = (int)(v.z*10.0f); o.z = (unsigned char)min(max(bz,0), NUM_BINS-1);
    int bw = (int)(v.w*10.0f); o.w = (unsigned char)min(max(bw,0), NUM_BINS-1);
    bins[i] = o;
}

// ---------------- LayerNorm: warp per row, 8 rows/block ---------------------
__global__ __launch_bounds__(256)
void ln_kernel(const float* __restrict__ h,
               const float* __restrict__ gamma,
               const float* __restrict__ beta,
               float* __restrict__ out) {
    int row = blockIdx.x*8 + (threadIdx.x >> 5);
    int l = threadIdx.x & 31;
    float4 v = ((const float4*)(h + (size_t)row*Hd))[l];
    float s  = (v.x + v.y) + (v.z + v.w);
    float s2 = (v.x*v.x + v.y*v.y) + (v.z*v.z + v.w*v.w);
    #pragma unroll
    for (int o = 16; o; o >>= 1) {
        s  += __shfl_xor_sync(0xffffffffu, s,  o);
        s2 += __shfl_xor_sync(0xffffffffu, s2, o);
    }
    float mean = s * (1.0f/Hd);
    float var  = s2 * (1.0f/Hd) - mean*mean;
    float inv  = rsqrtf(var + 1e-5f);
    float4 g = ((const float4*)gamma)[l];
    float4 bb = ((const float4*)beta)[l];
    float4 o4;
    o4.x = (v.x - mean)*inv*g.x + bb.x;
    o4.y = (v.y - mean)*inv*g.y + bb.y;
    o4.z = (v.z - mean)*inv*g.z + bb.z;
    o4.w = (v.w - mean)*inv*g.w + bb.w;
    ((float4*)(out + (size_t)row*Hd))[l] = o4;
}

// ======== tf32 MMA GEMM: 128x64 block tile, 8 warps (warp = 64M x 16N) ======
// AsT[k][m] pitch 136 (conflict-free a-frags), Ws[k][n] pitch 72 (b-frags).
#define ATP 136
#define WTP 72

__device__ __forceinline__
void gemm_mma_body(const float* __restrict__ A, const float* __restrict__ W,
                   const float* __restrict__ bias, const float* __restrict__ resid,
                   float* __restrict__ C, int N, int K, int ldc, int coff,
                   int bm, int bn) {
    __shared__ uint32_t AsT[2][16][ATP];
    __shared__ uint32_t Ws [2][16][WTP];
    int tid = threadIdx.x;
    int lane = tid & 31, wid = tid >> 5;
    int g = lane >> 2, t4 = lane & 3;
    int wm = (wid & 1) * 64, wn = (wid >> 1) * 16;

    int aRow = tid >> 2;            // 0..63
    int aCol = (tid & 3) * 4;
    int wK = tid >> 4, wN = (tid & 15) * 4;

    const float* Aptr  = A + (size_t)(bm + aRow)*K + aCol;
    const float* Aptr2 = Aptr + (size_t)64*K;
    const float* Wptr  = W + (size_t)wK*N + bn + wN;

    {
        float4 x = *(const float4*)Aptr;
        float4 y = *(const float4*)Aptr2;
        float4 w = *(const float4*)Wptr;
        AsT[0][aCol+0][aRow] = f2tf32(x.x); AsT[0][aCol+1][aRow] = f2tf32(x.y);
        AsT[0][aCol+2][aRow] = f2tf32(x.z); AsT[0][aCol+3][aRow] = f2tf32(x.w);
        AsT[0][aCol+0][aRow+64] = f2tf32(y.x); AsT[0][aCol+1][aRow+64] = f2tf32(y.y);
        AsT[0][aCol+2][aRow+64] = f2tf32(y.z); AsT[0][aCol+3][aRow+64] = f2tf32(y.w);
        Ws[0][wK][wN+0] = f2tf32(w.x); Ws[0][wK][wN+1] = f2tf32(w.y);
        Ws[0][wK][wN+2] = f2tf32(w.z); Ws[0][wK][wN+3] = f2tf32(w.w);
    }
    __syncthreads();

    float acc[4][2][4] = {};
    int buf = 0;
    for (int k0 = 16; k0 <= K; k0 += 16) {
        float4 xn, yn, wnv;
        if (k0 < K) {
            xn  = *(const float4*)(Aptr  + k0);
            yn  = *(const float4*)(Aptr2 + k0);
            wnv = *(const float4*)(Wptr + (size_t)k0*N);
        }
        #pragma unroll
        for (int ks = 0; ks < 2; ks++) {
            int kr = ks*8 + t4;
            uint32_t b00 = Ws[buf][kr  ][wn + g];
            uint32_t b01 = Ws[buf][kr+4][wn + g];
            uint32_t b10 = Ws[buf][kr  ][wn + 8 + g];
            uint32_t b11 = Ws[buf][kr+4][wn + 8 + g];
            #pragma unroll
            for (int mt = 0; mt < 4; mt++) {
                int mb = wm + mt*16;
                uint32_t a0 = AsT[buf][kr  ][mb+g];
                uint32_t a1 = AsT[buf][kr  ][mb+g+8];
                uint32_t a2 = AsT[buf][kr+4][mb+g];
                uint32_t a3 = AsT[buf][kr+4][mb+g+8];
                mma_tf32(acc[mt][0][0],acc[mt][0][1],acc[mt][0][2],acc[mt][0][3],
                         a0,a1,a2,a3, b00,b01);
                mma_tf32(acc[mt][1][0],acc[mt][1][1],acc[mt][1][2],acc[mt][1][3],
                         a0,a1,a2,a3, b10,b11);
            }
        }
        if (k0 < K) {
            int nb = buf^1;
            AsT[nb][aCol+0][aRow] = f2tf32(xn.x); AsT[nb][aCol+1][aRow] = f2tf32(xn.y);
            AsT[nb][aCol+2][aRow] = f2tf32(xn.z); AsT[nb][aCol+3][aRow] = f2tf32(xn.w);
            AsT[nb][aCol+0][aRow+64] = f2tf32(yn.x); AsT[nb][aCol+1][aRow+64] = f2tf32(yn.y);
            AsT[nb][aCol+2][aRow+64] = f2tf32(yn.z); AsT[nb][aCol+3][aRow+64] = f2tf32(yn.w);
            Ws[nb][wK][wN+0] = f2tf32(wnv.x); Ws[nb][wK][wN+1] = f2tf32(wnv.y);
            Ws[nb][wK][wN+2] = f2tf32(wnv.z); Ws[nb][wK][wN+3] = f2tf32(wnv.w);
            __syncthreads();
            buf ^= 1;
        }
    }

    #pragma unroll
    for (int mt = 0; mt < 4; mt++) {
        int r0 = bm + wm + mt*16 + g;
        #pragma unroll
        for (int nt = 0; nt < 2; nt++) {
            int col = bn + wn + nt*8 + 2*t4;
            float b0 = bias[col], b1 = bias[col+1];
            float v0 = acc[mt][nt][0] + b0, v1 = acc[mt][nt][1] + b1;
            float v2 = acc[mt][nt][2] + b0, v3 = acc[mt][nt][3] + b1;
            if (resid) {
                float2 r0v = *(const float2*)&resid[(size_t)r0*ldc + coff + col];
                float2 r1v = *(const float2*)&resid[(size_t)(r0+8)*ldc + coff + col];
                v0 += r0v.x; v1 += r0v.y; v2 += r1v.x; v3 += r1v.y;
            }
            *(float2*)&C[(size_t)r0*ldc + coff + col]     = make_float2(v0, v1);
            *(float2*)&C[(size_t)(r0+8)*ldc + coff + col] = make_float2(v2, v3);
        }
    }
}

__global__ __launch_bounds__(256)
void gemm_mma_kernel(const float* __restrict__ A, const float* __restrict__ W,
                     const float* __restrict__ bias, const float* __restrict__ resid,
                     float* __restrict__ C, int N, int K, int ldc, int coff) {
    gemm_mma_body(A, W, bias, resid, C, N, K, ldc, coff,
                  blockIdx.y*128, blockIdx.x*64);
}

// fused QKV: blockIdx.z selects among Wq/Wk/Wv -> QKV interleaved [M,384]
__global__ __launch_bounds__(256)
void qkv_mma_kernel(const float* __restrict__ A,
                    const float* __restrict__ Wq, const float* __restrict__ Wk,
                    const float* __restrict__ Wv,
                    const float* __restrict__ bq, const float* __restrict__ bk,
                    const float* __restrict__ bv,
                    float* __restrict__ QKV) {
    int z = blockIdx.z;
    const float* W    = (z == 0) ? Wq : (z == 1 ? Wk : Wv);
    const float* bias = (z == 0) ? bq : (z == 1 ? bk : bv);
    gemm_mma_body(A, W, bias, nullptr, QKV, Hd, Hd, QKVLD, z*Hd,
                  blockIdx.y*128, blockIdx.x*64);
}

// ---- tf32 MMA GEMM + GLU: G = (A@W1a+ba)*sigmoid(A@W1b+bb), both halves ----
__global__ __launch_bounds__(256)
void glu_mma_kernel(const float* __restrict__ A,
                    const float* __restrict__ Wf1,
                    const float* __restrict__ bf1,
                    float* __restrict__ G, int K) {
    __shared__ uint32_t AsT[2][16][ATP];
    __shared__ uint32_t Wsa[2][16][WTP];
    __shared__ uint32_t Wsb[2][16][WTP];
    int tid = threadIdx.x;
    int lane = tid & 31, wid = tid >> 5;
    int g = lane >> 2, t4 = lane & 3;
    int wm = (wid & 1) * 64, wn = (wid >> 1) * 16;
    int bm = blockIdx.y*128, bn = blockIdx.x*64;

    int aRow = tid >> 2;
    int aCol = (tid & 3) * 4;
    int wK = tid >> 4, wN = (tid & 15) * 4;

    const float* Aptr  = A + (size_t)(bm + aRow)*K + aCol;
    const float* Aptr2 = Aptr + (size_t)64*K;
    const float* Waptr = Wf1 + (size_t)wK*(2*FFd) + bn + wN;
    const float* Wbptr = Waptr + FFd;

    {
        float4 x = *(const float4*)Aptr;
        float4 y = *(const float4*)Aptr2;
        float4 wa = *(const float4*)Waptr;
        float4 wb = *(const float4*)Wbptr;
        AsT[0][aCol+0][aRow] = f2tf32(x.x); AsT[0][aCol+1][aRow] = f2tf32(x.y);
        AsT[0][aCol+2][aRow] = f2tf32(x.z); AsT[0][aCol+3][aRow] = f2tf32(x.w);
        AsT[0][aCol+0][aRow+64] = f2tf32(y.x); AsT[0][aCol+1][aRow+64] = f2tf32(y.y);
        AsT[0][aCol+2][aRow+64] = f2tf32(y.z); AsT[0][aCol+3][aRow+64] = f2tf32(y.w);
        Wsa[0][wK][wN+0] = f2tf32(wa.x); Wsa[0][wK][wN+1] = f2tf32(wa.y);
        Wsa[0][wK][wN+2] = f2tf32(wa.z); Wsa[0][wK][wN+3] = f2tf32(wa.w);
        Wsb[0][wK][wN+0] = f2tf32(wb.x); Wsb[0][wK][wN+1] = f2tf32(wb.y);
        Wsb[0][wK][wN+2] = f2tf32(wb.z); Wsb[0][wK][wN+3] = f2tf32(wb.w);
    }
    __syncthreads();

    float acca[4][2][4] = {};
    float accb[4][2][4] = {};
    int buf = 0;
    for (int k0 = 16; k0 <= K; k0 += 16) {
        float4 xn, yn, wan, wbn;
        if (k0 < K) {
            xn  = *(const float4*)(Aptr  + k0);
            yn  = *(const float4*)(Aptr2 + k0);
            wan = *(const float4*)(Waptr + (size_t)k0*(2*FFd));
            wbn = *(const float4*)(Wbptr + (size_t)k0*(2*FFd));
        }
        #pragma unroll
        for (int ks = 0; ks < 2; ks++) {
            int kr = ks*8 + t4;
            uint32_t ba00 = Wsa[buf][kr  ][wn + g];
            uint32_t ba01 = Wsa[buf][kr+4][wn + g];
            uint32_t ba10 = Wsa[buf][kr  ][wn + 8 + g];
            uint32_t ba11 = Wsa[buf][kr+4][wn + 8 + g];
            uint32_t bb00 = Wsb[buf][kr  ][wn + g];
            uint32_t bb01 = Wsb[buf][kr+4][wn + g];
            uint32_t bb10 = Wsb[buf][kr  ][wn + 8 + g];
            uint32_t bb11 = Wsb[buf][kr+4][wn + 8 + g];
            #pragma unroll
            for (int mt = 0; mt < 4; mt++) {
                int mb = wm + mt*16;
                uint32_t a0 = AsT[buf][kr  ][mb+g];
                uint32_t a1 = AsT[buf][kr  ][mb+g+8];
                uint32_t a2 = AsT[buf][kr+4][mb+g];
                uint32_t a3 = AsT[buf][kr+4][mb+g+8];
                mma_tf32(acca[mt][0][0],acca[mt][0][1],acca[mt][0][2],acca[mt][0][3],
                         a0,a1,a2,a3, ba00,ba01);
                mma_tf32(acca[mt][1][0],acca[mt][1][1],acca[mt][1][2],acca[mt][1][3],
                         a0,a1,a2,a3, ba10,ba11);
                mma_tf32(accb[mt][0][0],accb[mt][0][1],accb[mt][0][2],accb[mt][0][3],
                         a0,a1,a2,a3, bb00,bb01);
                mma_tf32(accb[mt][1][0],accb[mt][1][1],accb[mt][1][2],accb[mt][1][3],
                         a0,a1,a2,a3, bb10,bb11);
            }
        }
        if (k0 < K) {
            int nb = buf^1;
            AsT[nb][aCol+0][aRow] = f2tf32(xn.x); AsT[nb][aCol+1][aRow] = f2tf32(xn.y);
            AsT[nb][aCol+2][aRow] = f2tf32(xn.z); AsT[nb][aCol+3][aRow] = f2tf32(xn.w);
            AsT[nb][aCol+0][aRow+64] = f2tf32(yn.x); AsT[nb][aCol+1][aRow+64] = f2tf32(yn.y);
            AsT[nb][aCol+2][aRow+64] = f2tf32(yn.z); AsT[nb][aCol+3][aRow+64] = f2tf32(yn.w);
            Wsa[nb][wK][wN+0] = f2tf32(wan.x); Wsa[nb][wK][wN+1] = f2tf32(wan.y);
            Wsa[nb][wK][wN+2] = f2tf32(wan.z); Wsa[nb][wK][wN+3] = f2tf32(wan.w);
            Wsb[nb][wK][wN+0] = f2tf32(wbn.x); Wsb[nb][wK][wN+1] = f2tf32(wbn.y);
            Wsb[nb][wK][wN+2] = f2tf32(wbn.z); Wsb[nb][wK][wN+3] = f2tf32(wbn.w);
            __syncthreads();
            buf ^= 1;
        }
    }

    #pragma unroll
    for (int mt = 0; mt < 4; mt++) {
        int r0 = bm + wm + mt*16 + g;
        #pragma unroll
        for (int nt = 0; nt < 2; nt++) {
            int col = bn + wn + nt*8 + 2*t4;
            float ba0 = bf1[col], ba1 = bf1[col+1];
            float bb0 = bf1[FFd + col], bb1 = bf1[FFd + col+1];
            float ua0 = acca[mt][nt][0] + ba0, ua1 = acca[mt][nt][1] + ba1;
            float ua2 = acca[mt][nt][2] + ba0, ua3 = acca[mt][nt][3] + ba1;
            float ub0 = accb[mt][nt][0] + bb0, ub1 = accb[mt][nt][1] + bb1;
            float ub2 = accb[mt][nt][2] + bb0, ub3 = accb[mt][nt][3] + bb1;
            float g0 = ua0 * (1.0f/(1.0f + __expf(-ub0)));
            float g1 = ua1 * (1.0f/(1.0f + __expf(-ub1)));
            float g2 = ua2 * (1.0f/(1.0f + __expf(-ub2)));
            float g3 = ua3 * (1.0f/(1.0f + __expf(-ub3)));
            *(float2*)&G[(size_t)r0*FFd + col]     = make_float2(g0, g1);
            *(float2*)&G[(size_t)(r0+8)*FFd + col] = make_float2(g2, g3);
        }
    }
}

// ============ attention v3: tf32 mma flash-style, block per (h,b,half) ======
#define KT_PITCH 520
#define V_PITCH  24
#define ATTN_SMEM ((16*KT_PITCH + 512*V_PITCH + 512 + 64)*4)

__global__ __launch_bounds__(512, 2)
void attn3_kernel(const float* __restrict__ QKV,
                  const unsigned char* __restrict__ bins,
                  const unsigned char* __restrict__ mask,
                  const float* __restrict__ dist_emb_l,   // [50,8]
                  const float* __restrict__ attn_bias_l,  // [8]
                  float* __restrict__ out) {
    int h = blockIdx.x, b = blockIdx.y;
    extern __shared__ uint32_t smu[];
    uint32_t* Kt = smu;                         // [16][KT_PITCH]
    uint32_t* Vs = Kt + 16*KT_PITCH;            // [512][V_PITCH]
    float* mb    = (float*)(Vs + 512*V_PITCH);  // [512] additive mask bias
    float* emb2  = mb + 512;                    // [50] emb + attn_bias

    int tid = threadIdx.x;
    {
        int k = tid;
        const float* kr = QKV + ((size_t)(b*Nd + k)*QKVLD + Hd + h*HDd);
        #pragma unroll
        for (int d = 0; d < 16; d++) Kt[d*KT_PITCH + k] = f2tf32(kr[d]);
        #pragma unroll
        for (int d = 0; d < 16; d++) Vs[k*V_PITCH + d] = f2tf32(kr[128 + d]);
        mb[k] = mask[(size_t)b*Nd + k] ? -1e9f : 0.0f;
    }
    if (tid < NUM_BINS) emb2[tid] = dist_emb_l[tid*NHd + h] + attn_bias_l[h];
    __syncthreads();

    int lane = tid & 31, w = tid >> 5;
    int g = lane >> 2, t4 = lane & 3;
    int qbase = blockIdx.z*256 + w*16;

    const float* qp = QKV + ((size_t)(b*Nd + qbase)*QKVLD + h*HDd);
    uint32_t qa[8];
    #pragma unroll
    for (int s = 0; s < 2; s++) {
        qa[s*4+0] = f2tf32(qp[(size_t)g    *QKVLD + s*8 + t4]);
        qa[s*4+1] = f2tf32(qp[(size_t)(g+8)*QKVLD + s*8 + t4]);
        qa[s*4+2] = f2tf32(qp[(size_t)g    *QKVLD + s*8 + t4+4]);
        qa[s*4+3] = f2tf32(qp[(size_t)(g+8)*QKVLD + s*8 + t4+4]);
    }

    const uchar2* br0 = (const uchar2*)(bins + ((size_t)(b*Nd + qbase+g  ))*Nd);
    const uchar2* br1 = (const uchar2*)(bins + ((size_t)(b*Nd + qbase+g+8))*Nd);

    float o0=0,o1=0,o2=0,o3=0,o4=0,o5=0,o6=0,o7=0;
    float m0=-1e30f, m1=-1e30f, l0=0.0f, l1=0.0f;

    uchar2 nb0 = br0[t4], nb1 = br1[t4];

    for (int kc = 0; kc < Nd; kc += 8) {
        uchar2 bn0 = nb0, bn1 = nb1;
        if (kc + 8 < Nd) { nb0 = br0[(kc+8)/2 + t4]; nb1 = br1[(kc+8)/2 + t4]; }

        uint32_t kb0 = Kt[ t4      *KT_PITCH + kc + g];
        uint32_t kb1 = Kt[(t4+4 )  *KT_PITCH + kc + g];
        uint32_t kb2 = Kt[(t4+8 )  *KT_PITCH + kc + g];
        uint32_t kb3 = Kt[(t4+12)  *KT_PITCH + kc + g];

        float s0=0,s1=0,s2=0,s3=0;
        mma_tf32(s0,s1,s2,s3, qa[0],qa[1],qa[2],qa[3], kb0,kb1);
        mma_tf32(s0,s1,s2,s3, qa[4],qa[5],qa[6],qa[7], kb2,kb3);

        float mbl0 = mb[kc + 2*t4], mbl1 = mb[kc + 2*t4 + 1];
        s0 = s0*0.25f + emb2[bn0.x] + mbl0;
        s1 = s1*0.25f + emb2[bn0.y] + mbl1;
        s2 = s2*0.25f + emb2[bn1.x] + mbl0;
        s3 = s3*0.25f + emb2[bn1.y] + mbl1;

        float cm0 = fmaxf(s0, s1), cm1 = fmaxf(s2, s3);
        cm0 = fmaxf(cm0, __shfl_xor_sync(0xffffffffu, cm0, 1));
        cm0 = fmaxf(cm0, __shfl_xor_sync(0xffffffffu, cm0, 2));
        cm1 = fmaxf(cm1, __shfl_xor_sync(0xffffffffu, cm1, 1));
        cm1 = fmaxf(cm1, __shfl_xor_sync(0xffffffffu, cm1, 2));
        float m0n = fmaxf(m0, cm0), m1n = fmaxf(m1, cm1);
        float sc0 = __expf(m0 - m0n), sc1 = __expf(m1 - m1n);
        float p0 = __expf(s0 - m0n), p1 = __expf(s1 - m0n);
        float p2 = __expf(s2 - m1n), p3 = __expf(s3 - m1n);
        float rs0 = p0 + p1, rs1 = p2 + p3;
        rs0 += __shfl_xor_sync(0xffffffffu, rs0, 1);
        rs0 += __shfl_xor_sync(0xffffffffu, rs0, 2);
        rs1 += __shfl_xor_sync(0xffffffffu, rs1, 1);
        rs1 += __shfl_xor_sync(0xffffffffu, rs1, 2);
        l0 = l0*sc0 + rs0;  l1 = l1*sc1 + rs1;
        m0 = m0n;  m1 = m1n;
        o0 *= sc0; o1 *= sc0; o4 *= sc0; o5 *= sc0;
        o2 *= sc1; o3 *= sc1; o6 *= sc1; o7 *= sc1;

        int qsl0 = (lane & ~3) | (t4 >> 1);
        int qsl1 = qsl0 + 2;
        bool odd = (t4 & 1);
        float x0a = __shfl_sync(0xffffffffu, p0, qsl0);
        float x0b = __shfl_sync(0xffffffffu, p1, qsl0);
        float x2a = __shfl_sync(0xffffffffu, p0, qsl1);
        float x2b = __shfl_sync(0xffffffffu, p1, qsl1);
        float x1a = __shfl_sync(0xffffffffu, p2, qsl0);
        float x1b = __shfl_sync(0xffffffffu, p3, qsl0);
        float x3a = __shfl_sync(0xffffffffu, p2, qsl1);
        float x3b = __shfl_sync(0xffffffffu, p3, qsl1);
        uint32_t pa0 = __float_as_uint(odd ? x0b : x0a);
        uint32_t pa1 = __float_as_uint(odd ? x1b : x1a);
        uint32_t pa2 = __float_as_uint(odd ? x2b : x2a);
        uint32_t pa3 = __float_as_uint(odd ? x3b : x3a);

        uint32_t vb0 = Vs[(kc + t4    )*V_PITCH + g];
        uint32_t vb1 = Vs[(kc + t4 + 4)*V_PITCH + g];
        uint32_t vb2 = Vs[(kc + t4    )*V_PITCH + g + 8];
        uint32_t vb3 = Vs[(kc + t4 + 4)*V_PITCH + g + 8];

        mma_tf32(o0,o1,o2,o3, pa0,pa1,pa2,pa3, vb0,vb1);
        mma_tf32(o4,o5,o6,o7, pa0,pa1,pa2,pa3, vb2,vb3);
    }

    float i0 = 1.0f/l0, i1 = 1.0f/l1;
    float* orow0 = out + ((size_t)(b*Nd + qbase + g    ))*Hd + h*HDd + 2*t4;
    float* orow1 = out + ((size_t)(b*Nd + qbase + g + 8))*Hd + h*HDd + 2*t4;
    *(float2*)(orow0    ) = make_float2(o0*i0, o1*i0);
    *(float2*)(orow0 + 8) = make_float2(o4*i0, o5*i0);
    *(float2*)(orow1    ) = make_float2(o2*i1, o3*i1);
    *(float2*)(orow1 + 8) = make_float2(o6*i1, o7*i1);
}

extern "C" void kernel_launch(void* const* d_in, const int* in_sizes, int n_in,
                              void* d_out, int out_size) {
    const float* x    = (const float*)d_in[0];
    const float* dm   = (const float*)d_in[1];
    const void*  mraw = (const void*)d_in[2];
    const float* Wq = (const float*)d_in[3];
    const float* bq = (const float*)d_in[4];
    const float* Wk = (const float*)d_in[5];
    const float* bk = (const float*)d_in[6];
    const float* Wv = (const float*)d_in[7];
    const float* bv = (const float*)d_in[8];
    const float* Wo = (const float*)d_in[9];
    const float* bo = (const float*)d_in[10];
    const float* dist_emb  = (const float*)d_in[11];
    const float* attn_bias = (const float*)d_in[12];
    const float* g1 = (const float*)d_in[13];
    const float* b1 = (const float*)d_in[14];
    const float* g2 = (const float*)d_in[15];
    const float* b2 = (const float*)d_in[16];
    const float* Wf1 = (const float*)d_in[17];
    const float* bf1 = (const float*)d_in[18];
    const float* Wf2 = (const float*)d_in[19];
    const float* bf2 = (const float*)d_in[20];

    float *hn, *QKV, *AO, *G;
    unsigned char *msk, *bins;
    cudaGetSymbolAddress((void**)&hn,  g_hn);
    cudaGetSymbolAddress((void**)&QKV, g_qkv);
    cudaGetSymbolAddress((void**)&AO,  g_ao);
    cudaGetSymbolAddress((void**)&G,   g_gl);
    cudaGetSymbolAddress((void**)&msk, g_mask);
    cudaGetSymbolAddress((void**)&bins,g_bins);

    cudaFuncSetAttribute(attn3_kernel,
                         cudaFuncAttributeMaxDynamicSharedMemorySize, ATTN_SMEM);

    float* h = (float*)d_out;
    cudaMemcpyAsync(h, x, (size_t)Md*Hd*sizeof(float), cudaMemcpyDeviceToDevice);
    mask_expand_kernel<<<1,256>>>(mraw);
    bins_kernel<<<(Bd*Nd*Nd/4 + 255)/256, 256>>>((const float4*)dm,
                                                 (uchar4*)bins, Bd*Nd*Nd/4);

    for (int l = 0; l < Lr; l++) {
        // pre-LN attention block
        ln_kernel<<<Md/8,256>>>(h, g1 + l*Hd, b1 + l*Hd, hn);
        qkv_mma_kernel<<<dim3(Hd/64, Md/128, 3), 256>>>(hn,
                Wq + (size_t)l*Hd*Hd, Wk + (size_t)l*Hd*Hd, Wv + (size_t)l*Hd*Hd,
                bq + l*Hd, bk + l*Hd, bv + l*Hd, QKV);
        attn3_kernel<<<dim3(NHd, Bd, 2), 512, ATTN_SMEM>>>(QKV, bins, msk,
                                                dist_emb + (size_t)l*NUM_BINS*NHd,
                                                attn_bias + (size_t)l*NHd, AO);
        gemm_mma_kernel<<<dim3(Hd/64, Md/128), 256>>>(AO, Wo + (size_t)l*Hd*Hd,
                bo + l*Hd, h, h, Hd, Hd, Hd, 0);

        // pre-LN GLU FFN (fused GEMM+GLU)
        ln_kernel<<<Md/8,256>>>(h, g2 + l*Hd, b2 + l*Hd, hn);
        glu_mma_kernel<<<dim3(FFd/64, Md/128), 256>>>(hn,
                Wf1 + (size_t)l*Hd*2*FFd, bf1 + (size_t)l*2*FFd, G, Hd);
        gemm_mma_kernel<<<dim3(Hd/64, Md/128), 256>>>(G, Wf2 + (size_t)l*FFd*Hd,
                bf2 + l*Hd, h, h, Hd, FFd, Hd, 0);
    }
}

// round 13
// speedup vs baseline: 20.1752x; 1.1234x over previous
#include <cuda_runtime.h>
#include <cstdint>

#define Lr 3
#define Hd 128
#define NHd 8
#define HDd 16
#define FFd 512
#define Bd 32
#define Nd 512
#define NUM_BINS 50
#define Md (Bd*Nd)          // 16384 rows
#define QKVLD 384           // interleaved QKV row stride

// ---------------- scratch (device globals; no allocation allowed) ----------
__device__ float g_hn [(size_t)Md*Hd];
__device__ float g_qkv[(size_t)Md*QKVLD];
__device__ float g_ao [(size_t)Md*Hd];
__device__ float g_gl [(size_t)Md*FFd];
__device__ unsigned char g_mask[Md];
__device__ unsigned char g_bins[(size_t)Bd*Nd*Nd];   // 8.4 MB

// ---------------- helpers ----------------------------------------------------
__device__ __forceinline__ uint32_t f2tf32(float f) {
    uint32_t r; asm("cvt.rna.tf32.f32 %0, %1;" : "=r"(r) : "f"(f)); return r;
}
__device__ __forceinline__ void mma_tf32(float& d0, float& d1, float& d2, float& d3,
                                         uint32_t a0, uint32_t a1, uint32_t a2, uint32_t a3,
                                         uint32_t b0, uint32_t b1) {
    asm("mma.sync.aligned.m16n8k8.row.col.f32.tf32.tf32.f32 "
        "{%0,%1,%2,%3}, {%4,%5,%6,%7}, {%8,%9}, {%0,%1,%2,%3};"
        : "+f"(d0), "+f"(d1), "+f"(d2), "+f"(d3)
        : "r"(a0), "r"(a1), "r"(a2), "r"(a3), "r"(b0), "r"(b1));
}
__device__ __forceinline__ uint32_t smem_u32(const void* p) {
    uint32_t a;
    asm("{ .reg .u64 t; cvta.to.shared.u64 t, %1; cvt.u32.u64 %0, t; }"
        : "=r"(a) : "l"(p));
    return a;
}
#define CP16(dst,src)  asm volatile("cp.async.cg.shared.global [%0], [%1], 16;" :: "r"(dst), "l"(src))
#define CPCOMMIT()     asm volatile("cp.async.commit_group;")
#define CPWAIT1()      asm volatile("cp.async.wait_group 1;")
#define CPWAIT0()      asm volatile("cp.async.wait_group 0;")

// ---------------- mask dtype detection + expansion --------------------------
__global__ void mask_expand_kernel(const void* __restrict__ mraw) {
    __shared__ int s_notint, s_notfloat;
    if (threadIdx.x == 0) { s_notint = 0; s_notfloat = 0; }
    __syncthreads();
    const int* mi = (const int*)mraw;
    int notint = 0, notfloat = 0;
    for (int i = threadIdx.x; i < 4096; i += 256) {
        int v = mi[i];
        if (v != 0 && v != 1) notint = 1;
        if (v != 0 && v != 0x3F800000) notfloat = 1;
    }
    if (notint)   atomicOr(&s_notint, 1);
    if (notfloat) atomicOr(&s_notfloat, 1);
    __syncthreads();
    int isInt   = !s_notint;
    int isFloat = (!s_notfloat) && s_notint;
    for (int i = threadIdx.x; i < Md; i += 256) {
        unsigned char m;
        if (isInt)        m = (unsigned char)(mi[i] != 0);
        else if (isFloat) m = (unsigned char)(((const float*)mraw)[i] != 0.0f);
        else              m = (unsigned char)(((const unsigned char*)mraw)[i] != 0);
        g_mask[i] = m;
    }
}

// ---------------- bins: vectorized, once per call ---------------------------
__global__ void bins_kernel(const float4* __restrict__ dm,
                            uchar4* __restrict__ bins, int n4) {
    int i = blockIdx.x*blockDim.x + threadIdx.x;
    if (i >= n4) return;
    float4 v = dm[i];
    uchar4 o;
    int bx = (int)(v.x*10.0f); o.x = (unsigned char)min(max(bx,0), NUM_BINS-1);
    int by = (int)(v.y*10.0f); o.y = (unsigned char)min(max(by,0), NUM_BINS-1);
    int bz = (int)(v.z*10.0f); o.z = (unsigned char)min(max(bz,0), NUM_BINS-1);
    int bw = (int)(v.w*10.0f); o.w = (unsigned char)min(max(bw,0), NUM_BINS-1);
    bins[i] = o;
}

// ---------------- LayerNorm: warp per row, 8 rows/block ---------------------
__global__ __launch_bounds__(256)
void ln_kernel(const float* __restrict__ h,
               const float* __restrict__ gamma,
               const float* __restrict__ beta,
               float* __restrict__ out) {
    int row = blockIdx.x*8 + (threadIdx.x >> 5);
    int l = threadIdx.x & 31;
    float4 v = ((const float4*)(h + (size_t)row*Hd))[l];
    float s  = (v.x + v.y) + (v.z + v.w);
    float s2 = (v.x*v.x + v.y*v.y) + (v.z*v.z + v.w*v.w);
    #pragma unroll
    for (int o = 16; o; o >>= 1) {
        s  += __shfl_xor_sync(0xffffffffu, s,  o);
        s2 += __shfl_xor_sync(0xffffffffu, s2, o);
    }
    float mean = s * (1.0f/Hd);
    float var  = s2 * (1.0f/Hd) - mean*mean;
    float inv  = rsqrtf(var + 1e-5f);
    float4 g = ((const float4*)gamma)[l];
    float4 bb = ((const float4*)beta)[l];
    float4 o4;
    o4.x = (v.x - mean)*inv*g.x + bb.x;
    o4.y = (v.y - mean)*inv*g.y + bb.y;
    o4.z = (v.z - mean)*inv*g.z + bb.z;
    o4.w = (v.w - mean)*inv*g.w + bb.w;
    ((float4*)(out + (size_t)row*Hd))[l] = o4;
}

// ======== tf32 MMA GEMM, cp.async 3-stage: 128x64 tile, 8 warps =============
// As[m][k] pitch 20 floats (frag banks 20g+t4 -> all 32 distinct),
// Ws[k][n] pitch 72 floats (frag banks 8t4+g  -> all 32 distinct).
#define ATP2 20
#define WTP2 72

__device__ __forceinline__
void gemm_mma_body(const float* __restrict__ A, const float* __restrict__ W,
                   const float* __restrict__ bias, const float* __restrict__ resid,
                   float* __restrict__ C, int N, int K, int ldc, int coff,
                   int bm, int bn) {
    __shared__ __align__(16) float As[3][128][ATP2];
    __shared__ __align__(16) float Ws[3][16][WTP2];
    int tid = threadIdx.x, lane = tid & 31, wid = tid >> 5;
    int g = lane >> 2, t4 = lane & 3;
    int wm = (wid & 1) * 64, wn = (wid >> 1) * 16;

    int arow = tid >> 1, ahalf = tid & 1;
    int wrow = tid >> 4, wc = tid & 15;
    const float* aSrc = A + (size_t)(bm + arow)*K + ahalf*8;
    const float* wSrc = W + (size_t)wrow*N + bn + wc*4;

    uint32_t aDst[3], wDst[3];
    #pragma unroll
    for (int s = 0; s < 3; s++) {
        aDst[s] = smem_u32(&As[s][arow][ahalf*8]);
        wDst[s] = smem_u32(&Ws[s][wrow][wc*4]);
    }

    int nkt = K >> 4;
    #pragma unroll
    for (int pf = 0; pf < 2; pf++) {           // nkt >= 8 always
        CP16(aDst[pf],      aSrc + pf*16);
        CP16(aDst[pf] + 16, aSrc + pf*16 + 4);
        CP16(wDst[pf],      wSrc + (size_t)pf*16*N);
        CPCOMMIT();
    }

    float acc[4][2][4] = {};
    for (int kt = 0; kt < nkt; kt++) {
        if (kt == nkt-1) { CPWAIT0(); } else { CPWAIT1(); }
        __syncthreads();
        if (kt + 2 < nkt) {
            int s = (kt+2) % 3;
            CP16(aDst[s],      aSrc + (kt+2)*16);
            CP16(aDst[s] + 16, aSrc + (kt+2)*16 + 4);
            CP16(wDst[s],      wSrc + (size_t)(kt+2)*16*N);
            CPCOMMIT();
        }
        int buf = kt % 3;
        #pragma unroll
        for (int ks = 0; ks < 2; ks++) {
            int kr = ks*8 + t4;
            uint32_t b00 = __float_as_uint(Ws[buf][kr  ][wn + g]);
            uint32_t b01 = __float_as_uint(Ws[buf][kr+4][wn + g]);
            uint32_t b10 = __float_as_uint(Ws[buf][kr  ][wn + 8 + g]);
            uint32_t b11 = __float_as_uint(Ws[buf][kr+4][wn + 8 + g]);
            #pragma unroll
            for (int mt = 0; mt < 4; mt++) {
                int mb = wm + mt*16;
                uint32_t a0 = __float_as_uint(As[buf][mb+g  ][kr  ]);
                uint32_t a1 = __float_as_uint(As[buf][mb+g+8][kr  ]);
                uint32_t a2 = __float_as_uint(As[buf][mb+g  ][kr+4]);
                uint32_t a3 = __float_as_uint(As[buf][mb+g+8][kr+4]);
                mma_tf32(acc[mt][0][0],acc[mt][0][1],acc[mt][0][2],acc[mt][0][3],
                         a0,a1,a2,a3, b00,b01);
                mma_tf32(acc[mt][1][0],acc[mt][1][1],acc[mt][1][2],acc[mt][1][3],
                         a0,a1,a2,a3, b10,b11);
            }
        }
    }

    #pragma unroll
    for (int mt = 0; mt < 4; mt++) {
        int r0 = bm + wm + mt*16 + g;
        #pragma unroll
        for (int nt = 0; nt < 2; nt++) {
            int col = bn + wn + nt*8 + 2*t4;
            float b0 = bias[col], b1 = bias[col+1];
            float v0 = acc[mt][nt][0] + b0, v1 = acc[mt][nt][1] + b1;
            float v2 = acc[mt][nt][2] + b0, v3 = acc[mt][nt][3] + b1;
            if (resid) {
                float2 r0v = *(const float2*)&resid[(size_t)r0*ldc + coff + col];
                float2 r1v = *(const float2*)&resid[(size_t)(r0+8)*ldc + coff + col];
                v0 += r0v.x; v1 += r0v.y; v2 += r1v.x; v3 += r1v.y;
            }
            *(float2*)&C[(size_t)r0*ldc + coff + col]     = make_float2(v0, v1);
            *(float2*)&C[(size_t)(r0+8)*ldc + coff + col] = make_float2(v2, v3);
        }
    }
}

__global__ __launch_bounds__(256)
void gemm_mma_kernel(const float* __restrict__ A, const float* __restrict__ W,
                     const float* __restrict__ bias, const float* __restrict__ resid,
                     float* __restrict__ C, int N, int K, int ldc, int coff) {
    gemm_mma_body(A, W, bias, resid, C, N, K, ldc, coff,
                  blockIdx.y*128, blockIdx.x*64);
}

__global__ __launch_bounds__(256)
void qkv_mma_kernel(const float* __restrict__ A,
                    const float* __restrict__ Wq, const float* __restrict__ Wk,
                    const float* __restrict__ Wv,
                    const float* __restrict__ bq, const float* __restrict__ bk,
                    const float* __restrict__ bv,
                    float* __restrict__ QKV) {
    int z = blockIdx.z;
    const float* W    = (z == 0) ? Wq : (z == 1 ? Wk : Wv);
    const float* bias = (z == 0) ? bq : (z == 1 ? bk : bv);
    gemm_mma_body(A, W, bias, nullptr, QKV, Hd, Hd, QKVLD, z*Hd,
                  blockIdx.y*128, blockIdx.x*64);
}

// ---- tf32 MMA GEMM + GLU, cp.async 3-stage ---------------------------------
__global__ __launch_bounds__(256)
void glu_mma_kernel(const float* __restrict__ A,
                    const float* __restrict__ Wf1,
                    const float* __restrict__ bf1,
                    float* __restrict__ G, int K) {
    __shared__ __align__(16) float As [3][128][ATP2];
    __shared__ __align__(16) float Wsa[3][16][WTP2];
    __shared__ __align__(16) float Wsb[3][16][WTP2];
    int tid = threadIdx.x, lane = tid & 31, wid = tid >> 5;
    int g = lane >> 2, t4 = lane & 3;
    int wm = (wid & 1) * 64, wn = (wid >> 1) * 16;
    int bm = blockIdx.y*128, bn = blockIdx.x*64;

    int arow = tid >> 1, ahalf = tid & 1;
    int wrow = tid >> 4, wc = tid & 15;
    const float* aSrc  = A + (size_t)(bm + arow)*K + ahalf*8;
    const float* waSrc = Wf1 + (size_t)wrow*(2*FFd) + bn + wc*4;
    const float* wbSrc = waSrc + FFd;

    uint32_t aDst[3], waDst[3], wbDst[3];
    #pragma unroll
    for (int s = 0; s < 3; s++) {
        aDst[s]  = smem_u32(&As [s][arow][ahalf*8]);
        waDst[s] = smem_u32(&Wsa[s][wrow][wc*4]);
        wbDst[s] = smem_u32(&Wsb[s][wrow][wc*4]);
    }

    int nkt = K >> 4;
    #pragma unroll
    for (int pf = 0; pf < 2; pf++) {
        CP16(aDst[pf],      aSrc + pf*16);
        CP16(aDst[pf] + 16, aSrc + pf*16 + 4);
        CP16(waDst[pf],     waSrc + (size_t)pf*16*(2*FFd));
        CP16(wbDst[pf],     wbSrc + (size_t)pf*16*(2*FFd));
        CPCOMMIT();
    }

    float acca[4][2][4] = {};
    float accb[4][2][4] = {};
    for (int kt = 0; kt < nkt; kt++) {
        if (kt == nkt-1) { CPWAIT0(); } else { CPWAIT1(); }
        __syncthreads();
        if (kt + 2 < nkt) {
            int s = (kt+2) % 3;
            CP16(aDst[s],      aSrc + (kt+2)*16);
            CP16(aDst[s] + 16, aSrc + (kt+2)*16 + 4);
            CP16(waDst[s],     waSrc + (size_t)(kt+2)*16*(2*FFd));
            CP16(wbDst[s],     wbSrc + (size_t)(kt+2)*16*(2*FFd));
            CPCOMMIT();
        }
        int buf = kt % 3;
        #pragma unroll
        for (int ks = 0; ks < 2; ks++) {
            int kr = ks*8 + t4;
            uint32_t ba00 = __float_as_uint(Wsa[buf][kr  ][wn + g]);
            uint32_t ba01 = __float_as_uint(Wsa[buf][kr+4][wn + g]);
            uint32_t ba10 = __float_as_uint(Wsa[buf][kr  ][wn + 8 + g]);
            uint32_t ba11 = __float_as_uint(Wsa[buf][kr+4][wn + 8 + g]);
            uint32_t bb00 = __float_as_uint(Wsb[buf][kr  ][wn + g]);
            uint32_t bb01 = __float_as_uint(Wsb[buf][kr+4][wn + g]);
            uint32_t bb10 = __float_as_uint(Wsb[buf][kr  ][wn + 8 + g]);
            uint32_t bb11 = __float_as_uint(Wsb[buf][kr+4][wn + 8 + g]);
            #pragma unroll
            for (int mt = 0; mt < 4; mt++) {
                int mb = wm + mt*16;
                uint32_t a0 = __float_as_uint(As[buf][mb+g  ][kr  ]);
                uint32_t a1 = __float_as_uint(As[buf][mb+g+8][kr  ]);
                uint32_t a2 = __float_as_uint(As[buf][mb+g  ][kr+4]);
                uint32_t a3 = __float_as_uint(As[buf][mb+g+8][kr+4]);
                mma_tf32(acca[mt][0][0],acca[mt][0][1],acca[mt][0][2],acca[mt][0][3],
                         a0,a1,a2,a3, ba00,ba01);
                mma_tf32(acca[mt][1][0],acca[mt][1][1],acca[mt][1][2],acca[mt][1][3],
                         a0,a1,a2,a3, ba10,ba11);
                mma_tf32(accb[mt][0][0],accb[mt][0][1],accb[mt][0][2],accb[mt][0][3],
                         a0,a1,a2,a3, bb00,bb01);
                mma_tf32(accb[mt][1][0],accb[mt][1][1],accb[mt][1][2],accb[mt][1][3],
                         a0,a1,a2,a3, bb10,bb11);
            }
        }
    }

    #pragma unroll
    for (int mt = 0; mt < 4; mt++) {
        int r0 = bm + wm + mt*16 + g;
        #pragma unroll
        for (int nt = 0; nt < 2; nt++) {
            int col = bn + wn + nt*8 + 2*t4;
            float ba0 = bf1[col], ba1 = bf1[col+1];
            float bb0 = bf1[FFd + col], bb1 = bf1[FFd + col+1];
            float ua0 = acca[mt][nt][0] + ba0, ua1 = acca[mt][nt][1] + ba1;
            float ua2 = acca[mt][nt][2] + ba0, ua3 = acca[mt][nt][3] + ba1;
            float ub0 = accb[mt][nt][0] + bb0, ub1 = accb[mt][nt][1] + bb1;
            float ub2 = accb[mt][nt][2] + bb0, ub3 = accb[mt][nt][3] + bb1;
            float g0 = ua0 * (1.0f/(1.0f + __expf(-ub0)));
            float g1 = ua1 * (1.0f/(1.0f + __expf(-ub1)));
            float g2 = ua2 * (1.0f/(1.0f + __expf(-ub2)));
            float g3 = ua3 * (1.0f/(1.0f + __expf(-ub3)));
            *(float2*)&G[(size_t)r0*FFd + col]     = make_float2(g0, g1);
            *(float2*)&G[(size_t)(r0+8)*FFd + col] = make_float2(g2, g3);
        }
    }
}

// ============ attention v4: tf32 mma, NO online rescale =====================
// Scores are bounded (LN'd inputs): accumulate unnormalized exp(s); masked
// keys produce exp(-1e9) == 0. Row sums reduced once at the end.
#define KT_PITCH 520
#define V_PITCH  24
#define ATTN_SMEM ((16*KT_PITCH + 512*V_PITCH + 512 + 64)*4)

__global__ __launch_bounds__(512, 2)
void attn4_kernel(const float* __restrict__ QKV,
                  const unsigned char* __restrict__ bins,
                  const unsigned char* __restrict__ mask,
                  const float* __restrict__ dist_emb_l,   // [50,8]
                  const float* __restrict__ attn_bias_l,  // [8]
                  float* __restrict__ out) {
    int h = blockIdx.x, b = blockIdx.y;
    extern __shared__ uint32_t smu[];
    uint32_t* Kt = smu;                         // [16][KT_PITCH]
    uint32_t* Vs = Kt + 16*KT_PITCH;            // [512][V_PITCH]
    float* mb    = (float*)(Vs + 512*V_PITCH);  // [512] additive mask bias
    float* emb2  = mb + 512;                    // [50] emb + attn_bias

    int tid = threadIdx.x;
    {
        int k = tid;
        const float* kr = QKV + ((size_t)(b*Nd + k)*QKVLD + Hd + h*HDd);
        #pragma unroll
        for (int d = 0; d < 16; d++) Kt[d*KT_PITCH + k] = f2tf32(kr[d]);
        #pragma unroll
        for (int d = 0; d < 16; d++) Vs[k*V_PITCH + d] = f2tf32(kr[128 + d]);
        mb[k] = mask[(size_t)b*Nd + k] ? -1e9f : 0.0f;
    }
    if (tid < NUM_BINS) emb2[tid] = dist_emb_l[tid*NHd + h] + attn_bias_l[h];
    __syncthreads();

    int lane = tid & 31, w = tid >> 5;
    int g = lane >> 2, t4 = lane & 3;
    int qbase = blockIdx.z*256 + w*16;

    const float* qp = QKV + ((size_t)(b*Nd + qbase)*QKVLD + h*HDd);
    uint32_t qa[8];
    #pragma unroll
    for (int s = 0; s < 2; s++) {
        qa[s*4+0] = f2tf32(qp[(size_t)g    *QKVLD + s*8 + t4]);
        qa[s*4+1] = f2tf32(qp[(size_t)(g+8)*QKVLD + s*8 + t4]);
        qa[s*4+2] = f2tf32(qp[(size_t)g    *QKVLD + s*8 + t4+4]);
        qa[s*4+3] = f2tf32(qp[(size_t)(g+8)*QKVLD + s*8 + t4+4]);
    }

    const uchar2* br0 = (const uchar2*)(bins + ((size_t)(b*Nd + qbase+g  ))*Nd);
    const uchar2* br1 = (const uchar2*)(bins + ((size_t)(b*Nd + qbase+g+8))*Nd);

    float o0=0,o1=0,o2=0,o3=0,o4=0,o5=0,o6=0,o7=0;
    float l0=0.0f, l1=0.0f;

    uchar2 nb0 = br0[t4], nb1 = br1[t4];

    #pragma unroll 2
    for (int kc = 0; kc < Nd; kc += 8) {
        uchar2 bn0 = nb0, bn1 = nb1;
        if (kc + 8 < Nd) { nb0 = br0[(kc+8)/2 + t4]; nb1 = br1[(kc+8)/2 + t4]; }

        uint32_t kb0 = Kt[ t4      *KT_PITCH + kc + g];
        uint32_t kb1 = Kt[(t4+4 )  *KT_PITCH + kc + g];
        uint32_t kb2 = Kt[(t4+8 )  *KT_PITCH + kc + g];
        uint32_t kb3 = Kt[(t4+12)  *KT_PITCH + kc + g];

        float s0=0,s1=0,s2=0,s3=0;
        mma_tf32(s0,s1,s2,s3, qa[0],qa[1],qa[2],qa[3], kb0,kb1);
        mma_tf32(s0,s1,s2,s3, qa[4],qa[5],qa[6],qa[7], kb2,kb3);

        float mbl0 = mb[kc + 2*t4], mbl1 = mb[kc + 2*t4 + 1];
        float p0 = __expf(s0*0.25f + emb2[bn0.x] + mbl0);
        float p1 = __expf(s1*0.25f + emb2[bn0.y] + mbl1);
        float p2 = __expf(s2*0.25f + emb2[bn1.x] + mbl0);
        float p3 = __expf(s3*0.25f + emb2[bn1.y] + mbl1);
        l0 += p0 + p1;
        l1 += p2 + p3;

        // permute P (C-layout) -> A-frag layout
        int qsl0 = (lane & ~3) | (t4 >> 1);
        int qsl1 = qsl0 + 2;
        bool odd = (t4 & 1);
        float x0a = __shfl_sync(0xffffffffu, p0, qsl0);
        float x0b = __shfl_sync(0xffffffffu, p1, qsl0);
        float x2a = __shfl_sync(0xffffffffu, p0, qsl1);
        float x2b = __shfl_sync(0xffffffffu, p1, qsl1);
        float x1a = __shfl_sync(0xffffffffu, p2, qsl0);
        float x1b = __shfl_sync(0xffffffffu, p3, qsl0);
        float x3a = __shfl_sync(0xffffffffu, p2, qsl1);
        float x3b = __shfl_sync(0xffffffffu, p3, qsl1);
        uint32_t pa0 = __float_as_uint(odd ? x0b : x0a);
        uint32_t pa1 = __float_as_uint(odd ? x1b : x1a);
        uint32_t pa2 = __float_as_uint(odd ? x2b : x2a);
        uint32_t pa3 = __float_as_uint(odd ? x3b : x3a);

        uint32_t vb0 = Vs[(kc + t4    )*V_PITCH + g];
        uint32_t vb1 = Vs[(kc + t4 + 4)*V_PITCH + g];
        uint32_t vb2 = Vs[(kc + t4    )*V_PITCH + g + 8];
        uint32_t vb3 = Vs[(kc + t4 + 4)*V_PITCH + g + 8];

        mma_tf32(o0,o1,o2,o3, pa0,pa1,pa2,pa3, vb0,vb1);
        mma_tf32(o4,o5,o6,o7, pa0,pa1,pa2,pa3, vb2,vb3);
    }

    // reduce row sums across the quad (keys partitioned over t4)
    l0 += __shfl_xor_sync(0xffffffffu, l0, 1);
    l0 += __shfl_xor_sync(0xffffffffu, l0, 2);
    l1 += __shfl_xor_sync(0xffffffffu, l1, 1);
    l1 += __shfl_xor_sync(0xffffffffu, l1, 2);

    float i0 = 1.0f/l0, i1 = 1.0f/l1;
    float* orow0 = out + ((size_t)(b*Nd + qbase + g    ))*Hd + h*HDd + 2*t4;
    float* orow1 = out + ((size_t)(b*Nd + qbase + g + 8))*Hd + h*HDd + 2*t4;
    *(float2*)(orow0    ) = make_float2(o0*i0, o1*i0);
    *(float2*)(orow0 + 8) = make_float2(o4*i0, o5*i0);
    *(float2*)(orow1    ) = make_float2(o2*i1, o3*i1);
    *(float2*)(orow1 + 8) = make_float2(o6*i1, o7*i1);
}

extern "C" void kernel_launch(void* const* d_in, const int* in_sizes, int n_in,
                              void* d_out, int out_size) {
    const float* x    = (const float*)d_in[0];
    const float* dm   = (const float*)d_in[1];
    const void*  mraw = (const void*)d_in[2];
    const float* Wq = (const float*)d_in[3];
    const float* bq = (const float*)d_in[4];
    const float* Wk = (const float*)d_in[5];
    const float* bk = (const float*)d_in[6];
    const float* Wv = (const float*)d_in[7];
    const float* bv = (const float*)d_in[8];
    const float* Wo = (const float*)d_in[9];
    const float* bo = (const float*)d_in[10];
    const float* dist_emb  = (const float*)d_in[11];
    const float* attn_bias = (const float*)d_in[12];
    const float* g1 = (const float*)d_in[13];
    const float* b1 = (const float*)d_in[14];
    const float* g2 = (const float*)d_in[15];
    const float* b2 = (const float*)d_in[16];
    const float* Wf1 = (const float*)d_in[17];
    const float* bf1 = (const float*)d_in[18];
    const float* Wf2 = (const float*)d_in[19];
    const float* bf2 = (const float*)d_in[20];

    float *hn, *QKV, *AO, *G;
    unsigned char *msk, *bins;
    cudaGetSymbolAddress((void**)&hn,  g_hn);
    cudaGetSymbolAddress((void**)&QKV, g_qkv);
    cudaGetSymbolAddress((void**)&AO,  g_ao);
    cudaGetSymbolAddress((void**)&G,   g_gl);
    cudaGetSymbolAddress((void**)&msk, g_mask);
    cudaGetSymbolAddress((void**)&bins,g_bins);

    cudaFuncSetAttribute(attn4_kernel,
                         cudaFuncAttributeMaxDynamicSharedMemorySize, ATTN_SMEM);

    float* h = (float*)d_out;
    cudaMemcpyAsync(h, x, (size_t)Md*Hd*sizeof(float), cudaMemcpyDeviceToDevice);
    mask_expand_kernel<<<1,256>>>(mraw);
    bins_kernel<<<(Bd*Nd*Nd/4 + 255)/256, 256>>>((const float4*)dm,
                                                 (uchar4*)bins, Bd*Nd*Nd/4);

    for (int l = 0; l < Lr; l++) {
        // pre-LN attention block
        ln_kernel<<<Md/8,256>>>(h, g1 + l*Hd, b1 + l*Hd, hn);
        qkv_mma_kernel<<<dim3(Hd/64, Md/128, 3), 256>>>(hn,
                Wq + (size_t)l*Hd*Hd, Wk + (size_t)l*Hd*Hd, Wv + (size_t)l*Hd*Hd,
                bq + l*Hd, bk + l*Hd, bv + l*Hd, QKV);
        attn4_kernel<<<dim3(NHd, Bd, 2), 512, ATTN_SMEM>>>(QKV, bins, msk,
                                                dist_emb + (size_t)l*NUM_BINS*NHd,
                                                attn_bias + (size_t)l*NHd, AO);
        gemm_mma_kernel<<<dim3(Hd/64, Md/128), 256>>>(AO, Wo + (size_t)l*Hd*Hd,
                bo + l*Hd, h, h, Hd, Hd, Hd, 0);

        // pre-LN GLU FFN (fused GEMM+GLU)
        ln_kernel<<<Md/8,256>>>(h, g2 + l*Hd, b2 + l*Hd, hn);
        glu_mma_kernel<<<dim3(FFd/64, Md/128), 256>>>(hn,
                Wf1 + (size_t)l*Hd*2*FFd, bf1 + (size_t)l*2*FFd, G, Hd);
        gemm_mma_kernel<<<dim3(Hd/64, Md/128), 256>>>(G, Wf2 + (size_t)l*FFd*Hd,
                bf2 + l*Hd, h, h, Hd, FFd, Hd, 0);
    }
}

// round 14
// speedup vs baseline: 22.9799x; 1.1390x over previous
#include <cuda_runtime.h>
#include <cstdint>

#define Lr 3
#define Hd 128
#define NHd 8
#define HDd 16
#define FFd 512
#define Bd 32
#define Nd 512
#define NUM_BINS 50
#define Md (Bd*Nd)          // 16384 rows
#define QKVLD 384           // interleaved QKV row stride

// ---------------- scratch (device globals; no allocation allowed) ----------
__device__ float g_hn [(size_t)Md*Hd];
__device__ float g_qkv[(size_t)Md*QKVLD];
__device__ float g_ao [(size_t)Md*Hd];
__device__ float g_gl [(size_t)Md*FFd];
__device__ unsigned char g_mask[Md];
__device__ unsigned char g_bins[(size_t)Bd*Nd*Nd];   // 8.4 MB

// ---------------- helpers ----------------------------------------------------
__device__ __forceinline__ uint32_t f2tf32(float f) {
    uint32_t r; asm("cvt.rna.tf32.f32 %0, %1;" : "=r"(r) : "f"(f)); return r;
}
__device__ __forceinline__ void mma_tf32(float& d0, float& d1, float& d2, float& d3,
                                         uint32_t a0, uint32_t a1, uint32_t a2, uint32_t a3,
                                         uint32_t b0, uint32_t b1) {
    asm("mma.sync.aligned.m16n8k8.row.col.f32.tf32.tf32.f32 "
        "{%0,%1,%2,%3}, {%4,%5,%6,%7}, {%8,%9}, {%0,%1,%2,%3};"
        : "+f"(d0), "+f"(d1), "+f"(d2), "+f"(d3)
        : "r"(a0), "r"(a1), "r"(a2), "r"(a3), "r"(b0), "r"(b1));
}
__device__ __forceinline__ uint32_t smem_u32(const void* p) {
    uint32_t a;
    asm("{ .reg .u64 t; cvta.to.shared.u64 t, %1; cvt.u32.u64 %0, t; }"
        : "=r"(a) : "l"(p));
    return a;
}
#define CP16(dst,src)  asm volatile("cp.async.cg.shared.global [%0], [%1], 16;" :: "r"(dst), "l"(src))
#define CPCOMMIT()     asm volatile("cp.async.commit_group;")
#define CPWAIT1()      asm volatile("cp.async.wait_group 1;")
#define CPWAIT0()      asm volatile("cp.async.wait_group 0;")

// ---------------- mask dtype detection + expansion --------------------------
__global__ void mask_expand_kernel(const void* __restrict__ mraw) {
    __shared__ int s_notint, s_notfloat;
    if (threadIdx.x == 0) { s_notint = 0; s_notfloat = 0; }
    __syncthreads();
    const int* mi = (const int*)mraw;
    int notint = 0, notfloat = 0;
    for (int i = threadIdx.x; i < 4096; i += 256) {
        int v = mi[i];
        if (v != 0 && v != 1) notint = 1;
        if (v != 0 && v != 0x3F800000) notfloat = 1;
    }
    if (notint)   atomicOr(&s_notint, 1);
    if (notfloat) atomicOr(&s_notfloat, 1);
    __syncthreads();
    int isInt   = !s_notint;
    int isFloat = (!s_notfloat) && s_notint;
    for (int i = threadIdx.x; i < Md; i += 256) {
        unsigned char m;
        if (isInt)        m = (unsigned char)(mi[i] != 0);
        else if (isFloat) m = (unsigned char)(((const float*)mraw)[i] != 0.0f);
        else              m = (unsigned char)(((const unsigned char*)mraw)[i] != 0);
        g_mask[i] = m;
    }
}

// ---------------- bins: vectorized, once per call ---------------------------
__global__ void bins_kernel(const float4* __restrict__ dm,
                            uchar4* __restrict__ bins, int n4) {
    int i = blockIdx.x*blockDim.x + threadIdx.x;
    if (i >= n4) return;
    float4 v = dm[i];
    uchar4 o;
    int bx = (int)(v.x*10.0f); o.x = (unsigned char)min(max(bx,0), NUM_BINS-1);
    int by = (int)(v.y*10.0f); o.y = (unsigned char)min(max(by,0), NUM_BINS-1);
    int bz = (int)(v.z*10.0f); o.z = (unsigned char)min(max(bz,0), NUM_BINS-1);
    int bw = (int)(v.w*10.0f); o.w = (unsigned char)min(max(bw,0), NUM_BINS-1);
    bins[i] = o;
}

// ---------------- LayerNorm: warp per row, 8 rows/block ---------------------
__global__ __launch_bounds__(256)
void ln_kernel(const float* __restrict__ h,
               const float* __restrict__ gamma,
               const float* __restrict__ beta,
               float* __restrict__ out) {
    int row = blockIdx.x*8 + (threadIdx.x >> 5);
    int l = threadIdx.x & 31;
    float4 v = ((const float4*)(h + (size_t)row*Hd))[l];
    float s  = (v.x + v.y) + (v.z + v.w);
    float s2 = (v.x*v.x + v.y*v.y) + (v.z*v.z + v.w*v.w);
    #pragma unroll
    for (int o = 16; o; o >>= 1) {
        s  += __shfl_xor_sync(0xffffffffu, s,  o);
        s2 += __shfl_xor_sync(0xffffffffu, s2, o);
    }
    float mean = s * (1.0f/Hd);
    float var  = s2 * (1.0f/Hd) - mean*mean;
    float inv  = rsqrtf(var + 1e-5f);
    float4 g = ((const float4*)gamma)[l];
    float4 bb = ((const float4*)beta)[l];
    float4 o4;
    o4.x = (v.x - mean)*inv*g.x + bb.x;
    o4.y = (v.y - mean)*inv*g.y + bb.y;
    o4.z = (v.z - mean)*inv*g.z + bb.z;
    o4.w = (v.w - mean)*inv*g.w + bb.w;
    ((float4*)(out + (size_t)row*Hd))[l] = o4;
}

// ======== tf32 MMA GEMM, cp.async 3-stage: 128x64 tile, 8 warps =============
#define ATP2 20
#define WTP2 72

__device__ __forceinline__
void gemm_mma_body(const float* __restrict__ A, const float* __restrict__ W,
                   const float* __restrict__ bias, const float* __restrict__ resid,
                   float* __restrict__ C, int N, int K, int ldc, int coff,
                   int bm, int bn) {
    __shared__ __align__(16) float As[3][128][ATP2];
    __shared__ __align__(16) float Ws[3][16][WTP2];
    int tid = threadIdx.x, lane = tid & 31, wid = tid >> 5;
    int g = lane >> 2, t4 = lane & 3;
    int wm = (wid & 1) * 64, wn = (wid >> 1) * 16;

    int arow = tid >> 1, ahalf = tid & 1;
    int wrow = tid >> 4, wc = tid & 15;
    const float* aSrc = A + (size_t)(bm + arow)*K + ahalf*8;
    const float* wSrc = W + (size_t)wrow*N + bn + wc*4;

    uint32_t aDst[3], wDst[3];
    #pragma unroll
    for (int s = 0; s < 3; s++) {
        aDst[s] = smem_u32(&As[s][arow][ahalf*8]);
        wDst[s] = smem_u32(&Ws[s][wrow][wc*4]);
    }

    int nkt = K >> 4;
    #pragma unroll
    for (int pf = 0; pf < 2; pf++) {
        CP16(aDst[pf],      aSrc + pf*16);
        CP16(aDst[pf] + 16, aSrc + pf*16 + 4);
        CP16(wDst[pf],      wSrc + (size_t)pf*16*N);
        CPCOMMIT();
    }

    float acc[4][2][4] = {};
    for (int kt = 0; kt < nkt; kt++) {
        if (kt == nkt-1) { CPWAIT0(); } else { CPWAIT1(); }
        __syncthreads();
        if (kt + 2 < nkt) {
            int s = (kt+2) % 3;
            CP16(aDst[s],      aSrc + (kt+2)*16);
            CP16(aDst[s] + 16, aSrc + (kt+2)*16 + 4);
            CP16(wDst[s],      wSrc + (size_t)(kt+2)*16*N);
            CPCOMMIT();
        }
        int buf = kt % 3;
        #pragma unroll
        for (int ks = 0; ks < 2; ks++) {
            int kr = ks*8 + t4;
            uint32_t b00 = __float_as_uint(Ws[buf][kr  ][wn + g]);
            uint32_t b01 = __float_as_uint(Ws[buf][kr+4][wn + g]);
            uint32_t b10 = __float_as_uint(Ws[buf][kr  ][wn + 8 + g]);
            uint32_t b11 = __float_as_uint(Ws[buf][kr+4][wn + 8 + g]);
            #pragma unroll
            for (int mt = 0; mt < 4; mt++) {
                int mb = wm + mt*16;
                uint32_t a0 = __float_as_uint(As[buf][mb+g  ][kr  ]);
                uint32_t a1 = __float_as_uint(As[buf][mb+g+8][kr  ]);
                uint32_t a2 = __float_as_uint(As[buf][mb+g  ][kr+4]);
                uint32_t a3 = __float_as_uint(As[buf][mb+g+8][kr+4]);
                mma_tf32(acc[mt][0][0],acc[mt][0][1],acc[mt][0][2],acc[mt][0][3],
                         a0,a1,a2,a3, b00,b01);
                mma_tf32(acc[mt][1][0],acc[mt][1][1],acc[mt][1][2],acc[mt][1][3],
                         a0,a1,a2,a3, b10,b11);
            }
        }
    }

    #pragma unroll
    for (int mt = 0; mt < 4; mt++) {
        int r0 = bm + wm + mt*16 + g;
        #pragma unroll
        for (int nt = 0; nt < 2; nt++) {
            int col = bn + wn + nt*8 + 2*t4;
            float b0 = bias[col], b1 = bias[col+1];
            float v0 = acc[mt][nt][0] + b0, v1 = acc[mt][nt][1] + b1;
            float v2 = acc[mt][nt][2] + b0, v3 = acc[mt][nt][3] + b1;
            if (resid) {
                float2 r0v = *(const float2*)&resid[(size_t)r0*ldc + coff + col];
                float2 r1v = *(const float2*)&resid[(size_t)(r0+8)*ldc + coff + col];
                v0 += r0v.x; v1 += r0v.y; v2 += r1v.x; v3 += r1v.y;
            }
            *(float2*)&C[(size_t)r0*ldc + coff + col]     = make_float2(v0, v1);
            *(float2*)&C[(size_t)(r0+8)*ldc + coff + col] = make_float2(v2, v3);
        }
    }
}

__global__ __launch_bounds__(256, 3)
void gemm_mma_kernel(const float* __restrict__ A, const float* __restrict__ W,
                     const float* __restrict__ bias, const float* __restrict__ resid,
                     float* __restrict__ C, int N, int K, int ldc, int coff) {
    gemm_mma_body(A, W, bias, resid, C, N, K, ldc, coff,
                  blockIdx.y*128, blockIdx.x*64);
}

__global__ __launch_bounds__(256, 3)
void qkv_mma_kernel(const float* __restrict__ A,
                    const float* __restrict__ Wq, const float* __restrict__ Wk,
                    const float* __restrict__ Wv,
                    const float* __restrict__ bq, const float* __restrict__ bk,
                    const float* __restrict__ bv,
                    float* __restrict__ QKV) {
    int z = blockIdx.z;
    const float* W    = (z == 0) ? Wq : (z == 1 ? Wk : Wv);
    const float* bias = (z == 0) ? bq : (z == 1 ? bk : bv);
    gemm_mma_body(A, W, bias, nullptr, QKV, Hd, Hd, QKVLD, z*Hd,
                  blockIdx.y*128, blockIdx.x*64);
}

// ---- tf32 MMA GEMM + GLU, cp.async 3-stage ---------------------------------
__global__ __launch_bounds__(256, 2)
void glu_mma_kernel(const float* __restrict__ A,
                    const float* __restrict__ Wf1,
                    const float* __restrict__ bf1,
                    float* __restrict__ G, int K) {
    __shared__ __align__(16) float As [3][128][ATP2];
    __shared__ __align__(16) float Wsa[3][16][WTP2];
    __shared__ __align__(16) float Wsb[3][16][WTP2];
    int tid = threadIdx.x, lane = tid & 31, wid = tid >> 5;
    int g = lane >> 2, t4 = lane & 3;
    int wm = (wid & 1) * 64, wn = (wid >> 1) * 16;
    int bm = blockIdx.y*128, bn = blockIdx.x*64;

    int arow = tid >> 1, ahalf = tid & 1;
    int wrow = tid >> 4, wc = tid & 15;
    const float* aSrc  = A + (size_t)(bm + arow)*K + ahalf*8;
    const float* waSrc = Wf1 + (size_t)wrow*(2*FFd) + bn + wc*4;
    const float* wbSrc = waSrc + FFd;

    uint32_t aDst[3], waDst[3], wbDst[3];
    #pragma unroll
    for (int s = 0; s < 3; s++) {
        aDst[s]  = smem_u32(&As [s][arow][ahalf*8]);
        waDst[s] = smem_u32(&Wsa[s][wrow][wc*4]);
        wbDst[s] = smem_u32(&Wsb[s][wrow][wc*4]);
    }

    int nkt = K >> 4;
    #pragma unroll
    for (int pf = 0; pf < 2; pf++) {
        CP16(aDst[pf],      aSrc + pf*16);
        CP16(aDst[pf] + 16, aSrc + pf*16 + 4);
        CP16(waDst[pf],     waSrc + (size_t)pf*16*(2*FFd));
        CP16(wbDst[pf],     wbSrc + (size_t)pf*16*(2*FFd));
        CPCOMMIT();
    }

    float acca[4][2][4] = {};
    float accb[4][2][4] = {};
    for (int kt = 0; kt < nkt; kt++) {
        if (kt == nkt-1) { CPWAIT0(); } else { CPWAIT1(); }
        __syncthreads();
        if (kt + 2 < nkt) {
            int s = (kt+2) % 3;
            CP16(aDst[s],      aSrc + (kt+2)*16);
            CP16(aDst[s] + 16, aSrc + (kt+2)*16 + 4);
            CP16(waDst[s],     waSrc + (size_t)(kt+2)*16*(2*FFd));
            CP16(wbDst[s],     wbSrc + (size_t)(kt+2)*16*(2*FFd));
            CPCOMMIT();
        }
        int buf = kt % 3;
        #pragma unroll
        for (int ks = 0; ks < 2; ks++) {
            int kr = ks*8 + t4;
            uint32_t ba00 = __float_as_uint(Wsa[buf][kr  ][wn + g]);
            uint32_t ba01 = __float_as_uint(Wsa[buf][kr+4][wn + g]);
            uint32_t ba10 = __float_as_uint(Wsa[buf][kr  ][wn + 8 + g]);
            uint32_t ba11 = __float_as_uint(Wsa[buf][kr+4][wn + 8 + g]);
            uint32_t bb00 = __float_as_uint(Wsb[buf][kr  ][wn + g]);
            uint32_t bb01 = __float_as_uint(Wsb[buf][kr+4][wn + g]);
            uint32_t bb10 = __float_as_uint(Wsb[buf][kr  ][wn + 8 + g]);
            uint32_t bb11 = __float_as_uint(Wsb[buf][kr+4][wn + 8 + g]);
            #pragma unroll
            for (int mt = 0; mt < 4; mt++) {
                int mb = wm + mt*16;
                uint32_t a0 = __float_as_uint(As[buf][mb+g  ][kr  ]);
                uint32_t a1 = __float_as_uint(As[buf][mb+g+8][kr  ]);
                uint32_t a2 = __float_as_uint(As[buf][mb+g  ][kr+4]);
                uint32_t a3 = __float_as_uint(As[buf][mb+g+8][kr+4]);
                mma_tf32(acca[mt][0][0],acca[mt][0][1],acca[mt][0][2],acca[mt][0][3],
                         a0,a1,a2,a3, ba00,ba01);
                mma_tf32(acca[mt][1][0],acca[mt][1][1],acca[mt][1][2],acca[mt][1][3],
                         a0,a1,a2,a3, ba10,ba11);
                mma_tf32(accb[mt][0][0],accb[mt][0][1],accb[mt][0][2],accb[mt][0][3],
                         a0,a1,a2,a3, bb00,bb01);
                mma_tf32(accb[mt][1][0],accb[mt][1][1],accb[mt][1][2],accb[mt][1][3],
                         a0,a1,a2,a3, bb10,bb11);
            }
        }
    }

    #pragma unroll
    for (int mt = 0; mt < 4; mt++) {
        int r0 = bm + wm + mt*16 + g;
        #pragma unroll
        for (int nt = 0; nt < 2; nt++) {
            int col = bn + wn + nt*8 + 2*t4;
            float ba0 = bf1[col], ba1 = bf1[col+1];
            float bb0 = bf1[FFd + col], bb1 = bf1[FFd + col+1];
            float ua0 = acca[mt][nt][0] + ba0, ua1 = acca[mt][nt][1] + ba1;
            float ua2 = acca[mt][nt][2] + ba0, ua3 = acca[mt][nt][3] + ba1;
            float ub0 = accb[mt][nt][0] + bb0, ub1 = accb[mt][nt][1] + bb1;
            float ub2 = accb[mt][nt][2] + bb0, ub3 = accb[mt][nt][3] + bb1;
            float g0 = ua0 * (1.0f/(1.0f + __expf(-ub0)));
            float g1 = ua1 * (1.0f/(1.0f + __expf(-ub1)));
            float g2 = ua2 * (1.0f/(1.0f + __expf(-ub2)));
            float g3 = ua3 * (1.0f/(1.0f + __expf(-ub3)));
            *(float2*)&G[(size_t)r0*FFd + col]     = make_float2(g0, g1);
            *(float2*)&G[(size_t)(r0+8)*FFd + col] = make_float2(g2, g3);
        }
    }
}

// ============ attention v5: tf32 mma, coalesced staging, no online rescale ==
#define KT_PITCH 520
#define V_PITCH  24
#define ATTN_SMEM ((16*KT_PITCH + 512*V_PITCH + 512 + 64)*4)

__global__ __launch_bounds__(512, 2)
void attn5_kernel(const float* __restrict__ QKV,
                  const unsigned char* __restrict__ bins,
                  const unsigned char* __restrict__ mask,
                  const float* __restrict__ dist_emb_l,   // [50,8]
                  const float* __restrict__ attn_bias_l,  // [8]
                  float* __restrict__ out) {
    int h = blockIdx.x, b = blockIdx.y;
    extern __shared__ uint32_t smu[];
    uint32_t* Kt = smu;                         // [16][KT_PITCH]
    uint32_t* Vs = Kt + 16*KT_PITCH;            // [512][V_PITCH]
    float* mb    = (float*)(Vs + 512*V_PITCH);  // [512] additive mask bias
    float* emb2  = mb + 512;                    // [50] emb + attn_bias

    int tid = threadIdx.x;
    {   // coalesced K/V staging: 4 threads per row, float4 loads
        int r = tid >> 2, f4 = tid & 3;
        int d = f4*4;
        #pragma unroll
        for (int pass = 0; pass < 4; pass++) {
            int k = pass*128 + r;
            const float4* base = (const float4*)(QKV + ((size_t)(b*Nd + k)*QKVLD + Hd + h*HDd));
            float4 kv = base[f4];
            float4 vv = base[32 + f4];           // +128 floats
            Kt[(d+0)*KT_PITCH + k] = f2tf32(kv.x);
            Kt[(d+1)*KT_PITCH + k] = f2tf32(kv.y);
            Kt[(d+2)*KT_PITCH + k] = f2tf32(kv.z);
            Kt[(d+3)*KT_PITCH + k] = f2tf32(kv.w);
            *(uint4*)&Vs[k*V_PITCH + d] =
                make_uint4(f2tf32(vv.x), f2tf32(vv.y), f2tf32(vv.z), f2tf32(vv.w));
        }
        mb[tid] = mask[(size_t)b*Nd + tid] ? -1e9f : 0.0f;
    }
    if (tid < NUM_BINS) emb2[tid] = dist_emb_l[tid*NHd + h] + attn_bias_l[h];
    __syncthreads();

    int lane = tid & 31, w = tid >> 5;
    int g = lane >> 2, t4 = lane & 3;
    int qbase = blockIdx.z*256 + w*16;

    const float* qp = QKV + ((size_t)(b*Nd + qbase)*QKVLD + h*HDd);
    uint32_t qa[8];
    #pragma unroll
    for (int s = 0; s < 2; s++) {
        qa[s*4+0] = f2tf32(qp[(size_t)g    *QKVLD + s*8 + t4]);
        qa[s*4+1] = f2tf32(qp[(size_t)(g+8)*QKVLD + s*8 + t4]);
        qa[s*4+2] = f2tf32(qp[(size_t)g    *QKVLD + s*8 + t4+4]);
        qa[s*4+3] = f2tf32(qp[(size_t)(g+8)*QKVLD + s*8 + t4+4]);
    }

    const uchar2* br0 = (const uchar2*)(bins + ((size_t)(b*Nd + qbase+g  ))*Nd);
    const uchar2* br1 = (const uchar2*)(bins + ((size_t)(b*Nd + qbase+g+8))*Nd);

    float o0=0,o1=0,o2=0,o3=0,o4=0,o5=0,o6=0,o7=0;
    float l0=0.0f, l1=0.0f;

    uchar2 nb0 = br0[t4], nb1 = br1[t4];

    #pragma unroll 2
    for (int kc = 0; kc < Nd; kc += 8) {
        uchar2 bn0 = nb0, bn1 = nb1;
        if (kc + 8 < Nd) { nb0 = br0[(kc+8)/2 + t4]; nb1 = br1[(kc+8)/2 + t4]; }

        uint32_t kb0 = Kt[ t4      *KT_PITCH + kc + g];
        uint32_t kb1 = Kt[(t4+4 )  *KT_PITCH + kc + g];
        uint32_t kb2 = Kt[(t4+8 )  *KT_PITCH + kc + g];
        uint32_t kb3 = Kt[(t4+12)  *KT_PITCH + kc + g];

        float s0=0,s1=0,s2=0,s3=0;
        mma_tf32(s0,s1,s2,s3, qa[0],qa[1],qa[2],qa[3], kb0,kb1);
        mma_tf32(s0,s1,s2,s3, qa[4],qa[5],qa[6],qa[7], kb2,kb3);

        float mbl0 = mb[kc + 2*t4], mbl1 = mb[kc + 2*t4 + 1];
        float p0 = __expf(s0*0.25f + emb2[bn0.x] + mbl0);
        float p1 = __expf(s1*0.25f + emb2[bn0.y] + mbl1);
        float p2 = __expf(s2*0.25f + emb2[bn1.x] + mbl0);
        float p3 = __expf(s3*0.25f + emb2[bn1.y] + mbl1);
        l0 += p0 + p1;
        l1 += p2 + p3;

        int qsl0 = (lane & ~3) | (t4 >> 1);
        int qsl1 = qsl0 + 2;
        bool odd = (t4 & 1);
        float x0a = __shfl_sync(0xffffffffu, p0, qsl0);
        float x0b = __shfl_sync(0xffffffffu, p1, qsl0);
        float x2a = __shfl_sync(0xffffffffu, p0, qsl1);
        float x2b = __shfl_sync(0xffffffffu, p1, qsl1);
        float x1a = __shfl_sync(0xffffffffu, p2, qsl0);
        float x1b = __shfl_sync(0xffffffffu, p3, qsl0);
        float x3a = __shfl_sync(0xffffffffu, p2, qsl1);
        float x3b = __shfl_sync(0xffffffffu, p3, qsl1);
        uint32_t pa0 = __float_as_uint(odd ? x0b : x0a);
        uint32_t pa1 = __float_as_uint(odd ? x1b : x1a);
        uint32_t pa2 = __float_as_uint(odd ? x2b : x2a);
        uint32_t pa3 = __float_as_uint(odd ? x3b : x3a);

        uint32_t vb0 = Vs[(kc + t4    )*V_PITCH + g];
        uint32_t vb1 = Vs[(kc + t4 + 4)*V_PITCH + g];
        uint32_t vb2 = Vs[(kc + t4    )*V_PITCH + g + 8];
        uint32_t vb3 = Vs[(kc + t4 + 4)*V_PITCH + g + 8];

        mma_tf32(o0,o1,o2,o3, pa0,pa1,pa2,pa3, vb0,vb1);
        mma_tf32(o4,o5,o6,o7, pa0,pa1,pa2,pa3, vb2,vb3);
    }

    l0 += __shfl_xor_sync(0xffffffffu, l0, 1);
    l0 += __shfl_xor_sync(0xffffffffu, l0, 2);
    l1 += __shfl_xor_sync(0xffffffffu, l1, 1);
    l1 += __shfl_xor_sync(0xffffffffu, l1, 2);

    float i0 = 1.0f/l0, i1 = 1.0f/l1;
    float* orow0 = out + ((size_t)(b*Nd + qbase + g    ))*Hd + h*HDd + 2*t4;
    float* orow1 = out + ((size_t)(b*Nd + qbase + g + 8))*Hd + h*HDd + 2*t4;
    *(float2*)(orow0    ) = make_float2(o0*i0, o1*i0);
    *(float2*)(orow0 + 8) = make_float2(o4*i0, o5*i0);
    *(float2*)(orow1    ) = make_float2(o2*i1, o3*i1);
    *(float2*)(orow1 + 8) = make_float2(o6*i1, o7*i1);
}

extern "C" void kernel_launch(void* const* d_in, const int* in_sizes, int n_in,
                              void* d_out, int out_size) {
    const float* x    = (const float*)d_in[0];
    const float* dm   = (const float*)d_in[1];
    const void*  mraw = (const void*)d_in[2];
    const float* Wq = (const float*)d_in[3];
    const float* bq = (const float*)d_in[4];
    const float* Wk = (const float*)d_in[5];
    const float* bk = (const float*)d_in[6];
    const float* Wv = (const float*)d_in[7];
    const float* bv = (const float*)d_in[8];
    const float* Wo = (const float*)d_in[9];
    const float* bo = (const float*)d_in[10];
    const float* dist_emb  = (const float*)d_in[11];
    const float* attn_bias = (const float*)d_in[12];
    const float* g1 = (const float*)d_in[13];
    const float* b1 = (const float*)d_in[14];
    const float* g2 = (const float*)d_in[15];
    const float* b2 = (const float*)d_in[16];
    const float* Wf1 = (const float*)d_in[17];
    const float* bf1 = (const float*)d_in[18];
    const float* Wf2 = (const float*)d_in[19];
    const float* bf2 = (const float*)d_in[20];

    float *hn, *QKV, *AO, *G;
    unsigned char *msk, *bins;
    cudaGetSymbolAddress((void**)&hn,  g_hn);
    cudaGetSymbolAddress((void**)&QKV, g_qkv);
    cudaGetSymbolAddress((void**)&AO,  g_ao);
    cudaGetSymbolAddress((void**)&G,   g_gl);
    cudaGetSymbolAddress((void**)&msk, g_mask);
    cudaGetSymbolAddress((void**)&bins,g_bins);

    cudaFuncSetAttribute(attn5_kernel,
                         cudaFuncAttributeMaxDynamicSharedMemorySize, ATTN_SMEM);

    float* h = (float*)d_out;
    cudaMemcpyAsync(h, x, (size_t)Md*Hd*sizeof(float), cudaMemcpyDeviceToDevice);
    mask_expand_kernel<<<1,256>>>(mraw);
    bins_kernel<<<(Bd*Nd*Nd/4 + 255)/256, 256>>>((const float4*)dm,
                                                 (uchar4*)bins, Bd*Nd*Nd/4);

    for (int l = 0; l < Lr; l++) {
        // pre-LN attention block
        ln_kernel<<<Md/8,256>>>(h, g1 + l*Hd, b1 + l*Hd, hn);
        qkv_mma_kernel<<<dim3(Hd/64, Md/128, 3), 256>>>(hn,
                Wq + (size_t)l*Hd*Hd, Wk + (size_t)l*Hd*Hd, Wv + (size_t)l*Hd*Hd,
                bq + l*Hd, bk + l*Hd, bv + l*Hd, QKV);
        attn5_kernel<<<dim3(NHd, Bd, 2), 512, ATTN_SMEM>>>(QKV, bins, msk,
                                                dist_emb + (size_t)l*NUM_BINS*NHd,
                                                attn_bias + (size_t)l*NHd, AO);
        gemm_mma_kernel<<<dim3(Hd/64, Md/128), 256>>>(AO, Wo + (size_t)l*Hd*Hd,
                bo + l*Hd, h, h, Hd, Hd, Hd, 0);

        // pre-LN GLU FFN (fused GEMM+GLU)
        ln_kernel<<<Md/8,256>>>(h, g2 + l*Hd, b2 + l*Hd, hn);
        glu_mma_kernel<<<dim3(FFd/64, Md/128), 256>>>(hn,
                Wf1 + (size_t)l*Hd*2*FFd, bf1 + (size_t)l*2*FFd, G, Hd);
        gemm_mma_kernel<<<dim3(Hd/64, Md/128), 256>>>(G, Wf2 + (size_t)l*FFd*Hd,
                bf2 + l*Hd, h, h, Hd, FFd, Hd, 0);
    }
}

// round 15
// speedup vs baseline: 23.9247x; 1.0411x over previous
#include <cuda_runtime.h>
#include <cstdint>

#define Lr 3
#define Hd 128
#define NHd 8
#define HDd 16
#define FFd 512
#define Bd 32
#define Nd 512
#define NUM_BINS 50
#define Md (Bd*Nd)          // 16384 rows
#define QKVLD 384           // interleaved QKV row stride

// ---------------- scratch (device globals; no allocation allowed) ----------
__device__ float g_hn [(size_t)Md*Hd];
__device__ float g_qkv[(size_t)Md*QKVLD];
__device__ float g_ao [(size_t)Md*Hd];
__device__ float g_gl [(size_t)Md*FFd];
__device__ unsigned char g_mask[Md];
__device__ unsigned char g_bins[(size_t)Bd*Nd*Nd];   // 8.4 MB

// ---------------- helpers ----------------------------------------------------
__device__ __forceinline__ uint32_t f2tf32(float f) {
    uint32_t r; asm("cvt.rna.tf32.f32 %0, %1;" : "=r"(r) : "f"(f)); return r;
}
__device__ __forceinline__ void mma_tf32(float& d0, float& d1, float& d2, float& d3,
                                         uint32_t a0, uint32_t a1, uint32_t a2, uint32_t a3,
                                         uint32_t b0, uint32_t b1) {
    asm("mma.sync.aligned.m16n8k8.row.col.f32.tf32.tf32.f32 "
        "{%0,%1,%2,%3}, {%4,%5,%6,%7}, {%8,%9}, {%0,%1,%2,%3};"
        : "+f"(d0), "+f"(d1), "+f"(d2), "+f"(d3)
        : "r"(a0), "r"(a1), "r"(a2), "r"(a3), "r"(b0), "r"(b1));
}
__device__ __forceinline__ uint32_t smem_u32(const void* p) {
    uint32_t a;
    asm("{ .reg .u64 t; cvta.to.shared.u64 t, %1; cvt.u32.u64 %0, t; }"
        : "=r"(a) : "l"(p));
    return a;
}
#define CP16(dst,src)  asm volatile("cp.async.cg.shared.global [%0], [%1], 16;" :: "r"(dst), "l"(src))
#define CPCOMMIT()     asm volatile("cp.async.commit_group;")
#define CPWAIT1()      asm volatile("cp.async.wait_group 1;")
#define CPWAIT0()      asm volatile("cp.async.wait_group 0;")

// ---------------- mask dtype detection + expansion --------------------------
__global__ void mask_expand_kernel(const void* __restrict__ mraw) {
    __shared__ int s_notint, s_notfloat;
    if (threadIdx.x == 0) { s_notint = 0; s_notfloat = 0; }
    __syncthreads();
    const int* mi = (const int*)mraw;
    int notint = 0, notfloat = 0;
    for (int i = threadIdx.x; i < 4096; i += 256) {
        int v = mi[i];
        if (v != 0 && v != 1) notint = 1;
        if (v != 0 && v != 0x3F800000) notfloat = 1;
    }
    if (notint)   atomicOr(&s_notint, 1);
    if (notfloat) atomicOr(&s_notfloat, 1);
    __syncthreads();
    int isInt   = !s_notint;
    int isFloat = (!s_notfloat) && s_notint;
    for (int i = threadIdx.x; i < Md; i += 256) {
        unsigned char m;
        if (isInt)        m = (unsigned char)(mi[i] != 0);
        else if (isFloat) m = (unsigned char)(((const float*)mraw)[i] != 0.0f);
        else              m = (unsigned char)(((const unsigned char*)mraw)[i] != 0);
        g_mask[i] = m;
    }
}

// ---------------- bins: vectorized, once per call ---------------------------
__global__ void bins_kernel(const float4* __restrict__ dm,
                            uchar4* __restrict__ bins, int n4) {
    int i = blockIdx.x*blockDim.x + threadIdx.x;
    if (i >= n4) return;
    float4 v = dm[i];
    uchar4 o;
    int bx = (int)(v.x*10.0f); o.x = (unsigned char)min(max(bx,0), NUM_BINS-1);
    int by = (int)(v.y*10.0f); o.y = (unsigned char)min(max(by,0), NUM_BINS-1);
    int bz = (int)(v.z*10.0f); o.z = (unsigned char)min(max(bz,0), NUM_BINS-1);
    int bw = (int)(v.w*10.0f); o.w = (unsigned char)min(max(bw,0), NUM_BINS-1);
    bins[i] = o;
}

// ---------------- LayerNorm: warp per row, 8 rows/block ---------------------
__global__ __launch_bounds__(256)
void ln_kernel(const float* __restrict__ h,
               const float* __restrict__ gamma,
               const float* __restrict__ beta,
               float* __restrict__ out) {
    int row = blockIdx.x*8 + (threadIdx.x >> 5);
    int l = threadIdx.x & 31;
    float4 v = ((const float4*)(h + (size_t)row*Hd))[l];
    float s  = (v.x + v.y) + (v.z + v.w);
    float s2 = (v.x*v.x + v.y*v.y) + (v.z*v.z + v.w*v.w);
    #pragma unroll
    for (int o = 16; o; o >>= 1) {
        s  += __shfl_xor_sync(0xffffffffu, s,  o);
        s2 += __shfl_xor_sync(0xffffffffu, s2, o);
    }
    float mean = s * (1.0f/Hd);
    float var  = s2 * (1.0f/Hd) - mean*mean;
    float inv  = rsqrtf(var + 1e-5f);
    float4 g = ((const float4*)gamma)[l];
    float4 bb = ((const float4*)beta)[l];
    float4 o4;
    o4.x = (v.x - mean)*inv*g.x + bb.x;
    o4.y = (v.y - mean)*inv*g.y + bb.y;
    o4.z = (v.z - mean)*inv*g.z + bb.z;
    o4.w = (v.w - mean)*inv*g.w + bb.w;
    ((float4*)(out + (size_t)row*Hd))[l] = o4;
}

// ======== tf32 MMA GEMM v2: 128x128 tile, 8 warps (warp = 64M x 32N) ========
// As[m][k] pitch 20 (frag banks 20g+t4), Ws[k][n] pitch 136 (banks 8t4+g).
#define ATP2 20
#define WTP3 136

__device__ __forceinline__
void gemm_mma_body2(const float* __restrict__ A, const float* __restrict__ W,
                    const float* __restrict__ bias, const float* __restrict__ resid,
                    float* __restrict__ C, int N, int K, int ldc, int coff,
                    int bm, int bn) {
    __shared__ __align__(16) float As[3][128][ATP2];
    __shared__ __align__(16) float Ws[3][16][WTP3];
    int tid = threadIdx.x, lane = tid & 31, wid = tid >> 5;
    int g = lane >> 2, t4 = lane & 3;
    int wm = (wid & 1) * 64, wn = (wid >> 1) * 32;

    int arow = tid >> 1, ahalf = tid & 1;
    int wrow = tid >> 4, wc = tid & 15;          // each thread: 8 W floats
    const float* aSrc = A + (size_t)(bm + arow)*K + ahalf*8;
    const float* wSrc = W + (size_t)wrow*N + bn + wc*8;

    uint32_t aDst[3], wDst[3];
    #pragma unroll
    for (int s = 0; s < 3; s++) {
        aDst[s] = smem_u32(&As[s][arow][ahalf*8]);
        wDst[s] = smem_u32(&Ws[s][wrow][wc*8]);
    }

    int nkt = K >> 4;
    #pragma unroll
    for (int pf = 0; pf < 2; pf++) {
        CP16(aDst[pf],      aSrc + pf*16);
        CP16(aDst[pf] + 16, aSrc + pf*16 + 4);
        CP16(wDst[pf],      wSrc + (size_t)pf*16*N);
        CP16(wDst[pf] + 16, wSrc + (size_t)pf*16*N + 4);
        CPCOMMIT();
    }

    float acc[4][4][4] = {};
    for (int kt = 0; kt < nkt; kt++) {
        if (kt == nkt-1) { CPWAIT0(); } else { CPWAIT1(); }
        __syncthreads();
        if (kt + 2 < nkt) {
            int s = (kt+2) % 3;
            CP16(aDst[s],      aSrc + (kt+2)*16);
            CP16(aDst[s] + 16, aSrc + (kt+2)*16 + 4);
            CP16(wDst[s],      wSrc + (size_t)(kt+2)*16*N);
            CP16(wDst[s] + 16, wSrc + (size_t)(kt+2)*16*N + 4);
            CPCOMMIT();
        }
        int buf = kt % 3;
        #pragma unroll
        for (int ks = 0; ks < 2; ks++) {
            int kr = ks*8 + t4;
            uint32_t bf[4][2];
            #pragma unroll
            for (int nt = 0; nt < 4; nt++) {
                bf[nt][0] = __float_as_uint(Ws[buf][kr  ][wn + nt*8 + g]);
                bf[nt][1] = __float_as_uint(Ws[buf][kr+4][wn + nt*8 + g]);
            }
            #pragma unroll
            for (int mt = 0; mt < 4; mt++) {
                int mb = wm + mt*16;
                uint32_t a0 = __float_as_uint(As[buf][mb+g  ][kr  ]);
                uint32_t a1 = __float_as_uint(As[buf][mb+g+8][kr  ]);
                uint32_t a2 = __float_as_uint(As[buf][mb+g  ][kr+4]);
                uint32_t a3 = __float_as_uint(As[buf][mb+g+8][kr+4]);
                #pragma unroll
                for (int nt = 0; nt < 4; nt++)
                    mma_tf32(acc[mt][nt][0],acc[mt][nt][1],acc[mt][nt][2],acc[mt][nt][3],
                             a0,a1,a2,a3, bf[nt][0],bf[nt][1]);
            }
        }
    }

    #pragma unroll
    for (int mt = 0; mt < 4; mt++) {
        int r0 = bm + wm + mt*16 + g;
        #pragma unroll
        for (int nt = 0; nt < 4; nt++) {
            int col = bn + wn + nt*8 + 2*t4;
            float b0 = bias[col], b1 = bias[col+1];
            float v0 = acc[mt][nt][0] + b0, v1 = acc[mt][nt][1] + b1;
            float v2 = acc[mt][nt][2] + b0, v3 = acc[mt][nt][3] + b1;
            if (resid) {
                float2 r0v = *(const float2*)&resid[(size_t)r0*ldc + coff + col];
                float2 r1v = *(const float2*)&resid[(size_t)(r0+8)*ldc + coff + col];
                v0 += r0v.x; v1 += r0v.y; v2 += r1v.x; v3 += r1v.y;
            }
            *(float2*)&C[(size_t)r0*ldc + coff + col]     = make_float2(v0, v1);
            *(float2*)&C[(size_t)(r0+8)*ldc + coff + col] = make_float2(v2, v3);
        }
    }
}

__global__ __launch_bounds__(256, 2)
void gemm_mma_kernel(const float* __restrict__ A, const float* __restrict__ W,
                     const float* __restrict__ bias, const float* __restrict__ resid,
                     float* __restrict__ C, int N, int K, int ldc, int coff) {
    gemm_mma_body2(A, W, bias, resid, C, N, K, ldc, coff,
                   blockIdx.y*128, blockIdx.x*128);
}

__global__ __launch_bounds__(256, 2)
void qkv_mma_kernel(const float* __restrict__ A,
                    const float* __restrict__ Wq, const float* __restrict__ Wk,
                    const float* __restrict__ Wv,
                    const float* __restrict__ bq, const float* __restrict__ bk,
                    const float* __restrict__ bv,
                    float* __restrict__ QKV) {
    int z = blockIdx.z;
    const float* W    = (z == 0) ? Wq : (z == 1 ? Wk : Wv);
    const float* bias = (z == 0) ? bq : (z == 1 ? bk : bv);
    gemm_mma_body2(A, W, bias, nullptr, QKV, Hd, Hd, QKVLD, z*Hd,
                   blockIdx.y*128, 0);
}

// ---- tf32 MMA GEMM + GLU, cp.async 3-stage (64-wide tile, dual acc) --------
#define WTP2 72
__global__ __launch_bounds__(256, 2)
void glu_mma_kernel(const float* __restrict__ A,
                    const float* __restrict__ Wf1,
                    const float* __restrict__ bf1,
                    float* __restrict__ G, int K) {
    __shared__ __align__(16) float As [3][128][ATP2];
    __shared__ __align__(16) float Wsa[3][16][WTP2];
    __shared__ __align__(16) float Wsb[3][16][WTP2];
    int tid = threadIdx.x, lane = tid & 31, wid = tid >> 5;
    int g = lane >> 2, t4 = lane & 3;
    int wm = (wid & 1) * 64, wn = (wid >> 1) * 16;
    int bm = blockIdx.y*128, bn = blockIdx.x*64;

    int arow = tid >> 1, ahalf = tid & 1;
    int wrow = tid >> 4, wc = tid & 15;
    const float* aSrc  = A + (size_t)(bm + arow)*K + ahalf*8;
    const float* waSrc = Wf1 + (size_t)wrow*(2*FFd) + bn + wc*4;
    const float* wbSrc = waSrc + FFd;

    uint32_t aDst[3], waDst[3], wbDst[3];
    #pragma unroll
    for (int s = 0; s < 3; s++) {
        aDst[s]  = smem_u32(&As [s][arow][ahalf*8]);
        waDst[s] = smem_u32(&Wsa[s][wrow][wc*4]);
        wbDst[s] = smem_u32(&Wsb[s][wrow][wc*4]);
    }

    int nkt = K >> 4;
    #pragma unroll
    for (int pf = 0; pf < 2; pf++) {
        CP16(aDst[pf],      aSrc + pf*16);
        CP16(aDst[pf] + 16, aSrc + pf*16 + 4);
        CP16(waDst[pf],     waSrc + (size_t)pf*16*(2*FFd));
        CP16(wbDst[pf],     wbSrc + (size_t)pf*16*(2*FFd));
        CPCOMMIT();
    }

    float acca[4][2][4] = {};
    float accb[4][2][4] = {};
    for (int kt = 0; kt < nkt; kt++) {
        if (kt == nkt-1) { CPWAIT0(); } else { CPWAIT1(); }
        __syncthreads();
        if (kt + 2 < nkt) {
            int s = (kt+2) % 3;
            CP16(aDst[s],      aSrc + (kt+2)*16);
            CP16(aDst[s] + 16, aSrc + (kt+2)*16 + 4);
            CP16(waDst[s],     waSrc + (size_t)(kt+2)*16*(2*FFd));
            CP16(wbDst[s],     wbSrc + (size_t)(kt+2)*16*(2*FFd));
            CPCOMMIT();
        }
        int buf = kt % 3;
        #pragma unroll
        for (int ks = 0; ks < 2; ks++) {
            int kr = ks*8 + t4;
            uint32_t ba00 = __float_as_uint(Wsa[buf][kr  ][wn + g]);
            uint32_t ba01 = __float_as_uint(Wsa[buf][kr+4][wn + g]);
            uint32_t ba10 = __float_as_uint(Wsa[buf][kr  ][wn + 8 + g]);
            uint32_t ba11 = __float_as_uint(Wsa[buf][kr+4][wn + 8 + g]);
            uint32_t bb00 = __float_as_uint(Wsb[buf][kr  ][wn + g]);
            uint32_t bb01 = __float_as_uint(Wsb[buf][kr+4][wn + g]);
            uint32_t bb10 = __float_as_uint(Wsb[buf][kr  ][wn + 8 + g]);
            uint32_t bb11 = __float_as_uint(Wsb[buf][kr+4][wn + 8 + g]);
            #pragma unroll
            for (int mt = 0; mt < 4; mt++) {
                int mb = wm + mt*16;
                uint32_t a0 = __float_as_uint(As[buf][mb+g  ][kr  ]);
                uint32_t a1 = __float_as_uint(As[buf][mb+g+8][kr  ]);
                uint32_t a2 = __float_as_uint(As[buf][mb+g  ][kr+4]);
                uint32_t a3 = __float_as_uint(As[buf][mb+g+8][kr+4]);
                mma_tf32(acca[mt][0][0],acca[mt][0][1],acca[mt][0][2],acca[mt][0][3],
                         a0,a1,a2,a3, ba00,ba01);
                mma_tf32(acca[mt][1][0],acca[mt][1][1],acca[mt][1][2],acca[mt][1][3],
                         a0,a1,a2,a3, ba10,ba11);
                mma_tf32(accb[mt][0][0],accb[mt][0][1],accb[mt][0][2],accb[mt][0][3],
                         a0,a1,a2,a3, bb00,bb01);
                mma_tf32(accb[mt][1][0],accb[mt][1][1],accb[mt][1][2],accb[mt][1][3],
                         a0,a1,a2,a3, bb10,bb11);
            }
        }
    }

    #pragma unroll
    for (int mt = 0; mt < 4; mt++) {
        int r0 = bm + wm + mt*16 + g;
        #pragma unroll
        for (int nt = 0; nt < 2; nt++) {
            int col = bn + wn + nt*8 + 2*t4;
            float ba0 = bf1[col], ba1 = bf1[col+1];
            float bb0 = bf1[FFd + col], bb1 = bf1[FFd + col+1];
            float ua0 = acca[mt][nt][0] + ba0, ua1 = acca[mt][nt][1] + ba1;
            float ua2 = acca[mt][nt][2] + ba0, ua3 = acca[mt][nt][3] + ba1;
            float ub0 = accb[mt][nt][0] + bb0, ub1 = accb[mt][nt][1] + bb1;
            float ub2 = accb[mt][nt][2] + bb0, ub3 = accb[mt][nt][3] + bb1;
            float g0 = ua0 * (1.0f/(1.0f + __expf(-ub0)));
            float g1 = ua1 * (1.0f/(1.0f + __expf(-ub1)));
            float g2 = ua2 * (1.0f/(1.0f + __expf(-ub2)));
            float g3 = ua3 * (1.0f/(1.0f + __expf(-ub3)));
            *(float2*)&G[(size_t)r0*FFd + col]     = make_float2(g0, g1);
            *(float2*)&G[(size_t)(r0+8)*FFd + col] = make_float2(g2, g3);
        }
    }
}

// ============ attention v6: z=1, stage K/V once, two 16-query passes/warp ===
#define KT_PITCH 520
#define V_PITCH  24
#define ATTN_SMEM ((16*KT_PITCH + 512*V_PITCH + 512 + 64)*4)

__global__ __launch_bounds__(512, 2)
void attn6_kernel(const float* __restrict__ QKV,
                  const unsigned char* __restrict__ bins,
                  const unsigned char* __restrict__ mask,
                  const float* __restrict__ dist_emb_l,   // [50,8]
                  const float* __restrict__ attn_bias_l,  // [8]
                  float* __restrict__ out) {
    int h = blockIdx.x, b = blockIdx.y;
    extern __shared__ uint32_t smu[];
    uint32_t* Kt = smu;                         // [16][KT_PITCH]
    uint32_t* Vs = Kt + 16*KT_PITCH;            // [512][V_PITCH]
    float* mb    = (float*)(Vs + 512*V_PITCH);  // [512] additive mask bias
    float* emb2  = mb + 512;                    // [50] emb + attn_bias

    int tid = threadIdx.x;
    {   // coalesced K/V staging: 4 threads per row, float4 loads
        int r = tid >> 2, f4 = tid & 3;
        int d = f4*4;
        #pragma unroll
        for (int pass = 0; pass < 4; pass++) {
            int k = pass*128 + r;
            const float4* base = (const float4*)(QKV + ((size_t)(b*Nd + k)*QKVLD + Hd + h*HDd));
            float4 kv = base[f4];
            float4 vv = base[32 + f4];           // +128 floats
            Kt[(d+0)*KT_PITCH + k] = f2tf32(kv.x);
            Kt[(d+1)*KT_PITCH + k] = f2tf32(kv.y);
            Kt[(d+2)*KT_PITCH + k] = f2tf32(kv.z);
            Kt[(d+3)*KT_PITCH + k] = f2tf32(kv.w);
            *(uint4*)&Vs[k*V_PITCH + d] =
                make_uint4(f2tf32(vv.x), f2tf32(vv.y), f2tf32(vv.z), f2tf32(vv.w));
        }
        mb[tid] = mask[(size_t)b*Nd + tid] ? -1e9f : 0.0f;
    }
    if (tid < NUM_BINS) emb2[tid] = dist_emb_l[tid*NHd + h] + attn_bias_l[h];
    __syncthreads();

    int lane = tid & 31, w = tid >> 5;
    int g = lane >> 2, t4 = lane & 3;

    #pragma unroll
    for (int pass = 0; pass < 2; pass++) {
        int qbase = w*32 + pass*16;

        const float* qp = QKV + ((size_t)(b*Nd + qbase)*QKVLD + h*HDd);
        uint32_t qa[8];
        #pragma unroll
        for (int s = 0; s < 2; s++) {
            qa[s*4+0] = f2tf32(qp[(size_t)g    *QKVLD + s*8 + t4]);
            qa[s*4+1] = f2tf32(qp[(size_t)(g+8)*QKVLD + s*8 + t4]);
            qa[s*4+2] = f2tf32(qp[(size_t)g    *QKVLD + s*8 + t4+4]);
            qa[s*4+3] = f2tf32(qp[(size_t)(g+8)*QKVLD + s*8 + t4+4]);
        }

        const uchar2* br0 = (const uchar2*)(bins + ((size_t)(b*Nd + qbase+g  ))*Nd);
        const uchar2* br1 = (const uchar2*)(bins + ((size_t)(b*Nd + qbase+g+8))*Nd);

        float o0=0,o1=0,o2=0,o3=0,o4=0,o5=0,o6=0,o7=0;
        float l0=0.0f, l1=0.0f;

        uchar2 nb0 = br0[t4], nb1 = br1[t4];

        #pragma unroll 2
        for (int kc = 0; kc < Nd; kc += 8) {
            uchar2 bn0 = nb0, bn1 = nb1;
            if (kc + 8 < Nd) { nb0 = br0[(kc+8)/2 + t4]; nb1 = br1[(kc+8)/2 + t4]; }

            uint32_t kb0 = Kt[ t4      *KT_PITCH + kc + g];
            uint32_t kb1 = Kt[(t4+4 )  *KT_PITCH + kc + g];
            uint32_t kb2 = Kt[(t4+8 )  *KT_PITCH + kc + g];
            uint32_t kb3 = Kt[(t4+12)  *KT_PITCH + kc + g];

            float s0=0,s1=0,s2=0,s3=0;
            mma_tf32(s0,s1,s2,s3, qa[0],qa[1],qa[2],qa[3], kb0,kb1);
            mma_tf32(s0,s1,s2,s3, qa[4],qa[5],qa[6],qa[7], kb2,kb3);

            float mbl0 = mb[kc + 2*t4], mbl1 = mb[kc + 2*t4 + 1];
            float p0 = __expf(s0*0.25f + emb2[bn0.x] + mbl0);
            float p1 = __expf(s1*0.25f + emb2[bn0.y] + mbl1);
            float p2 = __expf(s2*0.25f + emb2[bn1.x] + mbl0);
            float p3 = __expf(s3*0.25f + emb2[bn1.y] + mbl1);
            l0 += p0 + p1;
            l1 += p2 + p3;

            int qsl0 = (lane & ~3) | (t4 >> 1);
            int qsl1 = qsl0 + 2;
            bool odd = (t4 & 1);
            float x0a = __shfl_sync(0xffffffffu, p0, qsl0);
            float x0b = __shfl_sync(0xffffffffu, p1, qsl0);
            float x2a = __shfl_sync(0xffffffffu, p0, qsl1);
            float x2b = __shfl_sync(0xffffffffu, p1, qsl1);
            float x1a = __shfl_sync(0xffffffffu, p2, qsl0);
            float x1b = __shfl_sync(0xffffffffu, p3, qsl0);
            float x3a = __shfl_sync(0xffffffffu, p2, qsl1);
            float x3b = __shfl_sync(0xffffffffu, p3, qsl1);
            uint32_t pa0 = __float_as_uint(odd ? x0b : x0a);
            uint32_t pa1 = __float_as_uint(odd ? x1b : x1a);
            uint32_t pa2 = __float_as_uint(odd ? x2b : x2a);
            uint32_t pa3 = __float_as_uint(odd ? x3b : x3a);

            uint32_t vb0 = Vs[(kc + t4    )*V_PITCH + g];
            uint32_t vb1 = Vs[(kc + t4 + 4)*V_PITCH + g];
            uint32_t vb2 = Vs[(kc + t4    )*V_PITCH + g + 8];
            uint32_t vb3 = Vs[(kc + t4 + 4)*V_PITCH + g + 8];

            mma_tf32(o0,o1,o2,o3, pa0,pa1,pa2,pa3, vb0,vb1);
            mma_tf32(o4,o5,o6,o7, pa0,pa1,pa2,pa3, vb2,vb3);
        }

        l0 += __shfl_xor_sync(0xffffffffu, l0, 1);
        l0 += __shfl_xor_sync(0xffffffffu, l0, 2);
        l1 += __shfl_xor_sync(0xffffffffu, l1, 1);
        l1 += __shfl_xor_sync(0xffffffffu, l1, 2);

        float i0 = 1.0f/l0, i1 = 1.0f/l1;
        float* orow0 = out + ((size_t)(b*Nd + qbase + g    ))*Hd + h*HDd + 2*t4;
        float* orow1 = out + ((size_t)(b*Nd + qbase + g + 8))*Hd + h*HDd + 2*t4;
        *(float2*)(orow0    ) = make_float2(o0*i0, o1*i0);
        *(float2*)(orow0 + 8) = make_float2(o4*i0, o5*i0);
        *(float2*)(orow1    ) = make_float2(o2*i1, o3*i1);
        *(float2*)(orow1 + 8) = make_float2(o6*i1, o7*i1);
    }
}

extern "C" void kernel_launch(void* const* d_in, const int* in_sizes, int n_in,
                              void* d_out, int out_size) {
    const float* x    = (const float*)d_in[0];
    const float* dm   = (const float*)d_in[1];
    const void*  mraw = (const void*)d_in[2];
    const float* Wq = (const float*)d_in[3];
    const float* bq = (const float*)d_in[4];
    const float* Wk = (const float*)d_in[5];
    const float* bk = (const float*)d_in[6];
    const float* Wv = (const float*)d_in[7];
    const float* bv = (const float*)d_in[8];
    const float* Wo = (const float*)d_in[9];
    const float* bo = (const float*)d_in[10];
    const float* dist_emb  = (const float*)d_in[11];
    const float* attn_bias = (const float*)d_in[12];
    const float* g1 = (const float*)d_in[13];
    const float* b1 = (const float*)d_in[14];
    const float* g2 = (const float*)d_in[15];
    const float* b2 = (const float*)d_in[16];
    const float* Wf1 = (const float*)d_in[17];
    const float* bf1 = (const float*)d_in[18];
    const float* Wf2 = (const float*)d_in[19];
    const float* bf2 = (const float*)d_in[20];

    float *hn, *QKV, *AO, *G;
    unsigned char *msk, *bins;
    cudaGetSymbolAddress((void**)&hn,  g_hn);
    cudaGetSymbolAddress((void**)&QKV, g_qkv);
    cudaGetSymbolAddress((void**)&AO,  g_ao);
    cudaGetSymbolAddress((void**)&G,   g_gl);
    cudaGetSymbolAddress((void**)&msk, g_mask);
    cudaGetSymbolAddress((void**)&bins,g_bins);

    cudaFuncSetAttribute(attn6_kernel,
                         cudaFuncAttributeMaxDynamicSharedMemorySize, ATTN_SMEM);

    float* h = (float*)d_out;
    cudaMemcpyAsync(h, x, (size_t)Md*Hd*sizeof(float), cudaMemcpyDeviceToDevice);
    mask_expand_kernel<<<1,256>>>(mraw);
    bins_kernel<<<(Bd*Nd*Nd/4 + 255)/256, 256>>>((const float4*)dm,
                                                 (uchar4*)bins, Bd*Nd*Nd/4);

    for (int l = 0; l < Lr; l++) {
        // pre-LN attention block
        ln_kernel<<<Md/8,256>>>(h, g1 + l*Hd, b1 + l*Hd, hn);
        qkv_mma_kernel<<<dim3(1, Md/128, 3), 256>>>(hn,
                Wq + (size_t)l*Hd*Hd, Wk + (size_t)l*Hd*Hd, Wv + (size_t)l*Hd*Hd,
                bq + l*Hd, bk + l*Hd, bv + l*Hd, QKV);
        attn6_kernel<<<dim3(NHd, Bd), 512, ATTN_SMEM>>>(QKV, bins, msk,
                                                dist_emb + (size_t)l*NUM_BINS*NHd,
                                                attn_bias + (size_t)l*NHd, AO);
        gemm_mma_kernel<<<dim3(1, Md/128), 256>>>(AO, Wo + (size_t)l*Hd*Hd,
                bo + l*Hd, h, h, Hd, Hd, Hd, 0);

        // pre-LN GLU FFN (fused GEMM+GLU)
        ln_kernel<<<Md/8,256>>>(h, g2 + l*Hd, b2 + l*Hd, hn);
        glu_mma_kernel<<<dim3(FFd/64, Md/128), 256>>>(hn,
                Wf1 + (size_t)l*Hd*2*FFd, bf1 + (size_t)l*2*FFd, G, Hd);
        gemm_mma_kernel<<<dim3(1, Md/128), 256>>>(G, Wf2 + (size_t)l*FFd*Hd,
                bf2 + l*Hd, h, h, Hd, FFd, Hd, 0);
    }
}

// round 17
// speedup vs baseline: 24.1519x; 1.0095x over previous
#include <cuda_runtime.h>
#include <cstdint>

#define Lr 3
#define Hd 128
#define NHd 8
#define HDd 16
#define FFd 512
#define Bd 32
#define Nd 512
#define NUM_BINS 50
#define Md (Bd*Nd)          // 16384 rows
#define QKVLD 384           // interleaved QKV row stride

// ---------------- scratch (device globals; no allocation allowed) ----------
__device__ float g_hn [(size_t)Md*Hd];
__device__ float g_qkv[(size_t)Md*QKVLD];
__device__ float g_ao [(size_t)Md*Hd];
__device__ float g_gl [(size_t)Md*FFd];
__device__ unsigned char g_mask[Md];
__device__ unsigned char g_bins[(size_t)Bd*Nd*Nd];   // 8.4 MB

// ---------------- helpers ----------------------------------------------------
__device__ __forceinline__ uint32_t f2tf32(float f) {
    uint32_t r; asm("cvt.rna.tf32.f32 %0, %1;" : "=r"(r) : "f"(f)); return r;
}
__device__ __forceinline__ void mma_tf32(float& d0, float& d1, float& d2, float& d3,
                                         uint32_t a0, uint32_t a1, uint32_t a2, uint32_t a3,
                                         uint32_t b0, uint32_t b1) {
    asm("mma.sync.aligned.m16n8k8.row.col.f32.tf32.tf32.f32 "
        "{%0,%1,%2,%3}, {%4,%5,%6,%7}, {%8,%9}, {%0,%1,%2,%3};"
        : "+f"(d0), "+f"(d1), "+f"(d2), "+f"(d3)
        : "r"(a0), "r"(a1), "r"(a2), "r"(a3), "r"(b0), "r"(b1));
}
__device__ __forceinline__ uint32_t smem_u32(const void* p) {
    uint32_t a;
    asm("{ .reg .u64 t; cvta.to.shared.u64 t, %1; cvt.u32.u64 %0, t; }"
        : "=r"(a) : "l"(p));
    return a;
}
#define CP16(dst,src)  asm volatile("cp.async.cg.shared.global [%0], [%1], 16;" :: "r"(dst), "l"(src))
#define CPCOMMIT()     asm volatile("cp.async.commit_group;")
#define CPWAIT1()      asm volatile("cp.async.wait_group 1;")
#define CPWAIT0()      asm volatile("cp.async.wait_group 0;")

// ---------------- mask dtype detection + expansion --------------------------
__global__ void mask_expand_kernel(const void* __restrict__ mraw) {
    __shared__ int s_notint, s_notfloat;
    if (threadIdx.x == 0) { s_notint = 0; s_notfloat = 0; }
    __syncthreads();
    const int* mi = (const int*)mraw;
    int notint = 0, notfloat = 0;
    for (int i = threadIdx.x; i < 4096; i += 256) {
        int v = mi[i];
        if (v != 0 && v != 1) notint = 1;
        if (v != 0 && v != 0x3F800000) notfloat = 1;
    }
    if (notint)   atomicOr(&s_notint, 1);
    if (notfloat) atomicOr(&s_notfloat, 1);
    __syncthreads();
    int isInt   = !s_notint;
    int isFloat = (!s_notfloat) && s_notint;
    for (int i = threadIdx.x; i < Md; i += 256) {
        unsigned char m;
        if (isInt)        m = (unsigned char)(mi[i] != 0);
        else if (isFloat) m = (unsigned char)(((const float*)mraw)[i] != 0.0f);
        else              m = (unsigned char)(((const unsigned char*)mraw)[i] != 0);
        g_mask[i] = m;
    }
}

// ---------------- bins: vectorized, once per call ---------------------------
__global__ void bins_kernel(const float4* __restrict__ dm,
                            uchar4* __restrict__ bins, int n4) {
    int i = blockIdx.x*blockDim.x + threadIdx.x;
    if (i >= n4) return;
    float4 v = dm[i];
    uchar4 o;
    int bx = (int)(v.x*10.0f); o.x = (unsigned char)min(max(bx,0), NUM_BINS-1);
    int by = (int)(v.y*10.0f); o.y = (unsigned char)min(max(by,0), NUM_BINS-1);
    int bz = (int)(v.z*10.0f); o.z = (unsigned char)min(max(bz,0), NUM_BINS-1);
    int bw = (int)(v.w*10.0f); o.w = (unsigned char)min(max(bw,0), NUM_BINS-1);
    bins[i] = o;
}

// ------- LayerNorm (standalone, used once): warp/row, optional src copy -----
__global__ __launch_bounds__(256)
void ln_kernel(const float* __restrict__ src,
               const float* __restrict__ gamma,
               const float* __restrict__ beta,
               float* __restrict__ out,
               float* __restrict__ copy) {       // may be null
    int row = blockIdx.x*8 + (threadIdx.x >> 5);
    int l = threadIdx.x & 31;
    float4 v = ((const float4*)(src + (size_t)row*Hd))[l];
    float s  = (v.x + v.y) + (v.z + v.w);
    float s2 = (v.x*v.x + v.y*v.y) + (v.z*v.z + v.w*v.w);
    #pragma unroll
    for (int o = 16; o; o >>= 1) {
        s  += __shfl_xor_sync(0xffffffffu, s,  o);
        s2 += __shfl_xor_sync(0xffffffffu, s2, o);
    }
    float mean = s * (1.0f/Hd);
    float var  = s2 * (1.0f/Hd) - mean*mean;
    float inv  = rsqrtf(var + 1e-5f);
    float4 g = ((const float4*)gamma)[l];
    float4 bb = ((const float4*)beta)[l];
    float4 o4;
    o4.x = (v.x - mean)*inv*g.x + bb.x;
    o4.y = (v.y - mean)*inv*g.y + bb.y;
    o4.z = (v.z - mean)*inv*g.z + bb.z;
    o4.w = (v.w - mean)*inv*g.w + bb.w;
    ((float4*)(out + (size_t)row*Hd))[l] = o4;
    if (copy) ((float4*)(copy + (size_t)row*Hd))[l] = v;
}

// ======== tf32 MMA GEMM v2: 128x128 tile, 8 warps (warp = 64M x 32N) ========
// As[m][k] pitch 20 (frag banks 20g+t4), Ws[k][n] pitch 136 (banks 8t4+g).
// Optional fused-LN epilogue (requires N==128, coff==0, ldc==128):
// writes C (=h) and hn = LN(h)*gamma+beta.
#define ATP2 20
#define WTP3 136

__device__ __forceinline__
void gemm_mma_body2(const float* __restrict__ A, const float* __restrict__ W,
                    const float* __restrict__ bias, const float* __restrict__ resid,
                    float* __restrict__ C, int N, int K, int ldc, int coff,
                    int bm, int bn,
                    const float* __restrict__ lng, const float* __restrict__ lnb,
                    float* __restrict__ hn) {
    __shared__ __align__(16) float As[3][128][ATP2];
    __shared__ __align__(16) float Ws[3][16][WTP3];
    __shared__ float2 lnpart[4][128];
    int tid = threadIdx.x, lane = tid & 31, wid = tid >> 5;
    int g = lane >> 2, t4 = lane & 3;
    int wm = (wid & 1) * 64, wn = (wid >> 1) * 32;

    int arow = tid >> 1, ahalf = tid & 1;
    int wrow = tid >> 4, wc = tid & 15;          // each thread: 8 W floats
    const float* aSrc = A + (size_t)(bm + arow)*K + ahalf*8;
    const float* wSrc = W + (size_t)wrow*N + bn + wc*8;

    uint32_t aDst[3], wDst[3];
    #pragma unroll
    for (int s = 0; s < 3; s++) {
        aDst[s] = smem_u32(&As[s][arow][ahalf*8]);
        wDst[s] = smem_u32(&Ws[s][wrow][wc*8]);
    }

    int nkt = K >> 4;
    #pragma unroll
    for (int pf = 0; pf < 2; pf++) {
        CP16(aDst[pf],      aSrc + pf*16);
        CP16(aDst[pf] + 16, aSrc + pf*16 + 4);
        CP16(wDst[pf],      wSrc + (size_t)pf*16*N);
        CP16(wDst[pf] + 16, wSrc + (size_t)pf*16*N + 4);
        CPCOMMIT();
    }

    float acc[4][4][4] = {};
    for (int kt = 0; kt < nkt; kt++) {
        if (kt == nkt-1) { CPWAIT0(); } else { CPWAIT1(); }
        __syncthreads();
        if (kt + 2 < nkt) {
            int s = (kt+2) % 3;
            CP16(aDst[s],      aSrc + (kt+2)*16);
            CP16(aDst[s] + 16, aSrc + (kt+2)*16 + 4);
            CP16(wDst[s],      wSrc + (size_t)(kt+2)*16*N);
            CP16(wDst[s] + 16, wSrc + (size_t)(kt+2)*16*N + 4);
            CPCOMMIT();
        }
        int buf = kt % 3;
        #pragma unroll
        for (int ks = 0; ks < 2; ks++) {
            int kr = ks*8 + t4;
            uint32_t bf[4][2];
            #pragma unroll
            for (int nt = 0; nt < 4; nt++) {
                bf[nt][0] = __float_as_uint(Ws[buf][kr  ][wn + nt*8 + g]);
                bf[nt][1] = __float_as_uint(Ws[buf][kr+4][wn + nt*8 + g]);
            }
            #pragma unroll
            for (int mt = 0; mt < 4; mt++) {
                int mb = wm + mt*16;
                uint32_t a0 = __float_as_uint(As[buf][mb+g  ][kr  ]);
                uint32_t a1 = __float_as_uint(As[buf][mb+g+8][kr  ]);
                uint32_t a2 = __float_as_uint(As[buf][mb+g  ][kr+4]);
                uint32_t a3 = __float_as_uint(As[buf][mb+g+8][kr+4]);
                #pragma unroll
                for (int nt = 0; nt < 4; nt++)
                    mma_tf32(acc[mt][nt][0],acc[mt][nt][1],acc[mt][nt][2],acc[mt][nt][3],
                             a0,a1,a2,a3, bf[nt][0],bf[nt][1]);
            }
        }
    }

    // pass 1: bias + resid, store C, accumulate LN row stats
    float rs[4][2], rs2[4][2];
    #pragma unroll
    for (int mt = 0; mt < 4; mt++) {
        rs[mt][0]=0; rs[mt][1]=0; rs2[mt][0]=0; rs2[mt][1]=0;
        int r0 = bm + wm + mt*16 + g;
        #pragma unroll
        for (int nt = 0; nt < 4; nt++) {
            int col = bn + wn + nt*8 + 2*t4;
            float b0 = bias[col], b1 = bias[col+1];
            float v0 = acc[mt][nt][0] + b0, v1 = acc[mt][nt][1] + b1;
            float v2 = acc[mt][nt][2] + b0, v3 = acc[mt][nt][3] + b1;
            if (resid) {
                float2 r0v = *(const float2*)&resid[(size_t)r0*ldc + coff + col];
                float2 r1v = *(const float2*)&resid[(size_t)(r0+8)*ldc + coff + col];
                v0 += r0v.x; v1 += r0v.y; v2 += r1v.x; v3 += r1v.y;
            }
            *(float2*)&C[(size_t)r0*ldc + coff + col]     = make_float2(v0, v1);
            *(float2*)&C[(size_t)(r0+8)*ldc + coff + col] = make_float2(v2, v3);
            rs [mt][0] += v0 + v1;      rs [mt][1] += v2 + v3;
            rs2[mt][0] += v0*v0 + v1*v1; rs2[mt][1] += v2*v2 + v3*v3;
        }
    }

    if (lng) {   // fused LN epilogue (N==128, coff==0, ldc==128)
        #pragma unroll
        for (int mt = 0; mt < 4; mt++) {
            #pragma unroll
            for (int hf = 0; hf < 2; hf++) {
                rs [mt][hf] += __shfl_xor_sync(0xffffffffu, rs [mt][hf], 1);
                rs [mt][hf] += __shfl_xor_sync(0xffffffffu, rs [mt][hf], 2);
                rs2[mt][hf] += __shfl_xor_sync(0xffffffffu, rs2[mt][hf], 1);
                rs2[mt][hf] += __shfl_xor_sync(0xffffffffu, rs2[mt][hf], 2);
            }
        }
        int wnid = wid >> 1;
        if (t4 == 0) {
            #pragma unroll
            for (int mt = 0; mt < 4; mt++) {
                int lr = wm + mt*16 + g;
                lnpart[wnid][lr    ] = make_float2(rs[mt][0], rs2[mt][0]);
                lnpart[wnid][lr + 8] = make_float2(rs[mt][1], rs2[mt][1]);
            }
        }
        __syncthreads();
        #pragma unroll
        for (int mt = 0; mt < 4; mt++) {
            int lr0 = wm + mt*16 + g;
            int r0  = bm + lr0;
            float2 p0 = lnpart[0][lr0], p1 = lnpart[1][lr0],
                   p2 = lnpart[2][lr0], p3 = lnpart[3][lr0];
            float s0  = p0.x + p1.x + p2.x + p3.x;
            float q0  = p0.y + p1.y + p2.y + p3.y;
            p0 = lnpart[0][lr0+8]; p1 = lnpart[1][lr0+8];
            p2 = lnpart[2][lr0+8]; p3 = lnpart[3][lr0+8];
            float s1  = p0.x + p1.x + p2.x + p3.x;
            float q1  = p0.y + p1.y + p2.y + p3.y;
            float mean0 = s0*(1.0f/Hd), var0 = q0*(1.0f/Hd) - mean0*mean0;
            float mean1 = s1*(1.0f/Hd), var1 = q1*(1.0f/Hd) - mean1*mean1;
            float inv0 = rsqrtf(var0 + 1e-5f), inv1 = rsqrtf(var1 + 1e-5f);
            #pragma unroll
            for (int nt = 0; nt < 4; nt++) {
                int col = wn + nt*8 + 2*t4;
                float2 gm = *(const float2*)&lng[col];
                float2 bt = *(const float2*)&lnb[col];
                float2 h0 = *(const float2*)&C[(size_t)r0*Hd + col];
                float2 h1 = *(const float2*)&C[(size_t)(r0+8)*Hd + col];
                float2 o0 = make_float2((h0.x-mean0)*inv0*gm.x + bt.x,
                                        (h0.y-mean0)*inv0*gm.y + bt.y);
                float2 o1 = make_float2((h1.x-mean1)*inv1*gm.x + bt.x,
                                        (h1.y-mean1)*inv1*gm.y + bt.y);
                *(float2*)&hn[(size_t)r0*Hd + col]     = o0;
                *(float2*)&hn[(size_t)(r0+8)*Hd + col] = o1;
            }
        }
    }
}

__global__ __launch_bounds__(256, 2)
void gemm_mma_kernel(const float* __restrict__ A, const float* __restrict__ W,
                     const float* __restrict__ bias, const float* __restrict__ resid,
                     float* __restrict__ C, int N, int K, int ldc, int coff,
                     const float* __restrict__ lng, const float* __restrict__ lnb,
                     float* __restrict__ hn) {
    gemm_mma_body2(A, W, bias, resid, C, N, K, ldc, coff,
                   blockIdx.y*128, blockIdx.x*128, lng, lnb, hn);
}

__global__ __launch_bounds__(256, 2)
void qkv_mma_kernel(const float* __restrict__ A,
                    const float* __restrict__ Wq, const float* __restrict__ Wk,
                    const float* __restrict__ Wv,
                    const float* __restrict__ bq, const float* __restrict__ bk,
                    const float* __restrict__ bv,
                    float* __restrict__ QKV) {
    int z = blockIdx.z;
    const float* W    = (z == 0) ? Wq : (z == 1 ? Wk : Wv);
    const float* bias = (z == 0) ? bq : (z == 1 ? bk : bv);
    gemm_mma_body2(A, W, bias, nullptr, QKV, Hd, Hd, QKVLD, z*Hd,
                   blockIdx.y*128, 0, nullptr, nullptr, nullptr);
}

// ---- tf32 MMA GEMM + GLU, cp.async 3-stage (64-wide tile, dual acc) --------
#define WTP2 72
__global__ __launch_bounds__(256, 2)
void glu_mma_kernel(const float* __restrict__ A,
                    const float* __restrict__ Wf1,
                    const float* __restrict__ bf1,
                    float* __restrict__ G, int K) {
    __shared__ __align__(16) float As [3][128][ATP2];
    __shared__ __align__(16) float Wsa[3][16][WTP2];
    __shared__ __align__(16) float Wsb[3][16][WTP2];
    int tid = threadIdx.x, lane = tid & 31, wid = tid >> 5;
    int g = lane >> 2, t4 = lane & 3;
    int wm = (wid & 1) * 64, wn = (wid >> 1) * 16;
    int bm = blockIdx.y*128, bn = blockIdx.x*64;

    int arow = tid >> 1, ahalf = tid & 1;
    int wrow = tid >> 4, wc = tid & 15;
    const float* aSrc  = A + (size_t)(bm + arow)*K + ahalf*8;
    const float* waSrc = Wf1 + (size_t)wrow*(2*FFd) + bn + wc*4;
    const float* wbSrc = waSrc + FFd;

    uint32_t aDst[3], waDst[3], wbDst[3];
    #pragma unroll
    for (int s = 0; s < 3; s++) {
        aDst[s]  = smem_u32(&As [s][arow][ahalf*8]);
        waDst[s] = smem_u32(&Wsa[s][wrow][wc*4]);
        wbDst[s] = smem_u32(&Wsb[s][wrow][wc*4]);
    }

    int nkt = K >> 4;
    #pragma unroll
    for (int pf = 0; pf < 2; pf++) {
        CP16(aDst[pf],      aSrc + pf*16);
        CP16(aDst[pf] + 16, aSrc + pf*16 + 4);
        CP16(waDst[pf],     waSrc + (size_t)pf*16*(2*FFd));
        CP16(wbDst[pf],     wbSrc + (size_t)pf*16*(2*FFd));
        CPCOMMIT();
    }

    float acca[4][2][4] = {};
    float accb[4][2][4] = {};
    for (int kt = 0; kt < nkt; kt++) {
        if (kt == nkt-1) { CPWAIT0(); } else { CPWAIT1(); }
        __syncthreads();
        if (kt + 2 < nkt) {
            int s = (kt+2) % 3;
            CP16(aDst[s],      aSrc + (kt+2)*16);
            CP16(aDst[s] + 16, aSrc + (kt+2)*16 + 4);
            CP16(waDst[s],     waSrc + (size_t)(kt+2)*16*(2*FFd));
            CP16(wbDst[s],     wbSrc + (size_t)(kt+2)*16*(2*FFd));
            CPCOMMIT();
        }
        int buf = kt % 3;
        #pragma unroll
        for (int ks = 0; ks < 2; ks++) {
            int kr = ks*8 + t4;
            uint32_t ba00 = __float_as_uint(Wsa[buf][kr  ][wn + g]);
            uint32_t ba01 = __float_as_uint(Wsa[buf][kr+4][wn + g]);
            uint32_t ba10 = __float_as_uint(Wsa[buf][kr  ][wn + 8 + g]);
            uint32_t ba11 = __float_as_uint(Wsa[buf][kr+4][wn + 8 + g]);
            uint32_t bb00 = __float_as_uint(Wsb[buf][kr  ][wn + g]);
            uint32_t bb01 = __float_as_uint(Wsb[buf][kr+4][wn + g]);
            uint32_t bb10 = __float_as_uint(Wsb[buf][kr  ][wn + 8 + g]);
            uint32_t bb11 = __float_as_uint(Wsb[buf][kr+4][wn + 8 + g]);
            #pragma unroll
            for (int mt = 0; mt < 4; mt++) {
                int mb = wm + mt*16;
                uint32_t a0 = __float_as_uint(As[buf][mb+g  ][kr  ]);
                uint32_t a1 = __float_as_uint(As[buf][mb+g+8][kr  ]);
                uint32_t a2 = __float_as_uint(As[buf][mb+g  ][kr+4]);
                uint32_t a3 = __float_as_uint(As[buf][mb+g+8][kr+4]);
                mma_tf32(acca[mt][0][0],acca[mt][0][1],acca[mt][0][2],acca[mt][0][3],
                         a0,a1,a2,a3, ba00,ba01);
                mma_tf32(acca[mt][1][0],acca[mt][1][1],acca[mt][1][2],acca[mt][1][3],
                         a0,a1,a2,a3, ba10,ba11);
                mma_tf32(accb[mt][0][0],accb[mt][0][1],accb[mt][0][2],accb[mt][0][3],
                         a0,a1,a2,a3, bb00,bb01);
                mma_tf32(accb[mt][1][0],accb[mt][1][1],accb[mt][1][2],accb[mt][1][3],
                         a0,a1,a2,a3, bb10,bb11);
            }
        }
    }

    #pragma unroll
    for (int mt = 0; mt < 4; mt++) {
        int r0 = bm + wm + mt*16 + g;
        #pragma unroll
        for (int nt = 0; nt < 2; nt++) {
            int col = bn + wn + nt*8 + 2*t4;
            float ba0 = bf1[col], ba1 = bf1[col+1];
            float bb0 = bf1[FFd + col], bb1 = bf1[FFd + col+1];
            float ua0 = acca[mt][nt][0] + ba0, ua1 = acca[mt][nt][1] + ba1;
            float ua2 = acca[mt][nt][2] + ba0, ua3 = acca[mt][nt][3] + ba1;
            float ub0 = accb[mt][nt][0] + bb0, ub1 = accb[mt][nt][1] + bb1;
            float ub2 = accb[mt][nt][2] + bb0, ub3 = accb[mt][nt][3] + bb1;
            float g0 = ua0 * (1.0f/(1.0f + __expf(-ub0)));
            float g1 = ua1 * (1.0f/(1.0f + __expf(-ub1)));
            float g2 = ua2 * (1.0f/(1.0f + __expf(-ub2)));
            float g3 = ua3 * (1.0f/(1.0f + __expf(-ub3)));
            *(float2*)&G[(size_t)r0*FFd + col]     = make_float2(g0, g1);
            *(float2*)&G[(size_t)(r0+8)*FFd + col] = make_float2(g2, g3);
        }
    }
}

// ============ attention v6: z=1, stage K/V once, two 16-query passes/warp ===
#define KT_PITCH 520
#define V_PITCH  24
#define ATTN_SMEM ((16*KT_PITCH + 512*V_PITCH + 512 + 64)*4)

__global__ __launch_bounds__(512, 2)
void attn6_kernel(const float* __restrict__ QKV,
                  const unsigned char* __restrict__ bins,
                  const unsigned char* __restrict__ mask,
                  const float* __restrict__ dist_emb_l,   // [50,8]
                  const float* __restrict__ attn_bias_l,  // [8]
                  float* __restrict__ out) {
    int h = blockIdx.x, b = blockIdx.y;
    extern __shared__ uint32_t smu[];
    uint32_t* Kt = smu;                         // [16][KT_PITCH]
    uint32_t* Vs = Kt + 16*KT_PITCH;            // [512][V_PITCH]
    float* mb    = (float*)(Vs + 512*V_PITCH);  // [512] additive mask bias
    float* emb2  = mb + 512;                    // [50] emb + attn_bias

    int tid = threadIdx.x;
    {   // coalesced K/V staging: 4 threads per row, float4 loads
        int r = tid >> 2, f4 = tid & 3;
        int d = f4*4;
        #pragma unroll
        for (int pass = 0; pass < 4; pass++) {
            int k = pass*128 + r;
            const float4* base = (const float4*)(QKV + ((size_t)(b*Nd + k)*QKVLD + Hd + h*HDd));
            float4 kv = base[f4];
            float4 vv = base[32 + f4];           // +128 floats
            Kt[(d+0)*KT_PITCH + k] = f2tf32(kv.x);
            Kt[(d+1)*KT_PITCH + k] = f2tf32(kv.y);
            Kt[(d+2)*KT_PITCH + k] = f2tf32(kv.z);
            Kt[(d+3)*KT_PITCH + k] = f2tf32(kv.w);
            *(uint4*)&Vs[k*V_PITCH + d] =
                make_uint4(f2tf32(vv.x), f2tf32(vv.y), f2tf32(vv.z), f2tf32(vv.w));
        }
        mb[tid] = mask[(size_t)b*Nd + tid] ? -1e9f : 0.0f;
    }
    if (tid < NUM_BINS) emb2[tid] = dist_emb_l[tid*NHd + h] + attn_bias_l[h];
    __syncthreads();

    int lane = tid & 31, w = tid >> 5;
    int g = lane >> 2, t4 = lane & 3;

    #pragma unroll
    for (int pass = 0; pass < 2; pass++) {
        int qbase = w*32 + pass*16;

        const float* qp = QKV + ((size_t)(b*Nd + qbase)*QKVLD + h*HDd);
        uint32_t qa[8];
        #pragma unroll
        for (int s = 0; s < 2; s++) {
            qa[s*4+0] = f2tf32(qp[(size_t)g    *QKVLD + s*8 + t4]);
            qa[s*4+1] = f2tf32(qp[(size_t)(g+8)*QKVLD + s*8 + t4]);
            qa[s*4+2] = f2tf32(qp[(size_t)g    *QKVLD + s*8 + t4+4]);
            qa[s*4+3] = f2tf32(qp[(size_t)(g+8)*QKVLD + s*8 + t4+4]);
        }

        const uchar2* br0 = (const uchar2*)(bins + ((size_t)(b*Nd + qbase+g  ))*Nd);
        const uchar2* br1 = (const uchar2*)(bins + ((size_t)(b*Nd + qbase+g+8))*Nd);

        float o0=0,o1=0,o2=0,o3=0,o4=0,o5=0,o6=0,o7=0;
        float l0=0.0f, l1=0.0f;

        uchar2 nb0 = br0[t4], nb1 = br1[t4];

        #pragma unroll 2
        for (int kc = 0; kc < Nd; kc += 8) {
            uchar2 bn0 = nb0, bn1 = nb1;
            if (kc + 8 < Nd) { nb0 = br0[(kc+8)/2 + t4]; nb1 = br1[(kc+8)/2 + t4]; }

            uint32_t kb0 = Kt[ t4      *KT_PITCH + kc + g];
            uint32_t kb1 = Kt[(t4+4 )  *KT_PITCH + kc + g];
            uint32_t kb2 = Kt[(t4+8 )  *KT_PITCH + kc + g];
            uint32_t kb3 = Kt[(t4+12)  *KT_PITCH + kc + g];

            float s0=0,s1=0,s2=0,s3=0;
            mma_tf32(s0,s1,s2,s3, qa[0],qa[1],qa[2],qa[3], kb0,kb1);
            mma_tf32(s0,s1,s2,s3, qa[4],qa[5],qa[6],qa[7], kb2,kb3);

            float mbl0 = mb[kc + 2*t4], mbl1 = mb[kc + 2*t4 + 1];
            float p0 = __expf(s0*0.25f + emb2[bn0.x] + mbl0);
            float p1 = __expf(s1*0.25f + emb2[bn0.y] + mbl1);
            float p2 = __expf(s2*0.25f + emb2[bn1.x] + mbl0);
            float p3 = __expf(s3*0.25f + emb2[bn1.y] + mbl1);
            l0 += p0 + p1;
            l1 += p2 + p3;

            int qsl0 = (lane & ~3) | (t4 >> 1);
            int qsl1 = qsl0 + 2;
            bool odd = (t4 & 1);
            float x0a = __shfl_sync(0xffffffffu, p0, qsl0);
            float x0b = __shfl_sync(0xffffffffu, p1, qsl0);
            float x2a = __shfl_sync(0xffffffffu, p0, qsl1);
            float x2b = __shfl_sync(0xffffffffu, p1, qsl1);
            float x1a = __shfl_sync(0xffffffffu, p2, qsl0);
            float x1b = __shfl_sync(0xffffffffu, p3, qsl0);
            float x3a = __shfl_sync(0xffffffffu, p2, qsl1);
            float x3b = __shfl_sync(0xffffffffu, p3, qsl1);
            uint32_t pa0 = __float_as_uint(odd ? x0b : x0a);
            uint32_t pa1 = __float_as_uint(odd ? x1b : x1a);
            uint32_t pa2 = __float_as_uint(odd ? x2b : x2a);
            uint32_t pa3 = __float_as_uint(odd ? x3b : x3a);

            uint32_t vb0 = Vs[(kc + t4    )*V_PITCH + g];
            uint32_t vb1 = Vs[(kc + t4 + 4)*V_PITCH + g];
            uint32_t vb2 = Vs[(kc + t4    )*V_PITCH + g + 8];
            uint32_t vb3 = Vs[(kc + t4 + 4)*V_PITCH + g + 8];

            mma_tf32(o0,o1,o2,o3, pa0,pa1,pa2,pa3, vb0,vb1);
            mma_tf32(o4,o5,o6,o7, pa0,pa1,pa2,pa3, vb2,vb3);
        }

        l0 += __shfl_xor_sync(0xffffffffu, l0, 1);
        l0 += __shfl_xor_sync(0xffffffffu, l0, 2);
        l1 += __shfl_xor_sync(0xffffffffu, l1, 1);
        l1 += __shfl_xor_sync(0xffffffffu, l1, 2);

        float i0 = 1.0f/l0, i1 = 1.0f/l1;
        float* orow0 = out + ((size_t)(b*Nd + qbase + g    ))*Hd + h*HDd + 2*t4;
        float* orow1 = out + ((size_t)(b*Nd + qbase + g + 8))*Hd + h*HDd + 2*t4;
        *(float2*)(orow0    ) = make_float2(o0*i0, o1*i0);
        *(float2*)(orow0 + 8) = make_float2(o4*i0, o5*i0);
        *(float2*)(orow1    ) = make_float2(o2*i1, o3*i1);
        *(float2*)(orow1 + 8) = make_float2(o6*i1, o7*i1);
    }
}

extern "C" void kernel_launch(void* const* d_in, const int* in_sizes, int n_in,
                              void* d_out, int out_size) {
    const float* x    = (const float*)d_in[0];
    const float* dm   = (const float*)d_in[1];
    const void*  mraw = (const void*)d_in[2];
    const float* Wq = (const float*)d_in[3];
    const float* bq = (const float*)d_in[4];
    const float* Wk = (const float*)d_in[5];
    const float* bk = (const float*)d_in[6];
    const float* Wv = (const float*)d_in[7];
    const float* bv = (const float*)d_in[8];
    const float* Wo = (const float*)d_in[9];
    const float* bo = (const float*)d_in[10];
    const float* dist_emb  = (const float*)d_in[11];
    const float* attn_bias = (const float*)d_in[12];
    const float* g1 = (const float*)d_in[13];
    const float* b1 = (const float*)d_in[14];
    const float* g2 = (const float*)d_in[15];
    const float* b2 = (const float*)d_in[16];
    const float* Wf1 = (const float*)d_in[17];
    const float* bf1 = (const float*)d_in[18];
    const float* Wf2 = (const float*)d_in[19];
    const float* bf2 = (const float*)d_in[20];

    float *hn, *QKV, *AO, *G;
    unsigned char *msk, *bins;
    cudaGetSymbolAddress((void**)&hn,  g_hn);
    cudaGetSymbolAddress((void**)&QKV, g_qkv);
    cudaGetSymbolAddress((void**)&AO,  g_ao);
    cudaGetSymbolAddress((void**)&G,   g_gl);
    cudaGetSymbolAddress((void**)&msk, g_mask);
    cudaGetSymbolAddress((void**)&bins,g_bins);

    cudaFuncSetAttribute(attn6_kernel,
                         cudaFuncAttributeMaxDynamicSharedMemorySize, ATTN_SMEM);

    float* h = (float*)d_out;
    mask_expand_kernel<<<1,256>>>(mraw);
    bins_kernel<<<(Bd*Nd*Nd/4 + 255)/256, 256>>>((const float4*)dm,
                                                 (uchar4*)bins, Bd*Nd*Nd/4);
    // initial LN(x) -> hn, and h = x (fused copy)
    ln_kernel<<<Md/8,256>>>(x, g1, b1, hn, h);

    for (int l = 0; l < Lr; l++) {
        qkv_mma_kernel<<<dim3(1, Md/128, 3), 256>>>(hn,
                Wq + (size_t)l*Hd*Hd, Wk + (size_t)l*Hd*Hd, Wv + (size_t)l*Hd*Hd,
                bq + l*Hd, bk + l*Hd, bv + l*Hd, QKV);
        attn6_kernel<<<dim3(NHd, Bd), 512, ATTN_SMEM>>>(QKV, bins, msk,
                                                dist_emb + (size_t)l*NUM_BINS*NHd,
                                                attn_bias + (size_t)l*NHd, AO);
        // Wo GEMM + residual -> h, fused LN(g2,b2) -> hn (feeds GLU)
        gemm_mma_kernel<<<dim3(1, Md/128), 256>>>(AO, Wo + (size_t)l*Hd*Hd,
                bo + l*Hd, h, h, Hd, Hd, Hd, 0,
                g2 + l*Hd, b2 + l*Hd, hn);
        glu_mma_kernel<<<dim3(FFd/64, Md/128), 256>>>(hn,
                Wf1 + (size_t)l*Hd*2*FFd, bf1 + (size_t)l*2*FFd, G, Hd);
        // Wf2 GEMM + residual -> h, fused LN(next layer g1,b1) -> hn
        const float* nlg = (l < Lr-1) ? (g1 + (size_t)(l+1)*Hd) : nullptr;
        const float* nlb = (l < Lr-1) ? (b1 + (size_t)(l+1)*Hd) : nullptr;
        gemm_mma_kernel<<<dim3(1, Md/128), 256>>>(G, Wf2 + (size_t)l*FFd*Hd,
                bf2 + l*Hd, h, h, Hd, FFd, Hd, 0,
                nlg, nlb, hn);
    }
}